// round 1
// baseline (speedup 1.0000x reference)
#include <cuda_runtime.h>
#include <math.h>

#define B_   2
#define T_   2048
#define C_   1024
#define H_   16
#define D_   64
#define M_   4096          // B_*T_
#define N1_  3072          // 3*C_
#define EPS_ 1e-6f

// ---------------- scratch (device globals; no allocation allowed) ----------------
__device__ float g_qkv[(size_t)M_ * N1_];          // 48 MB
__device__ float g_q[(size_t)B_ * H_ * T_ * D_];   // 16 MB
__device__ float g_k[(size_t)B_ * H_ * T_ * D_];
__device__ float g_v[(size_t)B_ * H_ * T_ * D_];
__device__ float g_att[(size_t)M_ * C_];           // 16 MB
__device__ float g_xsq[M_];
__device__ float g_osq[M_];
__device__ float g_wsq1[N1_];
__device__ float g_wsq2[C_];

// ---------------- row sum-of-squares (row length = 1024) ----------------
__global__ void rowsq_kernel(const float* __restrict__ X, float* __restrict__ out)
{
    int m = blockIdx.x;
    const float* x = X + (size_t)m * C_;
    int tid = threadIdx.x;
    float4 v = *(const float4*)(x + tid * 4);
    float s = v.x * v.x + v.y * v.y + v.z * v.z + v.w * v.w;
#pragma unroll
    for (int o = 16; o; o >>= 1) s += __shfl_xor_sync(0xffffffffu, s, o);
    __shared__ float red[8];
    if ((tid & 31) == 0) red[tid >> 5] = s;
    __syncthreads();
    if (tid == 0) {
        float t = 0.f;
#pragma unroll
        for (int i = 0; i < 8; i++) t += red[i];
        out[m] = t;
    }
}

// ---------------- column sum-of-squares of W[K][N] ----------------
__global__ void colsq_kernel(const float* __restrict__ W, float* __restrict__ out,
                             int K, int N)
{
    __shared__ float red[4][64];
    int tx = threadIdx.x & 63, ty = threadIdx.x >> 6;
    int n = blockIdx.x * 64 + tx;
    float s = 0.f;
    for (int k = ty; k < K; k += 4) {
        float w = W[(size_t)k * N + n];
        s = fmaf(w, w, s);
    }
    red[ty][tx] = s;
    __syncthreads();
    if (ty == 0) out[n] = red[0][tx] + red[1][tx] + red[2][tx] + red[3][tx];
}

// ---------------- yat-dense GEMM: C = yat(A[M,K] @ B[K,N]) ----------------
// 128x128 tile, BK=16, 256 threads, 8x8 per-thread tile, fused yat epilogue.
__global__ void __launch_bounds__(256) yat_gemm_kernel(
    const float* __restrict__ A, const float* __restrict__ Bw,
    const float* __restrict__ asq, const float* __restrict__ bsq,
    const float* __restrict__ bias, float* __restrict__ Cout,
    int M, int N, int K, float scale)
{
    __shared__ float As[16][132];   // transposed A tile, padded
    __shared__ float Bs[16][128];

    const int tid = threadIdx.x;
    const int tr = tid >> 4, tc = tid & 15;
    const int rowBase = blockIdx.y * 128;
    const int colBase = blockIdx.x * 128;
    const int aRow = tid >> 2;
    const int aCol = (tid & 3) << 2;
    const int bRow = tid >> 5;
    const int bCol = (tid & 31) << 2;

    float acc[8][8];
#pragma unroll
    for (int i = 0; i < 8; i++)
#pragma unroll
        for (int j = 0; j < 8; j++) acc[i][j] = 0.f;

    const float* Ag = A + (size_t)rowBase * K;
    const float* Bg = Bw + colBase;

    for (int kt = 0; kt < K; kt += 16) {
#pragma unroll
        for (int p = 0; p < 2; p++) {
            float4 a = *(const float4*)(Ag + (size_t)(aRow + p * 64) * K + kt + aCol);
            As[aCol + 0][aRow + p * 64] = a.x;
            As[aCol + 1][aRow + p * 64] = a.y;
            As[aCol + 2][aRow + p * 64] = a.z;
            As[aCol + 3][aRow + p * 64] = a.w;
        }
#pragma unroll
        for (int p = 0; p < 2; p++) {
            *(float4*)&Bs[bRow + p * 8][bCol] =
                *(const float4*)(Bg + (size_t)(kt + bRow + p * 8) * N + bCol);
        }
        __syncthreads();
#pragma unroll
        for (int kk = 0; kk < 16; kk++) {
            float ra[8], rb[8];
            *(float4*)&ra[0] = *(const float4*)&As[kk][tr * 8];
            *(float4*)&ra[4] = *(const float4*)&As[kk][tr * 8 + 4];
            *(float4*)&rb[0] = *(const float4*)&Bs[kk][tc * 8];
            *(float4*)&rb[4] = *(const float4*)&Bs[kk][tc * 8 + 4];
#pragma unroll
            for (int i = 0; i < 8; i++)
#pragma unroll
                for (int j = 0; j < 8; j++)
                    acc[i][j] = fmaf(ra[i], rb[j], acc[i][j]);
        }
        __syncthreads();
    }

    // fused yat epilogue: y = dot^2 / (asq + bsq - 2dot + eps) * scale + bias
#pragma unroll
    for (int i = 0; i < 8; i++) {
        int row = rowBase + tr * 8 + i;
        float av = asq[row];
        float* crow = Cout + (size_t)row * N + colBase + tc * 8;
#pragma unroll
        for (int jv = 0; jv < 2; jv++) {
            float r[4];
#pragma unroll
            for (int e = 0; e < 4; e++) {
                int j = jv * 4 + e;
                int n = colBase + tc * 8 + j;
                float dot = acc[i][j];
                float dist = av + bsq[n] - 2.f * dot + EPS_;
                r[e] = dot * dot / dist * scale + bias[n];
            }
            float4 o;
            o.x = r[0]; o.y = r[1]; o.z = r[2]; o.w = r[3];
            *(float4*)(crow + jv * 4) = o;
        }
    }
}

// ---------------- RoPE + split qkv[B,T,3,H,D] -> Q/K/V[B,H,T,D] ----------------
__global__ void rope_split_kernel(const float* __restrict__ qkv,
                                  float* __restrict__ Q, float* __restrict__ K,
                                  float* __restrict__ V)
{
    int t = blockIdx.x, b = blockIdx.y;
    int tid = threadIdx.x;            // 512 = 16 heads * 32 pairs
    int h = tid >> 5, i = tid & 31;
    const float* row = qkv + (size_t)(b * T_ + t) * N1_;
    float fr = powf(10000.0f, -(float)i / 32.0f);
    float ang = (float)t * fr;
    float s, c;
    sincosf(ang, &s, &c);
    size_t o = ((size_t)(b * H_ + h) * T_ + t) * D_ + 2 * i;
    int base = h * 64 + 2 * i;

    float q0 = row[base], q1 = row[base + 1];
    Q[o]     = q0 * c - q1 * s;
    Q[o + 1] = q1 * c + q0 * s;
    float k0 = row[C_ + base], k1 = row[C_ + base + 1];
    K[o]     = k0 * c - k1 * s;
    K[o + 1] = k1 * c + k0 * s;
    V[o]     = row[2 * C_ + base];
    V[o + 1] = row[2 * C_ + base + 1];
}

// ---------------- causal flash attention, fp32 ----------------
// BQ=128 rows per block, BKV=64, 256 threads (8 warps x 16 rows).
// Lane tile: 2 rows x 16 cols. Smem rows padded to stride 68 (conflict-free).
#define ASTR 68
#define ATTN_SMEM ((128 * ASTR + 64 * ASTR + 64 * ASTR + 128 * ASTR) * 4)

__global__ void __launch_bounds__(256) attn_kernel(const float* __restrict__ Qg,
                                                   const float* __restrict__ Kg,
                                                   const float* __restrict__ Vg,
                                                   float* __restrict__ Og)
{
    extern __shared__ float sm[];
    float* sQ = sm;                    // 128 x 68
    float* sK = sQ + 128 * ASTR;       // 64 x 68
    float* sV = sK + 64 * ASTR;        // 64 x 68
    float* sP = sV + 64 * ASTR;        // 128 x 68

    const int bh = blockIdx.y;
    const int qx = (int)gridDim.x - 1 - (int)blockIdx.x;   // big tiles first
    const int q0 = qx * 128;
    const float* Qb = Qg + (size_t)bh * T_ * D_;
    const float* Kb = Kg + (size_t)bh * T_ * D_;
    const float* Vb = Vg + (size_t)bh * T_ * D_;

    const int tid = threadIdx.x;
    const int warp = tid >> 5, lane = tid & 31;
    const int rg = lane & 7, cg = lane >> 3;
    const int r0 = warp * 16 + rg;
    const int r1 = r0 + 8;
    const int qrow0 = q0 + r0, qrow1 = q0 + r1;

    // load Q tile (pre-scaled by 1/sqrt(D) = 0.125)
#pragma unroll
    for (int it = 0; it < 8; it++) {
        int g = it * 1024 + tid * 4;
        int r = g >> 6, c = g & 63;
        float4 v = *(const float4*)(Qb + (size_t)(q0 + r) * D_ + c);
        v.x *= 0.125f; v.y *= 0.125f; v.z *= 0.125f; v.w *= 0.125f;
        *(float4*)&sQ[r * ASTR + c] = v;
    }

    float O0[16], O1[16];
#pragma unroll
    for (int j = 0; j < 16; j++) { O0[j] = 0.f; O1[j] = 0.f; }
    float m0 = -1e30f, m1 = -1e30f, l0 = 0.f, l1 = 0.f;

    const int ntiles = 2 * qx + 2;
    for (int kt = 0; kt < ntiles; kt++) {
        const int k0g = kt * 64;
        __syncthreads();
#pragma unroll
        for (int it = 0; it < 4; it++) {
            int g = it * 1024 + tid * 4;
            int r = g >> 6, c = g & 63;
            *(float4*)&sK[r * ASTR + c] = *(const float4*)(Kb + (size_t)(k0g + r) * D_ + c);
            *(float4*)&sV[r * ASTR + c] = *(const float4*)(Vb + (size_t)(k0g + r) * D_ + c);
        }
        __syncthreads();

        // ---- S = Q @ K^T (2 rows x 16 cols per lane; col = j*4+cg) ----
        float S0[16], S1[16];
#pragma unroll
        for (int j = 0; j < 16; j++) { S0[j] = 0.f; S1[j] = 0.f; }
#pragma unroll 2
        for (int d4 = 0; d4 < 16; d4++) {
            float4 qa = *(const float4*)&sQ[r0 * ASTR + d4 * 4];
            float4 qb = *(const float4*)&sQ[r1 * ASTR + d4 * 4];
#pragma unroll
            for (int j = 0; j < 16; j++) {
                float4 kv = *(const float4*)&sK[(j * 4 + cg) * ASTR + d4 * 4];
                S0[j] = fmaf(qa.x, kv.x, S0[j]);
                S0[j] = fmaf(qa.y, kv.y, S0[j]);
                S0[j] = fmaf(qa.z, kv.z, S0[j]);
                S0[j] = fmaf(qa.w, kv.w, S0[j]);
                S1[j] = fmaf(qb.x, kv.x, S1[j]);
                S1[j] = fmaf(qb.y, kv.y, S1[j]);
                S1[j] = fmaf(qb.z, kv.z, S1[j]);
                S1[j] = fmaf(qb.w, kv.w, S1[j]);
            }
        }

        // ---- causal mask ----
        if (k0g + 63 > qrow0) {
#pragma unroll
            for (int j = 0; j < 16; j++) {
                int kc = k0g + j * 4 + cg;
                if (kc > qrow0) S0[j] = -1e30f;
                if (kc > qrow1) S1[j] = -1e30f;
            }
        }

        // ---- online softmax ----
        float mx0 = S0[0], mx1 = S1[0];
#pragma unroll
        for (int j = 1; j < 16; j++) { mx0 = fmaxf(mx0, S0[j]); mx1 = fmaxf(mx1, S1[j]); }
        mx0 = fmaxf(mx0, __shfl_xor_sync(0xffffffffu, mx0, 8));
        mx0 = fmaxf(mx0, __shfl_xor_sync(0xffffffffu, mx0, 16));
        mx1 = fmaxf(mx1, __shfl_xor_sync(0xffffffffu, mx1, 8));
        mx1 = fmaxf(mx1, __shfl_xor_sync(0xffffffffu, mx1, 16));
        float mn0 = fmaxf(m0, mx0), mn1 = fmaxf(m1, mx1);
        float c0 = exp2f((m0 - mn0) * 1.44269504f);
        float c1 = exp2f((m1 - mn1) * 1.44269504f);
        m0 = mn0; m1 = mn1;

        float rs0 = 0.f, rs1 = 0.f;
#pragma unroll
        for (int j = 0; j < 16; j++) {
            float p0 = exp2f((S0[j] - mn0) * 1.44269504f);
            float p1 = exp2f((S1[j] - mn1) * 1.44269504f);
            rs0 += p0; rs1 += p1;
            sP[r0 * ASTR + j * 4 + cg] = p0;
            sP[r1 * ASTR + j * 4 + cg] = p1;
        }
        rs0 += __shfl_xor_sync(0xffffffffu, rs0, 8);
        rs0 += __shfl_xor_sync(0xffffffffu, rs0, 16);
        rs1 += __shfl_xor_sync(0xffffffffu, rs1, 8);
        rs1 += __shfl_xor_sync(0xffffffffu, rs1, 16);
        l0 = l0 * c0 + rs0;
        l1 = l1 * c1 + rs1;
#pragma unroll
        for (int j = 0; j < 16; j++) { O0[j] *= c0; O1[j] *= c1; }
        __syncwarp();

        // ---- O += P @ V (d-col of lane = cg*16 + local j; swizzled V reads) ----
#pragma unroll 2
        for (int k4 = 0; k4 < 16; k4++) {
            float4 p0 = *(const float4*)&sP[r0 * ASTR + k4 * 4];
            float4 p1 = *(const float4*)&sP[r1 * ASTR + k4 * 4];
            float pa0[4] = {p0.x, p0.y, p0.z, p0.w};
            float pa1[4] = {p1.x, p1.y, p1.z, p1.w};
#pragma unroll
            for (int kk = 0; kk < 4; kk++) {
                int kv = k4 * 4 + kk;
#pragma unroll
                for (int j4 = 0; j4 < 4; j4++) {
                    int dj = (j4 + cg) & 3;
                    float4 v = *(const float4*)&sV[kv * ASTR + cg * 16 + dj * 4];
                    O0[dj * 4 + 0] = fmaf(pa0[kk], v.x, O0[dj * 4 + 0]);
                    O0[dj * 4 + 1] = fmaf(pa0[kk], v.y, O0[dj * 4 + 1]);
                    O0[dj * 4 + 2] = fmaf(pa0[kk], v.z, O0[dj * 4 + 2]);
                    O0[dj * 4 + 3] = fmaf(pa0[kk], v.w, O0[dj * 4 + 3]);
                    O1[dj * 4 + 0] = fmaf(pa1[kk], v.x, O1[dj * 4 + 0]);
                    O1[dj * 4 + 1] = fmaf(pa1[kk], v.y, O1[dj * 4 + 1]);
                    O1[dj * 4 + 2] = fmaf(pa1[kk], v.z, O1[dj * 4 + 2]);
                    O1[dj * 4 + 3] = fmaf(pa1[kk], v.w, O1[dj * 4 + 3]);
                }
            }
        }
    }

    // ---- epilogue: normalize and write [B,T,H*D] ----
    float inv0 = 1.f / l0, inv1 = 1.f / l1;
    int b = bh >> 4, h = bh & 15;
    float* o0 = Og + (size_t)(b * T_ + qrow0) * C_ + h * 64 + cg * 16;
    float* o1 = Og + (size_t)(b * T_ + qrow1) * C_ + h * 64 + cg * 16;
#pragma unroll
    for (int j4 = 0; j4 < 4; j4++) {
        float4 a, c;
        a.x = O0[j4 * 4 + 0] * inv0; a.y = O0[j4 * 4 + 1] * inv0;
        a.z = O0[j4 * 4 + 2] * inv0; a.w = O0[j4 * 4 + 3] * inv0;
        c.x = O1[j4 * 4 + 0] * inv1; c.y = O1[j4 * 4 + 1] * inv1;
        c.z = O1[j4 * 4 + 2] * inv1; c.w = O1[j4 * 4 + 3] * inv1;
        *(float4*)(o0 + j4 * 4) = a;
        *(float4*)(o1 + j4 * 4) = c;
    }
}

// ---------------- launcher ----------------
extern "C" void kernel_launch(void* const* d_in, const int* in_sizes, int n_in,
                              void* d_out, int out_size)
{
    (void)in_sizes; (void)n_in; (void)out_size;
    const float* x      = (const float*)d_in[0];
    // d_in[1] = mask (bool causal tril, deterministic) — not needed
    const float* w_attn = (const float*)d_in[2];
    const float* b_attn = (const float*)d_in[3];
    const float* w_proj = (const float*)d_in[4];
    const float* b_proj = (const float*)d_in[5];
    float* out = (float*)d_out;

    float *qkv, *q, *k, *v, *att, *xsq, *osq, *wsq1, *wsq2;
    cudaGetSymbolAddress((void**)&qkv,  g_qkv);
    cudaGetSymbolAddress((void**)&q,    g_q);
    cudaGetSymbolAddress((void**)&k,    g_k);
    cudaGetSymbolAddress((void**)&v,    g_v);
    cudaGetSymbolAddress((void**)&att,  g_att);
    cudaGetSymbolAddress((void**)&xsq,  g_xsq);
    cudaGetSymbolAddress((void**)&osq,  g_osq);
    cudaGetSymbolAddress((void**)&wsq1, g_wsq1);
    cudaGetSymbolAddress((void**)&wsq2, g_wsq2);

    const float scale1 = (float)(sqrt(3072.0) / log1p(3072.0));
    const float scale2 = (float)(sqrt(1024.0) / log1p(1024.0));

    rowsq_kernel<<<M_, 256>>>(x, xsq);
    colsq_kernel<<<N1_ / 64, 256>>>(w_attn, wsq1, C_, N1_);
    colsq_kernel<<<C_ / 64, 256>>>(w_proj, wsq2, C_, C_);

    yat_gemm_kernel<<<dim3(N1_ / 128, M_ / 128), 256>>>(
        x, w_attn, xsq, wsq1, b_attn, qkv, M_, N1_, C_, scale1);

    rope_split_kernel<<<dim3(T_, B_), 512>>>(qkv, q, k, v);

    cudaFuncSetAttribute(attn_kernel, cudaFuncAttributeMaxDynamicSharedMemorySize,
                         ATTN_SMEM);
    attn_kernel<<<dim3(T_ / 128, B_ * H_), 256, ATTN_SMEM>>>(q, k, v, att);

    rowsq_kernel<<<M_, 256>>>(att, osq);

    yat_gemm_kernel<<<dim3(C_ / 128, M_ / 128), 256>>>(
        att, w_proj, osq, wsq2, b_proj, out, M_, C_, C_, scale2);
}

// round 2
// speedup vs baseline: 5.8601x; 5.8601x over previous
#include <cuda_runtime.h>
#include <math.h>

#define B_   2
#define T_   2048
#define C_   1024
#define H_   16
#define D_   64
#define M_   4096          // B_*T_
#define N1_  3072          // 3*C_
#define EPS_ 1e-6f

// ---------------- scratch (device globals; no allocation allowed) ----------------
__device__ float g_qkv[(size_t)M_ * N1_];          // 48 MB
__device__ float g_q[(size_t)B_ * H_ * T_ * D_];   // 16 MB, layout [B,H,D,T]
__device__ float g_k[(size_t)B_ * H_ * T_ * D_];   // 16 MB, layout [B,H,D,T]
__device__ float g_v[(size_t)B_ * H_ * T_ * D_];   // 16 MB, layout [B,H,T,D]
__device__ float g_att[(size_t)M_ * C_];           // 16 MB
__device__ float g_xsq[M_];
__device__ float g_osq[M_];
__device__ float g_wsq1[N1_];
__device__ float g_wsq2[C_];

__device__ __forceinline__ float fast_exp2(float x) {
    float r;
    asm("ex2.approx.ftz.f32 %0, %1;" : "=f"(r) : "f"(x));
    return r;
}

// ---------------- row sum-of-squares (row length = 1024) ----------------
__global__ void rowsq_kernel(const float* __restrict__ X, float* __restrict__ out)
{
    int m = blockIdx.x;
    const float* x = X + (size_t)m * C_;
    int tid = threadIdx.x;
    float4 v = *(const float4*)(x + tid * 4);
    float s = v.x * v.x + v.y * v.y + v.z * v.z + v.w * v.w;
#pragma unroll
    for (int o = 16; o; o >>= 1) s += __shfl_xor_sync(0xffffffffu, s, o);
    __shared__ float red[8];
    if ((tid & 31) == 0) red[tid >> 5] = s;
    __syncthreads();
    if (tid == 0) {
        float t = 0.f;
#pragma unroll
        for (int i = 0; i < 8; i++) t += red[i];
        out[m] = t;
    }
}

// ---------------- column sum-of-squares of W[K][N] ----------------
__global__ void colsq_kernel(const float* __restrict__ W, float* __restrict__ out,
                             int K, int N)
{
    __shared__ float red[4][64];
    int tx = threadIdx.x & 63, ty = threadIdx.x >> 6;
    int n = blockIdx.x * 64 + tx;
    float s = 0.f;
    for (int k = ty; k < K; k += 4) {
        float w = W[(size_t)k * N + n];
        s = fmaf(w, w, s);
    }
    red[ty][tx] = s;
    __syncthreads();
    if (ty == 0) out[n] = red[0][tx] + red[1][tx] + red[2][tx] + red[3][tx];
}

// ---------------- yat-dense GEMM: C = yat(A[M,K] @ B[K,N]) ----------------
__global__ void __launch_bounds__(256) yat_gemm_kernel(
    const float* __restrict__ A, const float* __restrict__ Bw,
    const float* __restrict__ asq, const float* __restrict__ bsq,
    const float* __restrict__ bias, float* __restrict__ Cout,
    int M, int N, int K, float scale)
{
    __shared__ float As[16][132];   // transposed A tile, padded
    __shared__ float Bs[16][128];

    const int tid = threadIdx.x;
    const int tr = tid >> 4, tc = tid & 15;
    const int rowBase = blockIdx.y * 128;
    const int colBase = blockIdx.x * 128;
    const int aRow = tid >> 2;
    const int aCol = (tid & 3) << 2;
    const int bRow = tid >> 5;
    const int bCol = (tid & 31) << 2;

    float acc[8][8];
#pragma unroll
    for (int i = 0; i < 8; i++)
#pragma unroll
        for (int j = 0; j < 8; j++) acc[i][j] = 0.f;

    const float* Ag = A + (size_t)rowBase * K;
    const float* Bg = Bw + colBase;

    for (int kt = 0; kt < K; kt += 16) {
#pragma unroll
        for (int p = 0; p < 2; p++) {
            float4 a = *(const float4*)(Ag + (size_t)(aRow + p * 64) * K + kt + aCol);
            As[aCol + 0][aRow + p * 64] = a.x;
            As[aCol + 1][aRow + p * 64] = a.y;
            As[aCol + 2][aRow + p * 64] = a.z;
            As[aCol + 3][aRow + p * 64] = a.w;
        }
#pragma unroll
        for (int p = 0; p < 2; p++) {
            *(float4*)&Bs[bRow + p * 8][bCol] =
                *(const float4*)(Bg + (size_t)(kt + bRow + p * 8) * N + bCol);
        }
        __syncthreads();
#pragma unroll
        for (int kk = 0; kk < 16; kk++) {
            float ra[8], rb[8];
            *(float4*)&ra[0] = *(const float4*)&As[kk][tr * 8];
            *(float4*)&ra[4] = *(const float4*)&As[kk][tr * 8 + 4];
            *(float4*)&rb[0] = *(const float4*)&Bs[kk][tc * 8];
            *(float4*)&rb[4] = *(const float4*)&Bs[kk][tc * 8 + 4];
#pragma unroll
            for (int i = 0; i < 8; i++)
#pragma unroll
                for (int j = 0; j < 8; j++)
                    acc[i][j] = fmaf(ra[i], rb[j], acc[i][j]);
        }
        __syncthreads();
    }

#pragma unroll
    for (int i = 0; i < 8; i++) {
        int row = rowBase + tr * 8 + i;
        float av = asq[row];
        float* crow = Cout + (size_t)row * N + colBase + tc * 8;
#pragma unroll
        for (int jv = 0; jv < 2; jv++) {
            float r[4];
#pragma unroll
            for (int e = 0; e < 4; e++) {
                int j = jv * 4 + e;
                int n = colBase + tc * 8 + j;
                float dot = acc[i][j];
                float dist = av + bsq[n] - 2.f * dot + EPS_;
                r[e] = dot * dot / dist * scale + bias[n];
            }
            float4 o;
            o.x = r[0]; o.y = r[1]; o.z = r[2]; o.w = r[3];
            *(float4*)(crow + jv * 4) = o;
        }
    }
}

// ---------------- RoPE + split qkv[B,T,3,H,D] -> Q/K d-major [B,H,D,T], V [B,H,T,D] ----------------
__global__ void rope_split_kernel(const float* __restrict__ qkv,
                                  float* __restrict__ Q, float* __restrict__ K,
                                  float* __restrict__ V)
{
    int t = blockIdx.x, b = blockIdx.y;
    int tid = threadIdx.x;            // 512 = 16 heads * 32 pairs
    int h = tid >> 5, i = tid & 31;
    const float* row = qkv + (size_t)(b * T_ + t) * N1_;
    float fr = powf(10000.0f, -(float)i / 32.0f);
    float ang = (float)t * fr;
    float s, c;
    sincosf(ang, &s, &c);
    int base = h * 64 + 2 * i;

    // Q,K: [B,H,D,T]
    size_t oq = ((size_t)(b * H_ + h) * D_ + 2 * i) * T_ + t;
    float q0 = row[base], q1 = row[base + 1];
    Q[oq]      = q0 * c - q1 * s;
    Q[oq + T_] = q1 * c + q0 * s;
    float k0 = row[C_ + base], k1 = row[C_ + base + 1];
    K[oq]      = k0 * c - k1 * s;
    K[oq + T_] = k1 * c + k0 * s;
    // V: [B,H,T,D]
    size_t ov = ((size_t)(b * H_ + h) * T_ + t) * D_ + 2 * i;
    V[ov]     = row[2 * C_ + base];
    V[ov + 1] = row[2 * C_ + base + 1];
}

// ---------------- causal flash attention, fp32, BQ=BKV=64, 256 threads ----------------
// Thread tile 4x4. Q/K come in d-major so no transposes. Smem stride 68 (float4-aligned,
// conflict-free). Online softmax in registers via half-warp shuffles.
#define SSTR 68
#define ATTN_SMEM (4 * 64 * SSTR * 4)    // sQT + sKT + sV + sP = 69632 B

__global__ void __launch_bounds__(256, 2) attn_kernel(const float* __restrict__ Qg,
                                                      const float* __restrict__ Kg,
                                                      const float* __restrict__ Vg,
                                                      float* __restrict__ Og)
{
    extern __shared__ float sm[];
    float* sQT = sm;                 // [64 d][64 q]
    float* sKT = sQT + 64 * SSTR;    // [64 d][64 k]
    float* sV  = sKT + 64 * SSTR;    // [64 k][64 d]
    float* sP  = sV  + 64 * SSTR;    // [64 q][64 k]

    const int bh = blockIdx.y;
    const int qx = 31 - (int)blockIdx.x;   // heavy blocks first
    const int q0 = qx * 64;
    const float* Qb = Qg + (size_t)bh * D_ * T_;
    const float* Kb = Kg + (size_t)bh * D_ * T_;
    const float* Vb = Vg + (size_t)bh * T_ * D_;

    const int tid = threadIdx.x;
    const int tr = tid >> 4;     // row group (0..15), rows tr*4..tr*4+3
    const int tc = tid & 15;     // col group (0..15), cols tc*4..tc*4+3

    // load Q tile, d-major, pre-scaled by (1/8)*log2(e)
    const float QSC = 0.125f * 1.4426950408889634f;
#pragma unroll
    for (int it = 0; it < 4; it++) {
        int idx = it * 1024 + tid * 4;
        int d = idx >> 6, c = idx & 63;
        float4 v = *(const float4*)(Qb + (size_t)d * T_ + q0 + c);
        v.x *= QSC; v.y *= QSC; v.z *= QSC; v.w *= QSC;
        *(float4*)&sQT[d * SSTR + c] = v;
    }

    float O[4][4];
#pragma unroll
    for (int i = 0; i < 4; i++)
#pragma unroll
        for (int j = 0; j < 4; j++) O[i][j] = 0.f;
    float m[4] = {-1e30f, -1e30f, -1e30f, -1e30f};
    float l[4] = {0.f, 0.f, 0.f, 0.f};

    for (int kt = 0; kt <= qx; kt++) {
        const int k0 = kt * 64;
        __syncthreads();
#pragma unroll
        for (int it = 0; it < 4; it++) {
            int idx = it * 1024 + tid * 4;
            int r = idx >> 6, c = idx & 63;
            *(float4*)&sKT[r * SSTR + c] = *(const float4*)(Kb + (size_t)r * T_ + k0 + c);
            *(float4*)&sV[r * SSTR + c]  = *(const float4*)(Vb + (size_t)(k0 + r) * D_ + c);
        }
        __syncthreads();

        // ---- S = Q^T K (both d-major): S[i][j], rows tr*4+i, cols tc*4+j ----
        float S[4][4];
#pragma unroll
        for (int i = 0; i < 4; i++)
#pragma unroll
            for (int j = 0; j < 4; j++) S[i][j] = 0.f;

#pragma unroll 8
        for (int d = 0; d < 64; d++) {
            float4 ra = *(const float4*)&sQT[d * SSTR + tr * 4];
            float4 rb = *(const float4*)&sKT[d * SSTR + tc * 4];
            S[0][0] = fmaf(ra.x, rb.x, S[0][0]);
            S[0][1] = fmaf(ra.x, rb.y, S[0][1]);
            S[0][2] = fmaf(ra.x, rb.z, S[0][2]);
            S[0][3] = fmaf(ra.x, rb.w, S[0][3]);
            S[1][0] = fmaf(ra.y, rb.x, S[1][0]);
            S[1][1] = fmaf(ra.y, rb.y, S[1][1]);
            S[1][2] = fmaf(ra.y, rb.z, S[1][2]);
            S[1][3] = fmaf(ra.y, rb.w, S[1][3]);
            S[2][0] = fmaf(ra.z, rb.x, S[2][0]);
            S[2][1] = fmaf(ra.z, rb.y, S[2][1]);
            S[2][2] = fmaf(ra.z, rb.z, S[2][2]);
            S[2][3] = fmaf(ra.z, rb.w, S[2][3]);
            S[3][0] = fmaf(ra.w, rb.x, S[3][0]);
            S[3][1] = fmaf(ra.w, rb.y, S[3][1]);
            S[3][2] = fmaf(ra.w, rb.z, S[3][2]);
            S[3][3] = fmaf(ra.w, rb.w, S[3][3]);
        }

        // ---- causal mask (diagonal tile only; q0 == k0 there) ----
        if (kt == qx) {
#pragma unroll
            for (int i = 0; i < 4; i++)
#pragma unroll
                for (int j = 0; j < 4; j++)
                    if (tc * 4 + j > tr * 4 + i) S[i][j] = -1e30f;
        }

        // ---- online softmax (S already in log2 units) ----
#pragma unroll
        for (int i = 0; i < 4; i++) {
            float mx = fmaxf(fmaxf(S[i][0], S[i][1]), fmaxf(S[i][2], S[i][3]));
            mx = fmaxf(mx, __shfl_xor_sync(0xffffffffu, mx, 1));
            mx = fmaxf(mx, __shfl_xor_sync(0xffffffffu, mx, 2));
            mx = fmaxf(mx, __shfl_xor_sync(0xffffffffu, mx, 4));
            mx = fmaxf(mx, __shfl_xor_sync(0xffffffffu, mx, 8));
            float mn = fmaxf(m[i], mx);
            float cf = fast_exp2(m[i] - mn);
            m[i] = mn;
            float p0 = fast_exp2(S[i][0] - mn);
            float p1 = fast_exp2(S[i][1] - mn);
            float p2 = fast_exp2(S[i][2] - mn);
            float p3 = fast_exp2(S[i][3] - mn);
            float rs = (p0 + p1) + (p2 + p3);
            rs += __shfl_xor_sync(0xffffffffu, rs, 1);
            rs += __shfl_xor_sync(0xffffffffu, rs, 2);
            rs += __shfl_xor_sync(0xffffffffu, rs, 4);
            rs += __shfl_xor_sync(0xffffffffu, rs, 8);
            l[i] = l[i] * cf + rs;
            O[i][0] *= cf; O[i][1] *= cf; O[i][2] *= cf; O[i][3] *= cf;
            float4 pv; pv.x = p0; pv.y = p1; pv.z = p2; pv.w = p3;
            *(float4*)&sP[(tr * 4 + i) * SSTR + tc * 4] = pv;
        }
        __syncthreads();

        // ---- O += P @ V : rows tr*4+i, d-cols tc*4+j ----
#pragma unroll 4
        for (int k4 = 0; k4 < 16; k4++) {
            float4 pa0 = *(const float4*)&sP[(tr * 4 + 0) * SSTR + k4 * 4];
            float4 pa1 = *(const float4*)&sP[(tr * 4 + 1) * SSTR + k4 * 4];
            float4 pa2 = *(const float4*)&sP[(tr * 4 + 2) * SSTR + k4 * 4];
            float4 pa3 = *(const float4*)&sP[(tr * 4 + 3) * SSTR + k4 * 4];
#pragma unroll
            for (int kk = 0; kk < 4; kk++) {
                float4 vb = *(const float4*)&sV[(k4 * 4 + kk) * SSTR + tc * 4];
                float p0 = kk == 0 ? pa0.x : kk == 1 ? pa0.y : kk == 2 ? pa0.z : pa0.w;
                float p1 = kk == 0 ? pa1.x : kk == 1 ? pa1.y : kk == 2 ? pa1.z : pa1.w;
                float p2 = kk == 0 ? pa2.x : kk == 1 ? pa2.y : kk == 2 ? pa2.z : pa2.w;
                float p3 = kk == 0 ? pa3.x : kk == 1 ? pa3.y : kk == 2 ? pa3.z : pa3.w;
                O[0][0] = fmaf(p0, vb.x, O[0][0]);
                O[0][1] = fmaf(p0, vb.y, O[0][1]);
                O[0][2] = fmaf(p0, vb.z, O[0][2]);
                O[0][3] = fmaf(p0, vb.w, O[0][3]);
                O[1][0] = fmaf(p1, vb.x, O[1][0]);
                O[1][1] = fmaf(p1, vb.y, O[1][1]);
                O[1][2] = fmaf(p1, vb.z, O[1][2]);
                O[1][3] = fmaf(p1, vb.w, O[1][3]);
                O[2][0] = fmaf(p2, vb.x, O[2][0]);
                O[2][1] = fmaf(p2, vb.y, O[2][1]);
                O[2][2] = fmaf(p2, vb.z, O[2][2]);
                O[2][3] = fmaf(p3 == p3 ? p2 : p2, vb.w, O[2][3]);
                O[3][0] = fmaf(p3, vb.x, O[3][0]);
                O[3][1] = fmaf(p3, vb.y, O[3][1]);
                O[3][2] = fmaf(p3, vb.z, O[3][2]);
                O[3][3] = fmaf(p3, vb.w, O[3][3]);
            }
        }
    }

    // ---- epilogue: normalize, write [B,T,H*D] ----
    int b = bh >> 4, h = bh & 15;
#pragma unroll
    for (int i = 0; i < 4; i++) {
        int row = q0 + tr * 4 + i;
        float inv = 1.f / l[i];
        float4 o;
        o.x = O[i][0] * inv; o.y = O[i][1] * inv;
        o.z = O[i][2] * inv; o.w = O[i][3] * inv;
        *(float4*)(Og + (size_t)(b * T_ + row) * C_ + h * 64 + tc * 4) = o;
    }
}

// ---------------- launcher ----------------
extern "C" void kernel_launch(void* const* d_in, const int* in_sizes, int n_in,
                              void* d_out, int out_size)
{
    (void)in_sizes; (void)n_in; (void)out_size;
    const float* x      = (const float*)d_in[0];
    const float* w_attn = (const float*)d_in[2];
    const float* b_attn = (const float*)d_in[3];
    const float* w_proj = (const float*)d_in[4];
    const float* b_proj = (const float*)d_in[5];
    float* out = (float*)d_out;

    float *qkv, *q, *k, *v, *att, *xsq, *osq, *wsq1, *wsq2;
    cudaGetSymbolAddress((void**)&qkv,  g_qkv);
    cudaGetSymbolAddress((void**)&q,    g_q);
    cudaGetSymbolAddress((void**)&k,    g_k);
    cudaGetSymbolAddress((void**)&v,    g_v);
    cudaGetSymbolAddress((void**)&att,  g_att);
    cudaGetSymbolAddress((void**)&xsq,  g_xsq);
    cudaGetSymbolAddress((void**)&osq,  g_osq);
    cudaGetSymbolAddress((void**)&wsq1, g_wsq1);
    cudaGetSymbolAddress((void**)&wsq2, g_wsq2);

    const float scale1 = (float)(sqrt(3072.0) / log1p(3072.0));
    const float scale2 = (float)(sqrt(1024.0) / log1p(1024.0));

    rowsq_kernel<<<M_, 256>>>(x, xsq);
    colsq_kernel<<<N1_ / 64, 256>>>(w_attn, wsq1, C_, N1_);
    colsq_kernel<<<C_ / 64, 256>>>(w_proj, wsq2, C_, C_);

    yat_gemm_kernel<<<dim3(N1_ / 128, M_ / 128), 256>>>(
        x, w_attn, xsq, wsq1, b_attn, qkv, M_, N1_, C_, scale1);

    rope_split_kernel<<<dim3(T_, B_), 512>>>(qkv, q, k, v);

    cudaFuncSetAttribute(attn_kernel, cudaFuncAttributeMaxDynamicSharedMemorySize,
                         ATTN_SMEM);
    attn_kernel<<<dim3(T_ / 64, B_ * H_), 256, ATTN_SMEM>>>(q, k, v, att);

    rowsq_kernel<<<M_, 256>>>(att, osq);

    yat_gemm_kernel<<<dim3(C_ / 128, M_ / 128), 256>>>(
        att, w_proj, osq, wsq2, b_proj, out, M_, C_, C_, scale2);
}

// round 4
// speedup vs baseline: 8.3469x; 1.4244x over previous
#include <cuda_runtime.h>
#include <cuda_bf16.h>
#include <math.h>
#include <stdint.h>

#define B_   2
#define T_   2048
#define C_   1024
#define H_   16
#define D_   64
#define M_   4096          // B_*T_
#define N1_  3072          // 3*C_
#define EPS_ 1e-6f

// ---------------- scratch (device globals; no allocation allowed) ----------------
__device__ float g_qkv[(size_t)M_ * N1_];          // 48 MB
__device__ float g_q[(size_t)B_ * H_ * T_ * D_];   // [B,H,D,T]
__device__ float g_k[(size_t)B_ * H_ * T_ * D_];   // [B,H,D,T]
__device__ float g_v[(size_t)B_ * H_ * T_ * D_];   // [B,H,T,D]
__device__ float g_att[(size_t)M_ * C_];
__device__ float g_xsq[M_];
__device__ float g_osq[M_];
__device__ float g_wsq1[N1_];
__device__ float g_wsq2[C_];
// bf16 hi/lo operands
__device__ __nv_bfloat16 g_xh[(size_t)M_ * C_];
__device__ __nv_bfloat16 g_xl[(size_t)M_ * C_];
__device__ __nv_bfloat16 g_ah[(size_t)M_ * C_];
__device__ __nv_bfloat16 g_al[(size_t)M_ * C_];
__device__ __nv_bfloat16 g_w1h[(size_t)N1_ * C_];  // [N,K] transposed
__device__ __nv_bfloat16 g_w1l[(size_t)N1_ * C_];
__device__ __nv_bfloat16 g_w2h[(size_t)C_ * C_];
__device__ __nv_bfloat16 g_w2l[(size_t)C_ * C_];

__device__ __forceinline__ float fast_exp2(float x) {
    float r;
    asm("ex2.approx.ftz.f32 %0, %1;" : "=f"(r) : "f"(x));
    return r;
}

__device__ __forceinline__ uint32_t smem_u32(const void* p) {
    return (uint32_t)__cvta_generic_to_shared(p);
}

// ======================= small helper kernels =======================

__global__ void rowsq_kernel(const float* __restrict__ X, float* __restrict__ out)
{
    int m = blockIdx.x;
    const float* x = X + (size_t)m * C_;
    int tid = threadIdx.x;
    float4 v = *(const float4*)(x + tid * 4);
    float s = v.x * v.x + v.y * v.y + v.z * v.z + v.w * v.w;
#pragma unroll
    for (int o = 16; o; o >>= 1) s += __shfl_xor_sync(0xffffffffu, s, o);
    __shared__ float red[8];
    if ((tid & 31) == 0) red[tid >> 5] = s;
    __syncthreads();
    if (tid == 0) {
        float t = 0.f;
#pragma unroll
        for (int i = 0; i < 8; i++) t += red[i];
        out[m] = t;
    }
}

__global__ void colsq_kernel(const float* __restrict__ W, float* __restrict__ out,
                             int K, int N)
{
    __shared__ float red[4][64];
    int tx = threadIdx.x & 63, ty = threadIdx.x >> 6;
    int n = blockIdx.x * 64 + tx;
    float s = 0.f;
    for (int k = ty; k < K; k += 4) {
        float w = W[(size_t)k * N + n];
        s = fmaf(w, w, s);
    }
    red[ty][tx] = s;
    __syncthreads();
    if (ty == 0) out[n] = red[0][tx] + red[1][tx] + red[2][tx] + red[3][tx];
}

// elementwise fp32 -> bf16 hi/lo split
__global__ void xconv_kernel(const float* __restrict__ X,
                             __nv_bfloat16* __restrict__ Xh,
                             __nv_bfloat16* __restrict__ Xl)
{
    size_t i = ((size_t)blockIdx.x * 256 + threadIdx.x) * 4;
    float4 v = *(const float4*)(X + i);
    __nv_bfloat16 h0 = __float2bfloat16(v.x);
    __nv_bfloat16 h1 = __float2bfloat16(v.y);
    __nv_bfloat16 h2 = __float2bfloat16(v.z);
    __nv_bfloat16 h3 = __float2bfloat16(v.w);
    __nv_bfloat162 a, b;
    a.x = h0; a.y = h1; b.x = h2; b.y = h3;
    *(__nv_bfloat162*)(Xh + i)     = a;
    *(__nv_bfloat162*)(Xh + i + 2) = b;
    __nv_bfloat162 c, d;
    c.x = __float2bfloat16(v.x - __bfloat162float(h0));
    c.y = __float2bfloat16(v.y - __bfloat162float(h1));
    d.x = __float2bfloat16(v.z - __bfloat162float(h2));
    d.y = __float2bfloat16(v.w - __bfloat162float(h3));
    *(__nv_bfloat162*)(Xl + i)     = c;
    *(__nv_bfloat162*)(Xl + i + 2) = d;
}

// W[K][N] fp32 -> WT[N][K] bf16 hi/lo (32x32 smem transpose)
__global__ void wconv_kernel(const float* __restrict__ W,
                             __nv_bfloat16* __restrict__ WhT,
                             __nv_bfloat16* __restrict__ WlT,
                             int K, int N)
{
    __shared__ float tile[32][33];
    int bx = blockIdx.x, by = blockIdx.y;
    int tx = threadIdx.x & 31, ty = threadIdx.x >> 5;
#pragma unroll
    for (int i = ty; i < 32; i += 8)
        tile[i][tx] = W[(size_t)(by * 32 + i) * N + bx * 32 + tx];
    __syncthreads();
#pragma unroll
    for (int i = ty; i < 32; i += 8) {
        int n = bx * 32 + i, k = by * 32 + tx;
        float v = tile[tx][i];
        __nv_bfloat16 h = __float2bfloat16(v);
        WhT[(size_t)n * K + k] = h;
        WlT[(size_t)n * K + k] = __float2bfloat16(v - __bfloat162float(h));
    }
}

// ======================= mma.sync helpers (portable sm_80+ path) =======================

#define LDSM4(r0, r1, r2, r3, addr) \
    asm volatile("ldmatrix.sync.aligned.m8n8.x4.shared.b16 {%0,%1,%2,%3}, [%4];" \
                 : "=r"(r0), "=r"(r1), "=r"(r2), "=r"(r3) : "r"(addr))

#define MMA16816(d, a, b) \
    asm volatile("mma.sync.aligned.m16n8k16.row.col.f32.bf16.bf16.f32 " \
                 "{%0,%1,%2,%3}, {%4,%5,%6,%7}, {%8,%9}, {%0,%1,%2,%3};" \
                 : "+f"((d)[0]), "+f"((d)[1]), "+f"((d)[2]), "+f"((d)[3]) \
                 : "r"((a)[0]), "r"((a)[1]), "r"((a)[2]), "r"((a)[3]), \
                   "r"((b)[0]), "r"((b)[1]))

__device__ __forceinline__ void cp16(uint32_t dst, const void* src) {
    asm volatile("cp.async.cg.shared.global [%0], [%1], 16;" :: "r"(dst), "l"(src));
}

// ======================= yat mma.sync GEMM (bf16x3 fp32-emulation) =======================
// CTA 128(M) x 128(N), BK=32, 8 warps (2 m x 4 n), warp tile 64x32.
// Smem rows: 32 bf16 = 64B data, stride 80B -> ldmatrix conflict-free.
#define ROWB   80
#define TILEB  (128 * ROWB)        // 10240 B per matrix tile
#define OFF_AH 0
#define OFF_AL (1 * TILEB)
#define OFF_BH (2 * TILEB)
#define OFF_BL (3 * TILEB)
#define STAGEB (4 * TILEB)         // 40960 B
#define MMA_SMEM (2 * STAGEB)      // 81920 B

__device__ __forceinline__ void load_stage(
    uint32_t st, const __nv_bfloat16* Agh, const __nv_bfloat16* Agl,
    const __nv_bfloat16* Bgh, const __nv_bfloat16* Bgl,
    int k0, int K, int tid)
{
#pragma unroll
    for (int it = 0; it < 2; it++) {
        int idx = it * 256 + tid;
        int row = idx >> 2;
        int ch = (idx & 3) * 16;                 // byte chunk within 64B row
        uint32_t dst = (uint32_t)row * ROWB + ch;
        size_t srcel = (size_t)row * K + k0;     // element offset, +ch bytes
        cp16(st + OFF_AH + dst, (const char*)(Agh + srcel) + ch);
        cp16(st + OFF_AL + dst, (const char*)(Agl + srcel) + ch);
        cp16(st + OFF_BH + dst, (const char*)(Bgh + srcel) + ch);
        cp16(st + OFF_BL + dst, (const char*)(Bgl + srcel) + ch);
    }
}

__global__ void __launch_bounds__(256, 2) yat_mma_gemm_kernel(
    const __nv_bfloat16* __restrict__ Ah, const __nv_bfloat16* __restrict__ Al,
    const __nv_bfloat16* __restrict__ BhT, const __nv_bfloat16* __restrict__ BlT,
    const float* __restrict__ asq, const float* __restrict__ bsq,
    const float* __restrict__ bias, float* __restrict__ Cout,
    int M, int N, int K, float scale)
{
    extern __shared__ char smem[];
    const uint32_t sb = smem_u32(smem);

    const int tid = threadIdx.x;
    const int wid = tid >> 5, lane = tid & 31;
    const int warpM = wid >> 2;          // 0..1
    const int warpN = wid & 3;           // 0..3
    const int rowBase = blockIdx.y * 128;
    const int colBase = blockIdx.x * 128;
    const int NC = K >> 5;               // chunks of 32

    const __nv_bfloat16* Agh = Ah + (size_t)rowBase * K;
    const __nv_bfloat16* Agl = Al + (size_t)rowBase * K;
    const __nv_bfloat16* Bgh = BhT + (size_t)colBase * K;
    const __nv_bfloat16* Bgl = BlT + (size_t)colBase * K;

    // lane-derived ldmatrix address components
    const uint32_t aSel = (uint32_t)(lane & 15) * ROWB + (uint32_t)(lane >> 4) * 16;
    const uint32_t bSel = (uint32_t)(((lane >> 4) & 1) * 8 + (lane & 7)) * ROWB +
                          (uint32_t)((lane >> 3) & 1) * 16;

    float acc[4][4][4];
#pragma unroll
    for (int i = 0; i < 4; i++)
#pragma unroll
        for (int j = 0; j < 4; j++)
#pragma unroll
            for (int e = 0; e < 4; e++) acc[i][j][e] = 0.f;

    load_stage(sb, Agh, Agl, Bgh, Bgl, 0, K, tid);
    asm volatile("cp.async.commit_group;" ::: "memory");

    for (int c = 0; c < NC; c++) {
        if (c + 1 < NC) {
            load_stage(sb + (uint32_t)((c + 1) & 1) * STAGEB,
                       Agh, Agl, Bgh, Bgl, (c + 1) << 5, K, tid);
            asm volatile("cp.async.commit_group;" ::: "memory");
            asm volatile("cp.async.wait_group 1;" ::: "memory");
        } else {
            asm volatile("cp.async.wait_group 0;" ::: "memory");
        }
        __syncthreads();

        const uint32_t st = sb + (uint32_t)(c & 1) * STAGEB;
#pragma unroll
        for (int p = 0; p < 3; p++) {
            const uint32_t aBase = st + (p < 2 ? OFF_AH : OFF_AL) +
                                   (uint32_t)warpM * 64 * ROWB + aSel;
            const uint32_t bBase = st + (p == 1 ? OFF_BL : OFF_BH) +
                                   (uint32_t)warpN * 32 * ROWB + bSel;
#pragma unroll
            for (int ks = 0; ks < 2; ks++) {
                uint32_t a[4][4];
#pragma unroll
                for (int mt = 0; mt < 4; mt++)
                    LDSM4(a[mt][0], a[mt][1], a[mt][2], a[mt][3],
                          aBase + mt * (16 * ROWB) + ks * 32);
                uint32_t b[4][2];
#pragma unroll
                for (int nt2 = 0; nt2 < 2; nt2++) {
                    uint32_t r0, r1, r2, r3;
                    LDSM4(r0, r1, r2, r3, bBase + nt2 * (16 * ROWB) + ks * 32);
                    b[nt2 * 2 + 0][0] = r0; b[nt2 * 2 + 0][1] = r1;
                    b[nt2 * 2 + 1][0] = r2; b[nt2 * 2 + 1][1] = r3;
                }
#pragma unroll
                for (int mt = 0; mt < 4; mt++)
#pragma unroll
                    for (int nt = 0; nt < 4; nt++)
                        MMA16816(acc[mt][nt], a[mt], b[nt]);
            }
        }
        __syncthreads();
    }

    // ---- fused yat epilogue (fragment layout: rows lr, lr+8; col pair lc) ----
    const int lr = lane >> 2, lc = (lane & 3) * 2;
    const int mW = rowBase + warpM * 64;
    const int nW = colBase + warpN * 32;
#pragma unroll
    for (int mt = 0; mt < 4; mt++) {
        const int r0g = mW + mt * 16 + lr;
        const int r1g = r0g + 8;
        const float av0 = asq[r0g];
        const float av1 = asq[r1g];
#pragma unroll
        for (int nt = 0; nt < 4; nt++) {
            const int cg = nW + nt * 8 + lc;
            const float bq0 = bsq[cg], bq1 = bsq[cg + 1];
            const float bi0 = bias[cg], bi1 = bias[cg + 1];
            float d00 = acc[mt][nt][0], d01 = acc[mt][nt][1];
            float d10 = acc[mt][nt][2], d11 = acc[mt][nt][3];
            float2 o0, o1;
            o0.x = __fdividef(d00 * d00, av0 + bq0 - 2.f * d00 + EPS_) * scale + bi0;
            o0.y = __fdividef(d01 * d01, av0 + bq1 - 2.f * d01 + EPS_) * scale + bi1;
            o1.x = __fdividef(d10 * d10, av1 + bq0 - 2.f * d10 + EPS_) * scale + bi0;
            o1.y = __fdividef(d11 * d11, av1 + bq1 - 2.f * d11 + EPS_) * scale + bi1;
            *(float2*)(Cout + (size_t)r0g * N + cg) = o0;
            *(float2*)(Cout + (size_t)r1g * N + cg) = o1;
        }
    }
}

// ---------------- RoPE + split qkv[B,T,3,H,D] -> Q/K d-major [B,H,D,T], V [B,H,T,D] ----------------
__global__ void rope_split_kernel(const float* __restrict__ qkv,
                                  float* __restrict__ Q, float* __restrict__ K,
                                  float* __restrict__ V)
{
    int t = blockIdx.x, b = blockIdx.y;
    int tid = threadIdx.x;            // 512 = 16 heads * 32 pairs
    int h = tid >> 5, i = tid & 31;
    const float* row = qkv + (size_t)(b * T_ + t) * N1_;
    float fr = powf(10000.0f, -(float)i / 32.0f);
    float ang = (float)t * fr;
    float s, c;
    sincosf(ang, &s, &c);
    int base = h * 64 + 2 * i;

    size_t oq = ((size_t)(b * H_ + h) * D_ + 2 * i) * T_ + t;
    float q0 = row[base], q1 = row[base + 1];
    Q[oq]      = q0 * c - q1 * s;
    Q[oq + T_] = q1 * c + q0 * s;
    float k0 = row[C_ + base], k1 = row[C_ + base + 1];
    K[oq]      = k0 * c - k1 * s;
    K[oq + T_] = k1 * c + k0 * s;
    size_t ov = ((size_t)(b * H_ + h) * T_ + t) * D_ + 2 * i;
    V[ov]     = row[2 * C_ + base];
    V[ov + 1] = row[2 * C_ + base + 1];
}

// ---------------- causal flash attention, fp32, BQ=BKV=64, 256 threads ----------------
#define SSTR 68
#define ATTN_SMEM (4 * 64 * SSTR * 4)

__global__ void __launch_bounds__(256, 2) attn_kernel(const float* __restrict__ Qg,
                                                      const float* __restrict__ Kg,
                                                      const float* __restrict__ Vg,
                                                      float* __restrict__ Og)
{
    extern __shared__ float sm[];
    float* sQT = sm;
    float* sKT = sQT + 64 * SSTR;
    float* sV  = sKT + 64 * SSTR;
    float* sP  = sV  + 64 * SSTR;

    const int bh = blockIdx.y;
    const int qx = 31 - (int)blockIdx.x;
    const int q0 = qx * 64;
    const float* Qb = Qg + (size_t)bh * D_ * T_;
    const float* Kb = Kg + (size_t)bh * D_ * T_;
    const float* Vb = Vg + (size_t)bh * T_ * D_;

    const int tid = threadIdx.x;
    const int tr = tid >> 4;
    const int tc = tid & 15;

    const float QSC = 0.125f * 1.4426950408889634f;
#pragma unroll
    for (int it = 0; it < 4; it++) {
        int idx = it * 1024 + tid * 4;
        int d = idx >> 6, c = idx & 63;
        float4 v = *(const float4*)(Qb + (size_t)d * T_ + q0 + c);
        v.x *= QSC; v.y *= QSC; v.z *= QSC; v.w *= QSC;
        *(float4*)&sQT[d * SSTR + c] = v;
    }

    float O[4][4];
#pragma unroll
    for (int i = 0; i < 4; i++)
#pragma unroll
        for (int j = 0; j < 4; j++) O[i][j] = 0.f;
    float m[4] = {-1e30f, -1e30f, -1e30f, -1e30f};
    float l[4] = {0.f, 0.f, 0.f, 0.f};

    for (int kt = 0; kt <= qx; kt++) {
        const int k0 = kt * 64;
        __syncthreads();
#pragma unroll
        for (int it = 0; it < 4; it++) {
            int idx = it * 1024 + tid * 4;
            int r = idx >> 6, c = idx & 63;
            *(float4*)&sKT[r * SSTR + c] = *(const float4*)(Kb + (size_t)r * T_ + k0 + c);
            *(float4*)&sV[r * SSTR + c]  = *(const float4*)(Vb + (size_t)(k0 + r) * D_ + c);
        }
        __syncthreads();

        float S[4][4];
#pragma unroll
        for (int i = 0; i < 4; i++)
#pragma unroll
            for (int j = 0; j < 4; j++) S[i][j] = 0.f;

#pragma unroll 8
        for (int d = 0; d < 64; d++) {
            float4 ra = *(const float4*)&sQT[d * SSTR + tr * 4];
            float4 rb = *(const float4*)&sKT[d * SSTR + tc * 4];
            S[0][0] = fmaf(ra.x, rb.x, S[0][0]);
            S[0][1] = fmaf(ra.x, rb.y, S[0][1]);
            S[0][2] = fmaf(ra.x, rb.z, S[0][2]);
            S[0][3] = fmaf(ra.x, rb.w, S[0][3]);
            S[1][0] = fmaf(ra.y, rb.x, S[1][0]);
            S[1][1] = fmaf(ra.y, rb.y, S[1][1]);
            S[1][2] = fmaf(ra.y, rb.z, S[1][2]);
            S[1][3] = fmaf(ra.y, rb.w, S[1][3]);
            S[2][0] = fmaf(ra.z, rb.x, S[2][0]);
            S[2][1] = fmaf(ra.z, rb.y, S[2][1]);
            S[2][2] = fmaf(ra.z, rb.z, S[2][2]);
            S[2][3] = fmaf(ra.z, rb.w, S[2][3]);
            S[3][0] = fmaf(ra.w, rb.x, S[3][0]);
            S[3][1] = fmaf(ra.w, rb.y, S[3][1]);
            S[3][2] = fmaf(ra.w, rb.z, S[3][2]);
            S[3][3] = fmaf(ra.w, rb.w, S[3][3]);
        }

        if (kt == qx) {
#pragma unroll
            for (int i = 0; i < 4; i++)
#pragma unroll
                for (int j = 0; j < 4; j++)
                    if (tc * 4 + j > tr * 4 + i) S[i][j] = -1e30f;
        }

#pragma unroll
        for (int i = 0; i < 4; i++) {
            float mx = fmaxf(fmaxf(S[i][0], S[i][1]), fmaxf(S[i][2], S[i][3]));
            mx = fmaxf(mx, __shfl_xor_sync(0xffffffffu, mx, 1));
            mx = fmaxf(mx, __shfl_xor_sync(0xffffffffu, mx, 2));
            mx = fmaxf(mx, __shfl_xor_sync(0xffffffffu, mx, 4));
            mx = fmaxf(mx, __shfl_xor_sync(0xffffffffu, mx, 8));
            float mn = fmaxf(m[i], mx);
            float cf = fast_exp2(m[i] - mn);
            m[i] = mn;
            float p0 = fast_exp2(S[i][0] - mn);
            float p1 = fast_exp2(S[i][1] - mn);
            float p2 = fast_exp2(S[i][2] - mn);
            float p3 = fast_exp2(S[i][3] - mn);
            float rs = (p0 + p1) + (p2 + p3);
            rs += __shfl_xor_sync(0xffffffffu, rs, 1);
            rs += __shfl_xor_sync(0xffffffffu, rs, 2);
            rs += __shfl_xor_sync(0xffffffffu, rs, 4);
            rs += __shfl_xor_sync(0xffffffffu, rs, 8);
            l[i] = l[i] * cf + rs;
            O[i][0] *= cf; O[i][1] *= cf; O[i][2] *= cf; O[i][3] *= cf;
            float4 pv; pv.x = p0; pv.y = p1; pv.z = p2; pv.w = p3;
            *(float4*)&sP[(tr * 4 + i) * SSTR + tc * 4] = pv;
        }
        __syncthreads();

#pragma unroll 4
        for (int k4 = 0; k4 < 16; k4++) {
            float pa0[4], pa1[4], pa2[4], pa3[4];
            *(float4*)pa0 = *(const float4*)&sP[(tr * 4 + 0) * SSTR + k4 * 4];
            *(float4*)pa1 = *(const float4*)&sP[(tr * 4 + 1) * SSTR + k4 * 4];
            *(float4*)pa2 = *(const float4*)&sP[(tr * 4 + 2) * SSTR + k4 * 4];
            *(float4*)pa3 = *(const float4*)&sP[(tr * 4 + 3) * SSTR + k4 * 4];
#pragma unroll
            for (int kk = 0; kk < 4; kk++) {
                float4 vb = *(const float4*)&sV[(k4 * 4 + kk) * SSTR + tc * 4];
                O[0][0] = fmaf(pa0[kk], vb.x, O[0][0]);
                O[0][1] = fmaf(pa0[kk], vb.y, O[0][1]);
                O[0][2] = fmaf(pa0[kk], vb.z, O[0][2]);
                O[0][3] = fmaf(pa0[kk], vb.w, O[0][3]);
                O[1][0] = fmaf(pa1[kk], vb.x, O[1][0]);
                O[1][1] = fmaf(pa1[kk], vb.y, O[1][1]);
                O[1][2] = fmaf(pa1[kk], vb.z, O[1][2]);
                O[1][3] = fmaf(pa1[kk], vb.w, O[1][3]);
                O[2][0] = fmaf(pa2[kk], vb.x, O[2][0]);
                O[2][1] = fmaf(pa2[kk], vb.y, O[2][1]);
                O[2][2] = fmaf(pa2[kk], vb.z, O[2][2]);
                O[2][3] = fmaf(pa2[kk], vb.w, O[2][3]);
                O[3][0] = fmaf(pa3[kk], vb.x, O[3][0]);
                O[3][1] = fmaf(pa3[kk], vb.y, O[3][1]);
                O[3][2] = fmaf(pa3[kk], vb.z, O[3][2]);
                O[3][3] = fmaf(pa3[kk], vb.w, O[3][3]);
            }
        }
    }

    int b = bh >> 4, h = bh & 15;
#pragma unroll
    for (int i = 0; i < 4; i++) {
        int row = q0 + tr * 4 + i;
        float inv = 1.f / l[i];
        float4 o;
        o.x = O[i][0] * inv; o.y = O[i][1] * inv;
        o.z = O[i][2] * inv; o.w = O[i][3] * inv;
        *(float4*)(Og + (size_t)(b * T_ + row) * C_ + h * 64 + tc * 4) = o;
    }
}

// ---------------- launcher ----------------
extern "C" void kernel_launch(void* const* d_in, const int* in_sizes, int n_in,
                              void* d_out, int out_size)
{
    (void)in_sizes; (void)n_in; (void)out_size;
    const float* x      = (const float*)d_in[0];
    const float* w_attn = (const float*)d_in[2];
    const float* b_attn = (const float*)d_in[3];
    const float* w_proj = (const float*)d_in[4];
    const float* b_proj = (const float*)d_in[5];
    float* out = (float*)d_out;

    float *qkv, *q, *k, *v, *att, *xsq, *osq, *wsq1, *wsq2;
    __nv_bfloat16 *xh, *xl, *ah, *al, *w1h, *w1l, *w2h, *w2l;
    cudaGetSymbolAddress((void**)&qkv,  g_qkv);
    cudaGetSymbolAddress((void**)&q,    g_q);
    cudaGetSymbolAddress((void**)&k,    g_k);
    cudaGetSymbolAddress((void**)&v,    g_v);
    cudaGetSymbolAddress((void**)&att,  g_att);
    cudaGetSymbolAddress((void**)&xsq,  g_xsq);
    cudaGetSymbolAddress((void**)&osq,  g_osq);
    cudaGetSymbolAddress((void**)&wsq1, g_wsq1);
    cudaGetSymbolAddress((void**)&wsq2, g_wsq2);
    cudaGetSymbolAddress((void**)&xh,   g_xh);
    cudaGetSymbolAddress((void**)&xl,   g_xl);
    cudaGetSymbolAddress((void**)&ah,   g_ah);
    cudaGetSymbolAddress((void**)&al,   g_al);
    cudaGetSymbolAddress((void**)&w1h,  g_w1h);
    cudaGetSymbolAddress((void**)&w1l,  g_w1l);
    cudaGetSymbolAddress((void**)&w2h,  g_w2h);
    cudaGetSymbolAddress((void**)&w2l,  g_w2l);

    const float scale1 = (float)(sqrt(3072.0) / log1p(3072.0));
    const float scale2 = (float)(sqrt(1024.0) / log1p(1024.0));

    cudaFuncSetAttribute(yat_mma_gemm_kernel,
                         cudaFuncAttributeMaxDynamicSharedMemorySize, MMA_SMEM);
    cudaFuncSetAttribute(attn_kernel,
                         cudaFuncAttributeMaxDynamicSharedMemorySize, ATTN_SMEM);

    rowsq_kernel<<<M_, 256>>>(x, xsq);
    colsq_kernel<<<N1_ / 64, 256>>>(w_attn, wsq1, C_, N1_);
    colsq_kernel<<<C_ / 64, 256>>>(w_proj, wsq2, C_, C_);

    xconv_kernel<<<(int)(((size_t)M_ * C_) / 1024), 256>>>(x, xh, xl);
    wconv_kernel<<<dim3(N1_ / 32, C_ / 32), 256>>>(w_attn, w1h, w1l, C_, N1_);
    wconv_kernel<<<dim3(C_ / 32, C_ / 32), 256>>>(w_proj, w2h, w2l, C_, C_);

    yat_mma_gemm_kernel<<<dim3(N1_ / 128, M_ / 128), 256, MMA_SMEM>>>(
        xh, xl, w1h, w1l, xsq, wsq1, b_attn, qkv, M_, N1_, C_, scale1);

    rope_split_kernel<<<dim3(T_, B_), 512>>>(qkv, q, k, v);

    attn_kernel<<<dim3(T_ / 64, B_ * H_), 256, ATTN_SMEM>>>(q, k, v, att);

    rowsq_kernel<<<M_, 256>>>(att, osq);
    xconv_kernel<<<(int)(((size_t)M_ * C_) / 1024), 256>>>(att, ah, al);

    yat_mma_gemm_kernel<<<dim3(C_ / 128, M_ / 128), 256, MMA_SMEM>>>(
        ah, al, w2h, w2l, osq, wsq2, b_proj, out, M_, C_, C_, scale2);
}

// round 5
// speedup vs baseline: 12.3881x; 1.4842x over previous
#include <cuda_runtime.h>
#include <cuda_bf16.h>
#include <math.h>
#include <stdint.h>

#define B_   2
#define T_   2048
#define C_   1024
#define H_   16
#define D_   64
#define M_   4096          // B_*T_
#define N1_  3072          // 3*C_
#define EPS_ 1e-6f

// ---------------- scratch (device globals; no allocation allowed) ----------------
__device__ float g_qkv[(size_t)M_ * N1_];          // 48 MB
__device__ float g_att[(size_t)M_ * C_];
__device__ float g_xsq[M_];
__device__ float g_osq[M_];
__device__ float g_wsq1[N1_];
__device__ float g_wsq2[C_];
// bf16 hi/lo operands for yat GEMMs
__device__ __nv_bfloat16 g_xh[(size_t)M_ * C_];
__device__ __nv_bfloat16 g_xl[(size_t)M_ * C_];
__device__ __nv_bfloat16 g_ah[(size_t)M_ * C_];
__device__ __nv_bfloat16 g_al[(size_t)M_ * C_];
__device__ __nv_bfloat16 g_w1h[(size_t)N1_ * C_];  // [N,K] transposed
__device__ __nv_bfloat16 g_w1l[(size_t)N1_ * C_];
__device__ __nv_bfloat16 g_w2h[(size_t)C_ * C_];
__device__ __nv_bfloat16 g_w2l[(size_t)C_ * C_];
// bf16 hi/lo attention operands
__device__ __nv_bfloat16 g_qbh[(size_t)B_ * H_ * T_ * D_];  // [B,H,T,D] (scaled)
__device__ __nv_bfloat16 g_qbl[(size_t)B_ * H_ * T_ * D_];
__device__ __nv_bfloat16 g_kbh[(size_t)B_ * H_ * T_ * D_];  // [B,H,T,D]
__device__ __nv_bfloat16 g_kbl[(size_t)B_ * H_ * T_ * D_];
__device__ __nv_bfloat16 g_vth[(size_t)B_ * H_ * D_ * T_];  // [B,H,D,T]
__device__ __nv_bfloat16 g_vtl[(size_t)B_ * H_ * D_ * T_];

__device__ __forceinline__ float fast_exp2(float x) {
    float r;
    asm("ex2.approx.ftz.f32 %0, %1;" : "=f"(r) : "f"(x));
    return r;
}

__device__ __forceinline__ uint32_t smem_u32(const void* p) {
    return (uint32_t)__cvta_generic_to_shared(p);
}

__device__ __forceinline__ uint32_t pack_bf16(float lo, float hi) {
    uint32_t r;
    asm("cvt.rn.bf16x2.f32 %0, %1, %2;" : "=r"(r) : "f"(hi), "f"(lo));
    return r;
}

// ======================= small helper kernels =======================

__global__ void rowsq_kernel(const float* __restrict__ X, float* __restrict__ out)
{
    int m = blockIdx.x;
    const float* x = X + (size_t)m * C_;
    int tid = threadIdx.x;
    float4 v = *(const float4*)(x + tid * 4);
    float s = v.x * v.x + v.y * v.y + v.z * v.z + v.w * v.w;
#pragma unroll
    for (int o = 16; o; o >>= 1) s += __shfl_xor_sync(0xffffffffu, s, o);
    __shared__ float red[8];
    if ((tid & 31) == 0) red[tid >> 5] = s;
    __syncthreads();
    if (tid == 0) {
        float t = 0.f;
#pragma unroll
        for (int i = 0; i < 8; i++) t += red[i];
        out[m] = t;
    }
}

__global__ void colsq_kernel(const float* __restrict__ W, float* __restrict__ out,
                             int K, int N)
{
    __shared__ float red[4][64];
    int tx = threadIdx.x & 63, ty = threadIdx.x >> 6;
    int n = blockIdx.x * 64 + tx;
    float s = 0.f;
    for (int k = ty; k < K; k += 4) {
        float w = W[(size_t)k * N + n];
        s = fmaf(w, w, s);
    }
    red[ty][tx] = s;
    __syncthreads();
    if (ty == 0) out[n] = red[0][tx] + red[1][tx] + red[2][tx] + red[3][tx];
}

// elementwise fp32 -> bf16 hi/lo split
__global__ void xconv_kernel(const float* __restrict__ X,
                             __nv_bfloat16* __restrict__ Xh,
                             __nv_bfloat16* __restrict__ Xl)
{
    size_t i = ((size_t)blockIdx.x * 256 + threadIdx.x) * 4;
    float4 v = *(const float4*)(X + i);
    __nv_bfloat16 h0 = __float2bfloat16(v.x);
    __nv_bfloat16 h1 = __float2bfloat16(v.y);
    __nv_bfloat16 h2 = __float2bfloat16(v.z);
    __nv_bfloat16 h3 = __float2bfloat16(v.w);
    __nv_bfloat162 a, b;
    a.x = h0; a.y = h1; b.x = h2; b.y = h3;
    *(__nv_bfloat162*)(Xh + i)     = a;
    *(__nv_bfloat162*)(Xh + i + 2) = b;
    __nv_bfloat162 c, d;
    c.x = __float2bfloat16(v.x - __bfloat162float(h0));
    c.y = __float2bfloat16(v.y - __bfloat162float(h1));
    d.x = __float2bfloat16(v.z - __bfloat162float(h2));
    d.y = __float2bfloat16(v.w - __bfloat162float(h3));
    *(__nv_bfloat162*)(Xl + i)     = c;
    *(__nv_bfloat162*)(Xl + i + 2) = d;
}

// W[K][N] fp32 -> WT[N][K] bf16 hi/lo (32x32 smem transpose)
__global__ void wconv_kernel(const float* __restrict__ W,
                             __nv_bfloat16* __restrict__ WhT,
                             __nv_bfloat16* __restrict__ WlT,
                             int K, int N)
{
    __shared__ float tile[32][33];
    int bx = blockIdx.x, by = blockIdx.y;
    int tx = threadIdx.x & 31, ty = threadIdx.x >> 5;
#pragma unroll
    for (int i = ty; i < 32; i += 8)
        tile[i][tx] = W[(size_t)(by * 32 + i) * N + bx * 32 + tx];
    __syncthreads();
#pragma unroll
    for (int i = ty; i < 32; i += 8) {
        int n = bx * 32 + i, k = by * 32 + tx;
        float v = tile[tx][i];
        __nv_bfloat16 h = __float2bfloat16(v);
        WhT[(size_t)n * K + k] = h;
        WlT[(size_t)n * K + k] = __float2bfloat16(v - __bfloat162float(h));
    }
}

// ======================= mma.sync helpers =======================

#define LDSM4(r0, r1, r2, r3, addr) \
    asm volatile("ldmatrix.sync.aligned.m8n8.x4.shared.b16 {%0,%1,%2,%3}, [%4];" \
                 : "=r"(r0), "=r"(r1), "=r"(r2), "=r"(r3) : "r"(addr))

#define MMA16816(d, a, b) \
    asm volatile("mma.sync.aligned.m16n8k16.row.col.f32.bf16.bf16.f32 " \
                 "{%0,%1,%2,%3}, {%4,%5,%6,%7}, {%8,%9}, {%0,%1,%2,%3};" \
                 : "+f"((d)[0]), "+f"((d)[1]), "+f"((d)[2]), "+f"((d)[3]) \
                 : "r"((a)[0]), "r"((a)[1]), "r"((a)[2]), "r"((a)[3]), \
                   "r"((b)[0]), "r"((b)[1]))

__device__ __forceinline__ void cp16(uint32_t dst, const void* src) {
    asm volatile("cp.async.cg.shared.global [%0], [%1], 16;" :: "r"(dst), "l"(src));
}

// ======================= yat mma.sync GEMM (bf16x3 fp32-emulation) =======================
#define ROWB   80
#define TILEB  (128 * ROWB)
#define OFF_AH 0
#define OFF_AL (1 * TILEB)
#define OFF_BH (2 * TILEB)
#define OFF_BL (3 * TILEB)
#define STAGEB (4 * TILEB)
#define MMA_SMEM (2 * STAGEB)

__device__ __forceinline__ void load_stage(
    uint32_t st, const __nv_bfloat16* Agh, const __nv_bfloat16* Agl,
    const __nv_bfloat16* Bgh, const __nv_bfloat16* Bgl,
    int k0, int K, int tid)
{
#pragma unroll
    for (int it = 0; it < 2; it++) {
        int idx = it * 256 + tid;
        int row = idx >> 2;
        int ch = (idx & 3) * 16;
        uint32_t dst = (uint32_t)row * ROWB + ch;
        size_t srcel = (size_t)row * K + k0;
        cp16(st + OFF_AH + dst, (const char*)(Agh + srcel) + ch);
        cp16(st + OFF_AL + dst, (const char*)(Agl + srcel) + ch);
        cp16(st + OFF_BH + dst, (const char*)(Bgh + srcel) + ch);
        cp16(st + OFF_BL + dst, (const char*)(Bgl + srcel) + ch);
    }
}

__global__ void __launch_bounds__(256, 2) yat_mma_gemm_kernel(
    const __nv_bfloat16* __restrict__ Ah, const __nv_bfloat16* __restrict__ Al,
    const __nv_bfloat16* __restrict__ BhT, const __nv_bfloat16* __restrict__ BlT,
    const float* __restrict__ asq, const float* __restrict__ bsq,
    const float* __restrict__ bias, float* __restrict__ Cout,
    int M, int N, int K, float scale)
{
    extern __shared__ char smem[];
    const uint32_t sb = smem_u32(smem);

    const int tid = threadIdx.x;
    const int wid = tid >> 5, lane = tid & 31;
    const int warpM = wid >> 2;
    const int warpN = wid & 3;
    const int rowBase = blockIdx.y * 128;
    const int colBase = blockIdx.x * 128;
    const int NC = K >> 5;

    const __nv_bfloat16* Agh = Ah + (size_t)rowBase * K;
    const __nv_bfloat16* Agl = Al + (size_t)rowBase * K;
    const __nv_bfloat16* Bgh = BhT + (size_t)colBase * K;
    const __nv_bfloat16* Bgl = BlT + (size_t)colBase * K;

    const uint32_t aSel = (uint32_t)(lane & 15) * ROWB + (uint32_t)(lane >> 4) * 16;
    const uint32_t bSel = (uint32_t)(((lane >> 4) & 1) * 8 + (lane & 7)) * ROWB +
                          (uint32_t)((lane >> 3) & 1) * 16;

    float acc[4][4][4];
#pragma unroll
    for (int i = 0; i < 4; i++)
#pragma unroll
        for (int j = 0; j < 4; j++)
#pragma unroll
            for (int e = 0; e < 4; e++) acc[i][j][e] = 0.f;

    load_stage(sb, Agh, Agl, Bgh, Bgl, 0, K, tid);
    asm volatile("cp.async.commit_group;" ::: "memory");

    for (int c = 0; c < NC; c++) {
        if (c + 1 < NC) {
            load_stage(sb + (uint32_t)((c + 1) & 1) * STAGEB,
                       Agh, Agl, Bgh, Bgl, (c + 1) << 5, K, tid);
            asm volatile("cp.async.commit_group;" ::: "memory");
            asm volatile("cp.async.wait_group 1;" ::: "memory");
        } else {
            asm volatile("cp.async.wait_group 0;" ::: "memory");
        }
        __syncthreads();

        const uint32_t st = sb + (uint32_t)(c & 1) * STAGEB;
#pragma unroll
        for (int p = 0; p < 3; p++) {
            const uint32_t aBase = st + (p < 2 ? OFF_AH : OFF_AL) +
                                   (uint32_t)warpM * 64 * ROWB + aSel;
            const uint32_t bBase = st + (p == 1 ? OFF_BL : OFF_BH) +
                                   (uint32_t)warpN * 32 * ROWB + bSel;
#pragma unroll
            for (int ks = 0; ks < 2; ks++) {
                uint32_t a[4][4];
#pragma unroll
                for (int mt = 0; mt < 4; mt++)
                    LDSM4(a[mt][0], a[mt][1], a[mt][2], a[mt][3],
                          aBase + mt * (16 * ROWB) + ks * 32);
                uint32_t b[4][2];
#pragma unroll
                for (int nt2 = 0; nt2 < 2; nt2++) {
                    uint32_t r0, r1, r2, r3;
                    LDSM4(r0, r1, r2, r3, bBase + nt2 * (16 * ROWB) + ks * 32);
                    b[nt2 * 2 + 0][0] = r0; b[nt2 * 2 + 0][1] = r1;
                    b[nt2 * 2 + 1][0] = r2; b[nt2 * 2 + 1][1] = r3;
                }
#pragma unroll
                for (int mt = 0; mt < 4; mt++)
#pragma unroll
                    for (int nt = 0; nt < 4; nt++)
                        MMA16816(acc[mt][nt], a[mt], b[nt]);
            }
        }
        __syncthreads();
    }

    const int lr = lane >> 2, lc = (lane & 3) * 2;
    const int mW = rowBase + warpM * 64;
    const int nW = colBase + warpN * 32;
#pragma unroll
    for (int mt = 0; mt < 4; mt++) {
        const int r0g = mW + mt * 16 + lr;
        const int r1g = r0g + 8;
        const float av0 = asq[r0g];
        const float av1 = asq[r1g];
#pragma unroll
        for (int nt = 0; nt < 4; nt++) {
            const int cg = nW + nt * 8 + lc;
            const float bq0 = bsq[cg], bq1 = bsq[cg + 1];
            const float bi0 = bias[cg], bi1 = bias[cg + 1];
            float d00 = acc[mt][nt][0], d01 = acc[mt][nt][1];
            float d10 = acc[mt][nt][2], d11 = acc[mt][nt][3];
            float2 o0, o1;
            o0.x = __fdividef(d00 * d00, av0 + bq0 - 2.f * d00 + EPS_) * scale + bi0;
            o0.y = __fdividef(d01 * d01, av0 + bq1 - 2.f * d01 + EPS_) * scale + bi1;
            o1.x = __fdividef(d10 * d10, av1 + bq0 - 2.f * d10 + EPS_) * scale + bi0;
            o1.y = __fdividef(d11 * d11, av1 + bq1 - 2.f * d11 + EPS_) * scale + bi1;
            *(float2*)(Cout + (size_t)r0g * N + cg) = o0;
            *(float2*)(Cout + (size_t)r1g * N + cg) = o1;
        }
    }
}

// ---------------- RoPE + split -> bf16 hi/lo Q/K [B,H,T,D], V^T [B,H,D,T] ----------------
__global__ void rope_split_kernel(const float* __restrict__ qkv,
                                  __nv_bfloat16* __restrict__ Qh, __nv_bfloat16* __restrict__ Ql,
                                  __nv_bfloat16* __restrict__ Kh, __nv_bfloat16* __restrict__ Kl,
                                  __nv_bfloat16* __restrict__ VTh, __nv_bfloat16* __restrict__ VTl)
{
    int t = blockIdx.x, b = blockIdx.y;
    int tid = threadIdx.x;            // 512 = 16 heads * 32 pairs
    int h = tid >> 5, i = tid & 31;
    const float* row = qkv + (size_t)(b * T_ + t) * N1_;
    float fr = powf(10000.0f, -(float)i / 32.0f);
    float ang = (float)t * fr;
    float s, c;
    sincosf(ang, &s, &c);
    int base = h * 64 + 2 * i;
    const float QSC = 0.125f * 1.4426950408889634f;   // 1/sqrt(D) * log2(e)

    // Q (scaled), K: [B,H,T,D] hi/lo
    size_t o = ((size_t)(b * H_ + h) * T_ + t) * D_ + 2 * i;
    float q0 = row[base], q1 = row[base + 1];
    float qr0 = (q0 * c - q1 * s) * QSC;
    float qr1 = (q1 * c + q0 * s) * QSC;
    __nv_bfloat162 qh2, ql2;
    qh2.x = __float2bfloat16(qr0); qh2.y = __float2bfloat16(qr1);
    ql2.x = __float2bfloat16(qr0 - __bfloat162float(qh2.x));
    ql2.y = __float2bfloat16(qr1 - __bfloat162float(qh2.y));
    *(__nv_bfloat162*)(Qh + o) = qh2;
    *(__nv_bfloat162*)(Ql + o) = ql2;

    float k0 = row[C_ + base], k1 = row[C_ + base + 1];
    float kr0 = k0 * c - k1 * s;
    float kr1 = k1 * c + k0 * s;
    __nv_bfloat162 kh2, kl2;
    kh2.x = __float2bfloat16(kr0); kh2.y = __float2bfloat16(kr1);
    kl2.x = __float2bfloat16(kr0 - __bfloat162float(kh2.x));
    kl2.y = __float2bfloat16(kr1 - __bfloat162float(kh2.y));
    *(__nv_bfloat162*)(Kh + o) = kh2;
    *(__nv_bfloat162*)(Kl + o) = kl2;

    // V^T: [B,H,D,T]
    float v0 = row[2 * C_ + base], v1 = row[2 * C_ + base + 1];
    size_t ov = ((size_t)(b * H_ + h) * D_ + 2 * i) * T_ + t;
    __nv_bfloat16 vh0 = __float2bfloat16(v0);
    __nv_bfloat16 vh1 = __float2bfloat16(v1);
    VTh[ov]      = vh0;
    VTh[ov + T_] = vh1;
    VTl[ov]      = __float2bfloat16(v0 - __bfloat162float(vh0));
    VTl[ov + T_] = __float2bfloat16(v1 - __bfloat162float(vh1));
}

// ======================= tensor-core causal flash attention =======================
// BQ=128, BKV=64, 8 warps x 16 q-rows. bf16x3 emulation for S and PV.
#define AROWB 144
#define QTILE (128 * AROWB)            // 18432
#define KVTILE (64 * AROWB)            // 9216
#define SQH_OFF 0
#define SQL_OFF QTILE
#define STG_OFF (2 * QTILE)
#define STGSZ  (4 * KVTILE)            // 36864
#define ST_KH 0
#define ST_KL (1 * KVTILE)
#define ST_VH (2 * KVTILE)
#define ST_VL (3 * KVTILE)
#define ATTN_SMEM (2 * QTILE + 2 * STGSZ)   // 110592

__device__ __forceinline__ void attn_load_stage(
    uint32_t st, const __nv_bfloat16* kh, const __nv_bfloat16* kl,
    const __nv_bfloat16* vth, const __nv_bfloat16* vtl,
    size_t bhT, size_t bhD, int k0, int tid)
{
#pragma unroll
    for (int it = 0; it < 2; it++) {
        int idx = it * 256 + tid;          // 0..511
        int row = idx >> 3;                // 0..63
        int ch = (idx & 7) * 16;           // byte chunk in 128B row
        uint32_t dst = (uint32_t)row * AROWB + ch;
        const char* ksrc = (const char*)(kh + (bhT + k0 + row) * D_) + ch;
        const char* klsrc = (const char*)(kl + (bhT + k0 + row) * D_) + ch;
        const char* vsrc = (const char*)(vth + (bhD + row) * T_ + k0) + ch;
        const char* vlsrc = (const char*)(vtl + (bhD + row) * T_ + k0) + ch;
        cp16(st + ST_KH + dst, ksrc);
        cp16(st + ST_KL + dst, klsrc);
        cp16(st + ST_VH + dst, vsrc);
        cp16(st + ST_VL + dst, vlsrc);
    }
}

__global__ void __launch_bounds__(256, 2) attn_mma_kernel(
    const __nv_bfloat16* __restrict__ qh, const __nv_bfloat16* __restrict__ ql,
    const __nv_bfloat16* __restrict__ kh, const __nv_bfloat16* __restrict__ kl,
    const __nv_bfloat16* __restrict__ vth, const __nv_bfloat16* __restrict__ vtl,
    float* __restrict__ Og)
{
    extern __shared__ char smem[];
    const uint32_t sb = smem_u32(smem);

    const int bh = blockIdx.y;
    const int qx = 15 - (int)blockIdx.x;    // heavy tiles first
    const int q0 = qx * 128;
    const size_t bhT = (size_t)bh * T_;
    const size_t bhD = (size_t)bh * D_;

    const int tid = threadIdx.x;
    const int wid = tid >> 5, lane = tid & 31;
    const int lr = lane >> 2, c2 = (lane & 3) * 2;

    const uint32_t aSel = (uint32_t)(lane & 15) * AROWB + (uint32_t)(lane >> 4) * 16;
    const uint32_t bSel = (uint32_t)(((lane >> 4) & 1) * 8 + (lane & 7)) * AROWB +
                          (uint32_t)((lane >> 3) & 1) * 16;

    // ---- load Q tile (hi+lo) into smem ----
#pragma unroll
    for (int it = 0; it < 4; it++) {
        int idx = it * 256 + tid;          // 0..1023
        int row = idx >> 3;                // 0..127
        int ch = (idx & 7) * 16;
        uint32_t dst = (uint32_t)row * AROWB + ch;
        cp16(sb + SQH_OFF + dst, (const char*)(qh + (bhT + q0 + row) * D_) + ch);
        cp16(sb + SQL_OFF + dst, (const char*)(ql + (bhT + q0 + row) * D_) + ch);
    }
    asm volatile("cp.async.commit_group;" ::: "memory");

    // prologue: stage 0 of KV
    attn_load_stage(sb + STG_OFF, kh, kl, vth, vtl, bhT, bhD, 0, tid);
    asm volatile("cp.async.commit_group;" ::: "memory");

    // wait for Q, pull Qh fragments into registers
    asm volatile("cp.async.wait_group 1;" ::: "memory");
    __syncthreads();
    uint32_t qhf[4][4];
    {
        const uint32_t aQ = sb + SQH_OFF + (uint32_t)wid * 16 * AROWB + aSel;
#pragma unroll
        for (int ks = 0; ks < 4; ks++)
            LDSM4(qhf[ks][0], qhf[ks][1], qhf[ks][2], qhf[ks][3], aQ + ks * 32);
    }

    float O[8][4];
#pragma unroll
    for (int j = 0; j < 8; j++)
#pragma unroll
        for (int e = 0; e < 4; e++) O[j][e] = 0.f;
    float mrow[2] = {-1e30f, -1e30f};
    float lrow[2] = {0.f, 0.f};

    const int ntiles = 2 * qx + 2;
    const int rowg0 = q0 + wid * 16 + lr;

    for (int kt = 0; kt < ntiles; kt++) {
        const uint32_t st = sb + STG_OFF + (uint32_t)(kt & 1) * STGSZ;
        if (kt + 1 < ntiles) {
            attn_load_stage(sb + STG_OFF + (uint32_t)((kt + 1) & 1) * STGSZ,
                            kh, kl, vth, vtl, bhT, bhD, (kt + 1) * 64, tid);
            asm volatile("cp.async.commit_group;" ::: "memory");
            asm volatile("cp.async.wait_group 1;" ::: "memory");
        } else {
            asm volatile("cp.async.wait_group 0;" ::: "memory");
        }
        __syncthreads();

        // ---- S = Q K^T, 3 passes accumulated ----
        float S[8][4];
#pragma unroll
        for (int j = 0; j < 8; j++)
#pragma unroll
            for (int e = 0; e < 4; e++) S[j][e] = 0.f;

        const uint32_t aQl = sb + SQL_OFF + (uint32_t)wid * 16 * AROWB + aSel;
#pragma unroll
        for (int ks = 0; ks < 4; ks++) {
            uint32_t al[4];
            LDSM4(al[0], al[1], al[2], al[3], aQl + ks * 32);
#pragma unroll
            for (int np = 0; np < 4; np++) {
                uint32_t r0, r1, r2, r3;
                // Kh: used by Qh and Ql passes
                LDSM4(r0, r1, r2, r3, st + ST_KH + np * (16 * AROWB) + bSel + ks * 32);
                uint32_t bh0[2] = {r0, r1}, bh1[2] = {r2, r3};
                MMA16816(S[np * 2 + 0], qhf[ks], bh0);
                MMA16816(S[np * 2 + 1], qhf[ks], bh1);
                MMA16816(S[np * 2 + 0], al, bh0);
                MMA16816(S[np * 2 + 1], al, bh1);
                // Kl: used by Qh pass
                LDSM4(r0, r1, r2, r3, st + ST_KL + np * (16 * AROWB) + bSel + ks * 32);
                uint32_t bl0[2] = {r0, r1}, bl1[2] = {r2, r3};
                MMA16816(S[np * 2 + 0], qhf[ks], bl0);
                MMA16816(S[np * 2 + 1], qhf[ks], bl1);
            }
        }

        // ---- causal mask (last two kv tiles only) ----
        const int k0 = kt * 64;
        if (kt >= 2 * qx) {
#pragma unroll
            for (int j = 0; j < 8; j++) {
                int col = k0 + j * 8 + c2;
                if (col > rowg0)     S[j][0] = -1e30f;
                if (col + 1 > rowg0) S[j][1] = -1e30f;
                if (col > rowg0 + 8)     S[j][2] = -1e30f;
                if (col + 1 > rowg0 + 8) S[j][3] = -1e30f;
            }
        }

        // ---- online softmax (log2 domain) ----
#pragma unroll
        for (int i = 0; i < 2; i++) {
            float mx = -1e30f;
#pragma unroll
            for (int j = 0; j < 8; j++)
                mx = fmaxf(mx, fmaxf(S[j][2 * i], S[j][2 * i + 1]));
            mx = fmaxf(mx, __shfl_xor_sync(0xffffffffu, mx, 1));
            mx = fmaxf(mx, __shfl_xor_sync(0xffffffffu, mx, 2));
            float mn = fmaxf(mrow[i], mx);
            float cf = fast_exp2(mrow[i] - mn);
            mrow[i] = mn;
            float rs = 0.f;
#pragma unroll
            for (int j = 0; j < 8; j++) {
                float p0 = fast_exp2(S[j][2 * i] - mn);
                float p1 = fast_exp2(S[j][2 * i + 1] - mn);
                S[j][2 * i] = p0; S[j][2 * i + 1] = p1;
                rs += p0 + p1;
            }
            rs += __shfl_xor_sync(0xffffffffu, rs, 1);
            rs += __shfl_xor_sync(0xffffffffu, rs, 2);
            lrow[i] = lrow[i] * cf + rs;
#pragma unroll
            for (int j = 0; j < 8; j++) { O[j][2 * i] *= cf; O[j][2 * i + 1] *= cf; }
        }

        // ---- pack P hi/lo into A fragments ----
        uint32_t PH[4][4], PL[4][4];
#pragma unroll
        for (int t = 0; t < 4; t++) {
#pragma unroll
            for (int h2 = 0; h2 < 2; h2++) {
                int j = 2 * t + h2;
                float p0 = S[j][0], p1 = S[j][1], p2 = S[j][2], p3 = S[j][3];
                float h0 = __bfloat162float(__float2bfloat16(p0));
                float h1 = __bfloat162float(__float2bfloat16(p1));
                float h2f = __bfloat162float(__float2bfloat16(p2));
                float h3 = __bfloat162float(__float2bfloat16(p3));
                PH[t][h2 * 2 + 0] = pack_bf16(p0, p1);
                PH[t][h2 * 2 + 1] = pack_bf16(p2, p3);
                PL[t][h2 * 2 + 0] = pack_bf16(p0 - h0, p1 - h1);
                PL[t][h2 * 2 + 1] = pack_bf16(p2 - h2f, p3 - h3);
            }
        }
        // reorder: A frag = {tile2t(c0c1), tile2t(c2c3), tile2t+1(c0c1), tile2t+1(c2c3)}
        // PH[t] currently = {t0c01, t0c23, t1c01, t1c23} -> matches {a0,a1,a2,a3} ✓

        // ---- O += P V : 3 passes ----
#pragma unroll
        for (int t = 0; t < 4; t++) {
#pragma unroll
            for (int dn = 0; dn < 4; dn++) {
                uint32_t r0, r1, r2, r3;
                LDSM4(r0, r1, r2, r3, st + ST_VH + dn * (16 * AROWB) + bSel + t * 32);
                uint32_t vh0[2] = {r0, r1}, vh1[2] = {r2, r3};
                MMA16816(O[dn * 2 + 0], PH[t], vh0);
                MMA16816(O[dn * 2 + 1], PH[t], vh1);
                MMA16816(O[dn * 2 + 0], PL[t], vh0);
                MMA16816(O[dn * 2 + 1], PL[t], vh1);
                LDSM4(r0, r1, r2, r3, st + ST_VL + dn * (16 * AROWB) + bSel + t * 32);
                uint32_t vl0[2] = {r0, r1}, vl1[2] = {r2, r3};
                MMA16816(O[dn * 2 + 0], PH[t], vl0);
                MMA16816(O[dn * 2 + 1], PH[t], vl1);
            }
        }
        __syncthreads();
    }

    // ---- epilogue: normalize, write att[B,T,C] ----
    const int b = bh >> 4, h = bh & 15;
    const float inv0 = 1.f / lrow[0], inv1 = 1.f / lrow[1];
    float* o0 = Og + (size_t)(b * T_ + rowg0) * C_ + h * 64;
    float* o1 = Og + (size_t)(b * T_ + rowg0 + 8) * C_ + h * 64;
#pragma unroll
    for (int j = 0; j < 8; j++) {
        float2 a, c;
        a.x = O[j][0] * inv0; a.y = O[j][1] * inv0;
        c.x = O[j][2] * inv1; c.y = O[j][3] * inv1;
        *(float2*)(o0 + j * 8 + c2) = a;
        *(float2*)(o1 + j * 8 + c2) = c;
    }
}

// ---------------- launcher ----------------
extern "C" void kernel_launch(void* const* d_in, const int* in_sizes, int n_in,
                              void* d_out, int out_size)
{
    (void)in_sizes; (void)n_in; (void)out_size;
    const float* x      = (const float*)d_in[0];
    const float* w_attn = (const float*)d_in[2];
    const float* b_attn = (const float*)d_in[3];
    const float* w_proj = (const float*)d_in[4];
    const float* b_proj = (const float*)d_in[5];
    float* out = (float*)d_out;

    float *qkv, *att, *xsq, *osq, *wsq1, *wsq2;
    __nv_bfloat16 *xh, *xl, *ah, *al, *w1h, *w1l, *w2h, *w2l;
    __nv_bfloat16 *qbh, *qbl, *kbh, *kbl, *vth, *vtl;
    cudaGetSymbolAddress((void**)&qkv,  g_qkv);
    cudaGetSymbolAddress((void**)&att,  g_att);
    cudaGetSymbolAddress((void**)&xsq,  g_xsq);
    cudaGetSymbolAddress((void**)&osq,  g_osq);
    cudaGetSymbolAddress((void**)&wsq1, g_wsq1);
    cudaGetSymbolAddress((void**)&wsq2, g_wsq2);
    cudaGetSymbolAddress((void**)&xh,   g_xh);
    cudaGetSymbolAddress((void**)&xl,   g_xl);
    cudaGetSymbolAddress((void**)&ah,   g_ah);
    cudaGetSymbolAddress((void**)&al,   g_al);
    cudaGetSymbolAddress((void**)&w1h,  g_w1h);
    cudaGetSymbolAddress((void**)&w1l,  g_w1l);
    cudaGetSymbolAddress((void**)&w2h,  g_w2h);
    cudaGetSymbolAddress((void**)&w2l,  g_w2l);
    cudaGetSymbolAddress((void**)&qbh,  g_qbh);
    cudaGetSymbolAddress((void**)&qbl,  g_qbl);
    cudaGetSymbolAddress((void**)&kbh,  g_kbh);
    cudaGetSymbolAddress((void**)&kbl,  g_kbl);
    cudaGetSymbolAddress((void**)&vth,  g_vth);
    cudaGetSymbolAddress((void**)&vtl,  g_vtl);

    const float scale1 = (float)(sqrt(3072.0) / log1p(3072.0));
    const float scale2 = (float)(sqrt(1024.0) / log1p(1024.0));

    cudaFuncSetAttribute(yat_mma_gemm_kernel,
                         cudaFuncAttributeMaxDynamicSharedMemorySize, MMA_SMEM);
    cudaFuncSetAttribute(attn_mma_kernel,
                         cudaFuncAttributeMaxDynamicSharedMemorySize, ATTN_SMEM);

    rowsq_kernel<<<M_, 256>>>(x, xsq);
    colsq_kernel<<<N1_ / 64, 256>>>(w_attn, wsq1, C_, N1_);
    colsq_kernel<<<C_ / 64, 256>>>(w_proj, wsq2, C_, C_);

    xconv_kernel<<<(int)(((size_t)M_ * C_) / 1024), 256>>>(x, xh, xl);
    wconv_kernel<<<dim3(N1_ / 32, C_ / 32), 256>>>(w_attn, w1h, w1l, C_, N1_);
    wconv_kernel<<<dim3(C_ / 32, C_ / 32), 256>>>(w_proj, w2h, w2l, C_, C_);

    yat_mma_gemm_kernel<<<dim3(N1_ / 128, M_ / 128), 256, MMA_SMEM>>>(
        xh, xl, w1h, w1l, xsq, wsq1, b_attn, qkv, M_, N1_, C_, scale1);

    rope_split_kernel<<<dim3(T_, B_), 512>>>(qkv, qbh, qbl, kbh, kbl, vth, vtl);

    attn_mma_kernel<<<dim3(T_ / 128, B_ * H_), 256, ATTN_SMEM>>>(
        qbh, qbl, kbh, kbl, vth, vtl, att);

    rowsq_kernel<<<M_, 256>>>(att, osq);
    xconv_kernel<<<(int)(((size_t)M_ * C_) / 1024), 256>>>(att, ah, al);

    yat_mma_gemm_kernel<<<dim3(C_ / 128, M_ / 128), 256, MMA_SMEM>>>(
        ah, al, w2h, w2l, osq, wsq2, b_proj, out, M_, C_, C_, scale2);
}

// round 6
// speedup vs baseline: 14.0525x; 1.1344x over previous
#include <cuda_runtime.h>
#include <cuda_bf16.h>
#include <math.h>
#include <stdint.h>

#define B_   2
#define T_   2048
#define C_   1024
#define H_   16
#define D_   64
#define M_   4096          // B_*T_
#define N1_  3072          // 3*C_
#define EPS_ 1e-6f

// ---------------- scratch (device globals; no allocation allowed) ----------------
__device__ float g_xsq[M_];
__device__ float g_osq[M_];
__device__ float g_wsq1[N1_];
__device__ float g_wsq2[C_];
// bf16 hi/lo operands for yat GEMMs
__device__ __nv_bfloat16 g_xh[(size_t)M_ * C_];
__device__ __nv_bfloat16 g_xl[(size_t)M_ * C_];
__device__ __nv_bfloat16 g_ah[(size_t)M_ * C_];
__device__ __nv_bfloat16 g_al[(size_t)M_ * C_];
__device__ __nv_bfloat16 g_w1h[(size_t)N1_ * C_];  // [N,K] transposed
__device__ __nv_bfloat16 g_w1l[(size_t)N1_ * C_];
__device__ __nv_bfloat16 g_w2h[(size_t)C_ * C_];
__device__ __nv_bfloat16 g_w2l[(size_t)C_ * C_];
// bf16 hi/lo attention operands
__device__ __nv_bfloat16 g_qbh[(size_t)B_ * H_ * T_ * D_];  // [B,H,T,D] (scaled)
__device__ __nv_bfloat16 g_qbl[(size_t)B_ * H_ * T_ * D_];
__device__ __nv_bfloat16 g_kbh[(size_t)B_ * H_ * T_ * D_];  // [B,H,T,D]
__device__ __nv_bfloat16 g_kbl[(size_t)B_ * H_ * T_ * D_];
__device__ __nv_bfloat16 g_vth[(size_t)B_ * H_ * D_ * T_];  // [B,H,D,T]
__device__ __nv_bfloat16 g_vtl[(size_t)B_ * H_ * D_ * T_];

__device__ __forceinline__ float fast_exp2(float x) {
    float r;
    asm("ex2.approx.ftz.f32 %0, %1;" : "=f"(r) : "f"(x));
    return r;
}

__device__ __forceinline__ uint32_t smem_u32(const void* p) {
    return (uint32_t)__cvta_generic_to_shared(p);
}

__device__ __forceinline__ uint32_t pack_bf16(float lo, float hi) {
    uint32_t r;
    asm("cvt.rn.bf16x2.f32 %0, %1, %2;" : "=r"(r) : "f"(hi), "f"(lo));
    return r;
}

// ======================= small helper kernels =======================

// fused: row sum-of-squares + fp32 -> bf16 hi/lo split of X (one read pass)
__global__ void prep_x_kernel(const float* __restrict__ X, float* __restrict__ xsq,
                              __nv_bfloat16* __restrict__ Xh,
                              __nv_bfloat16* __restrict__ Xl)
{
    int m = blockIdx.x;
    int tid = threadIdx.x;
    size_t i = (size_t)m * C_ + tid * 4;
    float4 v = *(const float4*)(X + i);
    __nv_bfloat16 h0 = __float2bfloat16(v.x);
    __nv_bfloat16 h1 = __float2bfloat16(v.y);
    __nv_bfloat16 h2 = __float2bfloat16(v.z);
    __nv_bfloat16 h3 = __float2bfloat16(v.w);
    __nv_bfloat162 a, b;
    a.x = h0; a.y = h1; b.x = h2; b.y = h3;
    *(__nv_bfloat162*)(Xh + i)     = a;
    *(__nv_bfloat162*)(Xh + i + 2) = b;
    __nv_bfloat162 c, d;
    c.x = __float2bfloat16(v.x - __bfloat162float(h0));
    c.y = __float2bfloat16(v.y - __bfloat162float(h1));
    d.x = __float2bfloat16(v.z - __bfloat162float(h2));
    d.y = __float2bfloat16(v.w - __bfloat162float(h3));
    *(__nv_bfloat162*)(Xl + i)     = c;
    *(__nv_bfloat162*)(Xl + i + 2) = d;

    float s = v.x * v.x + v.y * v.y + v.z * v.z + v.w * v.w;
#pragma unroll
    for (int o = 16; o; o >>= 1) s += __shfl_xor_sync(0xffffffffu, s, o);
    __shared__ float red[8];
    if ((tid & 31) == 0) red[tid >> 5] = s;
    __syncthreads();
    if (tid == 0) {
        float t = 0.f;
#pragma unroll
        for (int j = 0; j < 8; j++) t += red[j];
        xsq[m] = t;
    }
}

__global__ void colsq_kernel(const float* __restrict__ W, float* __restrict__ out,
                             int K, int N)
{
    __shared__ float red[4][64];
    int tx = threadIdx.x & 63, ty = threadIdx.x >> 6;
    int n = blockIdx.x * 64 + tx;
    float s = 0.f;
    for (int k = ty; k < K; k += 4) {
        float w = W[(size_t)k * N + n];
        s = fmaf(w, w, s);
    }
    red[ty][tx] = s;
    __syncthreads();
    if (ty == 0) out[n] = red[0][tx] + red[1][tx] + red[2][tx] + red[3][tx];
}

// W[K][N] fp32 -> WT[N][K] bf16 hi/lo (32x32 smem transpose)
__global__ void wconv_kernel(const float* __restrict__ W,
                             __nv_bfloat16* __restrict__ WhT,
                             __nv_bfloat16* __restrict__ WlT,
                             int K, int N)
{
    __shared__ float tile[32][33];
    int bx = blockIdx.x, by = blockIdx.y;
    int tx = threadIdx.x & 31, ty = threadIdx.x >> 5;
#pragma unroll
    for (int i = ty; i < 32; i += 8)
        tile[i][tx] = W[(size_t)(by * 32 + i) * N + bx * 32 + tx];
    __syncthreads();
#pragma unroll
    for (int i = ty; i < 32; i += 8) {
        int n = bx * 32 + i, k = by * 32 + tx;
        float v = tile[tx][i];
        __nv_bfloat16 h = __float2bfloat16(v);
        WhT[(size_t)n * K + k] = h;
        WlT[(size_t)n * K + k] = __float2bfloat16(v - __bfloat162float(h));
    }
}

// ======================= mma.sync helpers =======================

#define LDSM4(r0, r1, r2, r3, addr) \
    asm volatile("ldmatrix.sync.aligned.m8n8.x4.shared.b16 {%0,%1,%2,%3}, [%4];" \
                 : "=r"(r0), "=r"(r1), "=r"(r2), "=r"(r3) : "r"(addr))

#define MMA16816(d, a, b) \
    asm volatile("mma.sync.aligned.m16n8k16.row.col.f32.bf16.bf16.f32 " \
                 "{%0,%1,%2,%3}, {%4,%5,%6,%7}, {%8,%9}, {%0,%1,%2,%3};" \
                 : "+f"((d)[0]), "+f"((d)[1]), "+f"((d)[2]), "+f"((d)[3]) \
                 : "r"((a)[0]), "r"((a)[1]), "r"((a)[2]), "r"((a)[3]), \
                   "r"((b)[0]), "r"((b)[1]))

__device__ __forceinline__ void cp16(uint32_t dst, const void* src) {
    asm volatile("cp.async.cg.shared.global [%0], [%1], 16;" :: "r"(dst), "l"(src));
}

// ======================= shared GEMM core pieces =======================
#define ROWB   80
#define TILEB  (128 * ROWB)
#define OFF_AH 0
#define OFF_AL (1 * TILEB)
#define OFF_BH (2 * TILEB)
#define OFF_BL (3 * TILEB)
#define STAGEB (4 * TILEB)
#define MMA_SMEM (2 * STAGEB)

__device__ __forceinline__ void load_stage(
    uint32_t st, const __nv_bfloat16* Agh, const __nv_bfloat16* Agl,
    const __nv_bfloat16* Bgh, const __nv_bfloat16* Bgl,
    int k0, int K, int tid)
{
#pragma unroll
    for (int it = 0; it < 2; it++) {
        int idx = it * 256 + tid;
        int row = idx >> 2;
        int ch = (idx & 3) * 16;
        uint32_t dst = (uint32_t)row * ROWB + ch;
        size_t srcel = (size_t)row * K + k0;
        cp16(st + OFF_AH + dst, (const char*)(Agh + srcel) + ch);
        cp16(st + OFF_AL + dst, (const char*)(Agl + srcel) + ch);
        cp16(st + OFF_BH + dst, (const char*)(Bgh + srcel) + ch);
        cp16(st + OFF_BL + dst, (const char*)(Bgl + srcel) + ch);
    }
}

// bf16x3 mainloop over one K-chunk stage; fragment-cached (12 LDSM4 / kstep)
__device__ __forceinline__ void gemm_chunk(
    uint32_t st, uint32_t aSel, uint32_t bSel, int warpM, int warpN,
    float acc[4][4][4])
{
#pragma unroll
    for (int ks = 0; ks < 2; ks++) {
        const uint32_t aHB = st + OFF_AH + (uint32_t)warpM * 64 * ROWB + aSel + ks * 32;
        const uint32_t aLB = st + OFF_AL + (uint32_t)warpM * 64 * ROWB + aSel + ks * 32;
        const uint32_t bHB = st + OFF_BH + (uint32_t)warpN * 32 * ROWB + bSel + ks * 32;
        const uint32_t bLB = st + OFF_BL + (uint32_t)warpN * 32 * ROWB + bSel + ks * 32;
        uint32_t ah4[4][4];
#pragma unroll
        for (int mt = 0; mt < 4; mt++)
            LDSM4(ah4[mt][0], ah4[mt][1], ah4[mt][2], ah4[mt][3],
                  aHB + mt * (16 * ROWB));
        uint32_t bh[4][2], bl[4][2];
#pragma unroll
        for (int nt2 = 0; nt2 < 2; nt2++) {
            uint32_t r0, r1, r2, r3;
            LDSM4(r0, r1, r2, r3, bHB + nt2 * (16 * ROWB));
            bh[nt2 * 2 + 0][0] = r0; bh[nt2 * 2 + 0][1] = r1;
            bh[nt2 * 2 + 1][0] = r2; bh[nt2 * 2 + 1][1] = r3;
            LDSM4(r0, r1, r2, r3, bLB + nt2 * (16 * ROWB));
            bl[nt2 * 2 + 0][0] = r0; bl[nt2 * 2 + 0][1] = r1;
            bl[nt2 * 2 + 1][0] = r2; bl[nt2 * 2 + 1][1] = r3;
        }
#pragma unroll
        for (int mt = 0; mt < 4; mt++)
#pragma unroll
            for (int nt = 0; nt < 4; nt++)
                MMA16816(acc[mt][nt], ah4[mt], bh[nt]);
#pragma unroll
        for (int mt = 0; mt < 4; mt++)
#pragma unroll
            for (int nt = 0; nt < 4; nt++)
                MMA16816(acc[mt][nt], ah4[mt], bl[nt]);
        uint32_t al4[4];
#pragma unroll
        for (int mt = 0; mt < 4; mt++) {
            LDSM4(al4[0], al4[1], al4[2], al4[3], aLB + mt * (16 * ROWB));
#pragma unroll
            for (int nt = 0; nt < 4; nt++)
                MMA16816(acc[mt][nt], al4, bh[nt]);
        }
    }
}

// ======================= GEMM2: yat -> fp32 out =======================
__global__ void __launch_bounds__(256, 2) yat_mma_gemm_kernel(
    const __nv_bfloat16* __restrict__ Ah, const __nv_bfloat16* __restrict__ Al,
    const __nv_bfloat16* __restrict__ BhT, const __nv_bfloat16* __restrict__ BlT,
    const float* __restrict__ asq, const float* __restrict__ bsq,
    const float* __restrict__ bias, float* __restrict__ Cout,
    int M, int N, int K, float scale)
{
    extern __shared__ char smem[];
    const uint32_t sb = smem_u32(smem);

    const int tid = threadIdx.x;
    const int wid = tid >> 5, lane = tid & 31;
    const int warpM = wid >> 2;
    const int warpN = wid & 3;
    const int rowBase = blockIdx.y * 128;
    const int colBase = blockIdx.x * 128;
    const int NC = K >> 5;

    const __nv_bfloat16* Agh = Ah + (size_t)rowBase * K;
    const __nv_bfloat16* Agl = Al + (size_t)rowBase * K;
    const __nv_bfloat16* Bgh = BhT + (size_t)colBase * K;
    const __nv_bfloat16* Bgl = BlT + (size_t)colBase * K;

    const uint32_t aSel = (uint32_t)(lane & 15) * ROWB + (uint32_t)(lane >> 4) * 16;
    const uint32_t bSel = (uint32_t)(((lane >> 4) & 1) * 8 + (lane & 7)) * ROWB +
                          (uint32_t)((lane >> 3) & 1) * 16;

    float acc[4][4][4];
#pragma unroll
    for (int i = 0; i < 4; i++)
#pragma unroll
        for (int j = 0; j < 4; j++)
#pragma unroll
            for (int e = 0; e < 4; e++) acc[i][j][e] = 0.f;

    load_stage(sb, Agh, Agl, Bgh, Bgl, 0, K, tid);
    asm volatile("cp.async.commit_group;" ::: "memory");

    for (int c = 0; c < NC; c++) {
        if (c + 1 < NC) {
            load_stage(sb + (uint32_t)((c + 1) & 1) * STAGEB,
                       Agh, Agl, Bgh, Bgl, (c + 1) << 5, K, tid);
            asm volatile("cp.async.commit_group;" ::: "memory");
            asm volatile("cp.async.wait_group 1;" ::: "memory");
        } else {
            asm volatile("cp.async.wait_group 0;" ::: "memory");
        }
        __syncthreads();
        gemm_chunk(sb + (uint32_t)(c & 1) * STAGEB, aSel, bSel, warpM, warpN, acc);
        __syncthreads();
    }

    const int lr = lane >> 2, lc = (lane & 3) * 2;
    const int mW = rowBase + warpM * 64;
    const int nW = colBase + warpN * 32;
#pragma unroll
    for (int mt = 0; mt < 4; mt++) {
        const int r0g = mW + mt * 16 + lr;
        const int r1g = r0g + 8;
        const float av0 = asq[r0g];
        const float av1 = asq[r1g];
#pragma unroll
        for (int nt = 0; nt < 4; nt++) {
            const int cg = nW + nt * 8 + lc;
            const float bq0 = bsq[cg], bq1 = bsq[cg + 1];
            const float bi0 = bias[cg], bi1 = bias[cg + 1];
            float d00 = acc[mt][nt][0], d01 = acc[mt][nt][1];
            float d10 = acc[mt][nt][2], d11 = acc[mt][nt][3];
            float2 o0, o1;
            o0.x = __fdividef(d00 * d00, av0 + bq0 - 2.f * d00 + EPS_) * scale + bi0;
            o0.y = __fdividef(d01 * d01, av0 + bq1 - 2.f * d01 + EPS_) * scale + bi1;
            o1.x = __fdividef(d10 * d10, av1 + bq0 - 2.f * d10 + EPS_) * scale + bi0;
            o1.y = __fdividef(d11 * d11, av1 + bq1 - 2.f * d11 + EPS_) * scale + bi1;
            *(float2*)(Cout + (size_t)r0g * N + cg) = o0;
            *(float2*)(Cout + (size_t)r1g * N + cg) = o1;
        }
    }
}

// ======================= GEMM1: yat + RoPE + hi/lo split fused epilogue =======================
// Writes Q/K [B,H,T,D] (Q pre-scaled by QSC) and V^T [B,H,D,T], all bf16 hi/lo.
__global__ void __launch_bounds__(256, 2) yat_rope_gemm_kernel(
    const __nv_bfloat16* __restrict__ Ah, const __nv_bfloat16* __restrict__ Al,
    const __nv_bfloat16* __restrict__ BhT, const __nv_bfloat16* __restrict__ BlT,
    const float* __restrict__ asq, const float* __restrict__ bsq,
    const float* __restrict__ bias,
    __nv_bfloat16* __restrict__ Qh, __nv_bfloat16* __restrict__ Ql,
    __nv_bfloat16* __restrict__ Kh, __nv_bfloat16* __restrict__ Kl,
    __nv_bfloat16* __restrict__ VTh, __nv_bfloat16* __restrict__ VTl,
    float scale)
{
    extern __shared__ char smem[];
    const uint32_t sb = smem_u32(smem);
    const int K = C_, N = N1_;

    const int tid = threadIdx.x;
    const int wid = tid >> 5, lane = tid & 31;
    const int warpM = wid >> 2;
    const int warpN = wid & 3;
    const int rowBase = blockIdx.y * 128;
    const int colBase = blockIdx.x * 128;
    const int NC = K >> 5;

    const __nv_bfloat16* Agh = Ah + (size_t)rowBase * K;
    const __nv_bfloat16* Agl = Al + (size_t)rowBase * K;
    const __nv_bfloat16* Bgh = BhT + (size_t)colBase * K;
    const __nv_bfloat16* Bgl = BlT + (size_t)colBase * K;

    const uint32_t aSel = (uint32_t)(lane & 15) * ROWB + (uint32_t)(lane >> 4) * 16;
    const uint32_t bSel = (uint32_t)(((lane >> 4) & 1) * 8 + (lane & 7)) * ROWB +
                          (uint32_t)((lane >> 3) & 1) * 16;

    float acc[4][4][4];
#pragma unroll
    for (int i = 0; i < 4; i++)
#pragma unroll
        for (int j = 0; j < 4; j++)
#pragma unroll
            for (int e = 0; e < 4; e++) acc[i][j][e] = 0.f;

    load_stage(sb, Agh, Agl, Bgh, Bgl, 0, K, tid);
    asm volatile("cp.async.commit_group;" ::: "memory");

    for (int c = 0; c < NC; c++) {
        if (c + 1 < NC) {
            load_stage(sb + (uint32_t)((c + 1) & 1) * STAGEB,
                       Agh, Agl, Bgh, Bgl, (c + 1) << 5, K, tid);
            asm volatile("cp.async.commit_group;" ::: "memory");
            asm volatile("cp.async.wait_group 1;" ::: "memory");
        } else {
            asm volatile("cp.async.wait_group 0;" ::: "memory");
        }
        __syncthreads();
        gemm_chunk(sb + (uint32_t)(c & 1) * STAGEB, aSel, bSel, warpM, warpN, acc);
        __syncthreads();
    }

    // ---- epilogue: yat + bias, then RoPE/split per segment ----
    const int lr = lane >> 2, lc = (lane & 3) * 2;
    const int mW = rowBase + warpM * 64;
    const int nW = colBase + warpN * 32;
    const int seg = colBase >> 10;                 // 0=Q, 1=K, 2=V
    const float QSC = 0.125f * 1.4426950408889634f;

    // rotation frequencies per nt (col pair index within head)
    float fr[4];
#pragma unroll
    for (int nt = 0; nt < 4; nt++) {
        int cg = nW + nt * 8 + lc;
        int i = (cg & 63) >> 1;
        fr[nt] = powf(10000.0f, -(float)i / 32.0f);
    }

#pragma unroll
    for (int mt = 0; mt < 4; mt++) {
        const int r0g = mW + mt * 16 + lr;
        const int r1g = r0g + 8;
        const float av0 = asq[r0g];
        const float av1 = asq[r1g];
        const int b0 = r0g >> 11, t0 = r0g & 2047;
        const int b1 = r1g >> 11, t1 = r1g & 2047;
#pragma unroll
        for (int nt = 0; nt < 4; nt++) {
            const int cg = nW + nt * 8 + lc;
            const float bq0 = bsq[cg], bq1 = bsq[cg + 1];
            const float bi0 = bias[cg], bi1 = bias[cg + 1];
            float d00 = acc[mt][nt][0], d01 = acc[mt][nt][1];
            float d10 = acc[mt][nt][2], d11 = acc[mt][nt][3];
            float y00 = __fdividef(d00 * d00, av0 + bq0 - 2.f * d00 + EPS_) * scale + bi0;
            float y01 = __fdividef(d01 * d01, av0 + bq1 - 2.f * d01 + EPS_) * scale + bi1;
            float y10 = __fdividef(d10 * d10, av1 + bq0 - 2.f * d10 + EPS_) * scale + bi0;
            float y11 = __fdividef(d11 * d11, av1 + bq1 - 2.f * d11 + EPS_) * scale + bi1;

            const int colh = cg & 1023;
            const int h = colh >> 6;
            const int d = colh & 63;

            if (seg < 2) {
                float s0, c0, s1, c1;
                sincosf((float)t0 * fr[nt], &s0, &c0);
                sincosf((float)t1 * fr[nt], &s1, &c1);
                float sc = (seg == 0) ? QSC : 1.0f;
                float a0 = (y00 * c0 - y01 * s0) * sc;
                float a1 = (y01 * c0 + y00 * s0) * sc;
                float e0 = (y10 * c1 - y11 * s1) * sc;
                float e1 = (y11 * c1 + y10 * s1) * sc;
                __nv_bfloat16* Dh = (seg == 0) ? Qh : Kh;
                __nv_bfloat16* Dl = (seg == 0) ? Ql : Kl;
                size_t o0 = ((size_t)(b0 * H_ + h) * T_ + t0) * D_ + d;
                size_t o1 = ((size_t)(b1 * H_ + h) * T_ + t1) * D_ + d;
                __nv_bfloat162 hh, ll;
                hh.x = __float2bfloat16(a0); hh.y = __float2bfloat16(a1);
                ll.x = __float2bfloat16(a0 - __bfloat162float(hh.x));
                ll.y = __float2bfloat16(a1 - __bfloat162float(hh.y));
                *(__nv_bfloat162*)(Dh + o0) = hh;
                *(__nv_bfloat162*)(Dl + o0) = ll;
                hh.x = __float2bfloat16(e0); hh.y = __float2bfloat16(e1);
                ll.x = __float2bfloat16(e0 - __bfloat162float(hh.x));
                ll.y = __float2bfloat16(e1 - __bfloat162float(hh.y));
                *(__nv_bfloat162*)(Dh + o1) = hh;
                *(__nv_bfloat162*)(Dl + o1) = ll;
            } else {
                // V: transpose store into [B,H,D,T]
                size_t ov0 = ((size_t)(b0 * H_ + h) * D_ + d) * T_ + t0;
                size_t ov1 = ((size_t)(b1 * H_ + h) * D_ + d) * T_ + t1;
                __nv_bfloat16 vh;
                vh = __float2bfloat16(y00);
                VTh[ov0] = vh; VTl[ov0] = __float2bfloat16(y00 - __bfloat162float(vh));
                vh = __float2bfloat16(y01);
                VTh[ov0 + T_] = vh; VTl[ov0 + T_] = __float2bfloat16(y01 - __bfloat162float(vh));
                vh = __float2bfloat16(y10);
                VTh[ov1] = vh; VTl[ov1] = __float2bfloat16(y10 - __bfloat162float(vh));
                vh = __float2bfloat16(y11);
                VTh[ov1 + T_] = vh; VTl[ov1 + T_] = __float2bfloat16(y11 - __bfloat162float(vh));
            }
        }
    }
}

// ======================= tensor-core causal flash attention =======================
// BQ=128, BKV=64, 8 warps x 16 q-rows. bf16x3 emulation for S and PV.
// Epilogue writes ah/al bf16 hi/lo directly + atomic row sum-of-squares into osq.
#define AROWB 144
#define QTILE (128 * AROWB)
#define KVTILE (64 * AROWB)
#define SQH_OFF 0
#define SQL_OFF QTILE
#define STG_OFF (2 * QTILE)
#define STGSZ  (4 * KVTILE)
#define ST_KH 0
#define ST_KL (1 * KVTILE)
#define ST_VH (2 * KVTILE)
#define ST_VL (3 * KVTILE)
#define ATTN_SMEM (2 * QTILE + 2 * STGSZ)

__device__ __forceinline__ void attn_load_stage(
    uint32_t st, const __nv_bfloat16* kh, const __nv_bfloat16* kl,
    const __nv_bfloat16* vth, const __nv_bfloat16* vtl,
    size_t bhT, size_t bhD, int k0, int tid)
{
#pragma unroll
    for (int it = 0; it < 2; it++) {
        int idx = it * 256 + tid;
        int row = idx >> 3;
        int ch = (idx & 7) * 16;
        uint32_t dst = (uint32_t)row * AROWB + ch;
        cp16(st + ST_KH + dst, (const char*)(kh + (bhT + k0 + row) * D_) + ch);
        cp16(st + ST_KL + dst, (const char*)(kl + (bhT + k0 + row) * D_) + ch);
        cp16(st + ST_VH + dst, (const char*)(vth + (bhD + row) * T_ + k0) + ch);
        cp16(st + ST_VL + dst, (const char*)(vtl + (bhD + row) * T_ + k0) + ch);
    }
}

__global__ void __launch_bounds__(256, 2) attn_mma_kernel(
    const __nv_bfloat16* __restrict__ qh, const __nv_bfloat16* __restrict__ ql,
    const __nv_bfloat16* __restrict__ kh, const __nv_bfloat16* __restrict__ kl,
    const __nv_bfloat16* __restrict__ vth, const __nv_bfloat16* __restrict__ vtl,
    __nv_bfloat16* __restrict__ Oh, __nv_bfloat16* __restrict__ Ol,
    float* __restrict__ osq)
{
    extern __shared__ char smem[];
    const uint32_t sb = smem_u32(smem);

    const int bh = blockIdx.y;
    const int qx = 15 - (int)blockIdx.x;
    const int q0 = qx * 128;
    const size_t bhT = (size_t)bh * T_;
    const size_t bhD = (size_t)bh * D_;

    const int tid = threadIdx.x;
    const int wid = tid >> 5, lane = tid & 31;
    const int lr = lane >> 2, c2 = (lane & 3) * 2;

    const uint32_t aSel = (uint32_t)(lane & 15) * AROWB + (uint32_t)(lane >> 4) * 16;
    const uint32_t bSel = (uint32_t)(((lane >> 4) & 1) * 8 + (lane & 7)) * AROWB +
                          (uint32_t)((lane >> 3) & 1) * 16;

#pragma unroll
    for (int it = 0; it < 4; it++) {
        int idx = it * 256 + tid;
        int row = idx >> 3;
        int ch = (idx & 7) * 16;
        uint32_t dst = (uint32_t)row * AROWB + ch;
        cp16(sb + SQH_OFF + dst, (const char*)(qh + (bhT + q0 + row) * D_) + ch);
        cp16(sb + SQL_OFF + dst, (const char*)(ql + (bhT + q0 + row) * D_) + ch);
    }
    asm volatile("cp.async.commit_group;" ::: "memory");

    attn_load_stage(sb + STG_OFF, kh, kl, vth, vtl, bhT, bhD, 0, tid);
    asm volatile("cp.async.commit_group;" ::: "memory");

    asm volatile("cp.async.wait_group 1;" ::: "memory");
    __syncthreads();
    uint32_t qhf[4][4];
    {
        const uint32_t aQ = sb + SQH_OFF + (uint32_t)wid * 16 * AROWB + aSel;
#pragma unroll
        for (int ks = 0; ks < 4; ks++)
            LDSM4(qhf[ks][0], qhf[ks][1], qhf[ks][2], qhf[ks][3], aQ + ks * 32);
    }

    float O[8][4];
#pragma unroll
    for (int j = 0; j < 8; j++)
#pragma unroll
        for (int e = 0; e < 4; e++) O[j][e] = 0.f;
    float mrow[2] = {-1e30f, -1e30f};
    float lrow[2] = {0.f, 0.f};

    const int ntiles = 2 * qx + 2;
    const int rowg0 = q0 + wid * 16 + lr;

    for (int kt = 0; kt < ntiles; kt++) {
        const uint32_t st = sb + STG_OFF + (uint32_t)(kt & 1) * STGSZ;
        if (kt + 1 < ntiles) {
            attn_load_stage(sb + STG_OFF + (uint32_t)((kt + 1) & 1) * STGSZ,
                            kh, kl, vth, vtl, bhT, bhD, (kt + 1) * 64, tid);
            asm volatile("cp.async.commit_group;" ::: "memory");
            asm volatile("cp.async.wait_group 1;" ::: "memory");
        } else {
            asm volatile("cp.async.wait_group 0;" ::: "memory");
        }
        __syncthreads();

        float S[8][4];
#pragma unroll
        for (int j = 0; j < 8; j++)
#pragma unroll
            for (int e = 0; e < 4; e++) S[j][e] = 0.f;

        const uint32_t aQl = sb + SQL_OFF + (uint32_t)wid * 16 * AROWB + aSel;
#pragma unroll
        for (int ks = 0; ks < 4; ks++) {
            uint32_t al[4];
            LDSM4(al[0], al[1], al[2], al[3], aQl + ks * 32);
#pragma unroll
            for (int np = 0; np < 4; np++) {
                uint32_t r0, r1, r2, r3;
                LDSM4(r0, r1, r2, r3, st + ST_KH + np * (16 * AROWB) + bSel + ks * 32);
                uint32_t bh0[2] = {r0, r1}, bh1[2] = {r2, r3};
                MMA16816(S[np * 2 + 0], qhf[ks], bh0);
                MMA16816(S[np * 2 + 1], qhf[ks], bh1);
                MMA16816(S[np * 2 + 0], al, bh0);
                MMA16816(S[np * 2 + 1], al, bh1);
                LDSM4(r0, r1, r2, r3, st + ST_KL + np * (16 * AROWB) + bSel + ks * 32);
                uint32_t bl0[2] = {r0, r1}, bl1[2] = {r2, r3};
                MMA16816(S[np * 2 + 0], qhf[ks], bl0);
                MMA16816(S[np * 2 + 1], qhf[ks], bl1);
            }
        }

        const int k0 = kt * 64;
        if (kt >= 2 * qx) {
#pragma unroll
            for (int j = 0; j < 8; j++) {
                int col = k0 + j * 8 + c2;
                if (col > rowg0)     S[j][0] = -1e30f;
                if (col + 1 > rowg0) S[j][1] = -1e30f;
                if (col > rowg0 + 8)     S[j][2] = -1e30f;
                if (col + 1 > rowg0 + 8) S[j][3] = -1e30f;
            }
        }

#pragma unroll
        for (int i = 0; i < 2; i++) {
            float mx = -1e30f;
#pragma unroll
            for (int j = 0; j < 8; j++)
                mx = fmaxf(mx, fmaxf(S[j][2 * i], S[j][2 * i + 1]));
            mx = fmaxf(mx, __shfl_xor_sync(0xffffffffu, mx, 1));
            mx = fmaxf(mx, __shfl_xor_sync(0xffffffffu, mx, 2));
            float mn = fmaxf(mrow[i], mx);
            float cf = fast_exp2(mrow[i] - mn);
            mrow[i] = mn;
            float rs = 0.f;
#pragma unroll
            for (int j = 0; j < 8; j++) {
                float p0 = fast_exp2(S[j][2 * i] - mn);
                float p1 = fast_exp2(S[j][2 * i + 1] - mn);
                S[j][2 * i] = p0; S[j][2 * i + 1] = p1;
                rs += p0 + p1;
            }
            rs += __shfl_xor_sync(0xffffffffu, rs, 1);
            rs += __shfl_xor_sync(0xffffffffu, rs, 2);
            lrow[i] = lrow[i] * cf + rs;
#pragma unroll
            for (int j = 0; j < 8; j++) { O[j][2 * i] *= cf; O[j][2 * i + 1] *= cf; }
        }

        uint32_t PH[4][4], PL[4][4];
#pragma unroll
        for (int t = 0; t < 4; t++) {
#pragma unroll
            for (int h2 = 0; h2 < 2; h2++) {
                int j = 2 * t + h2;
                float p0 = S[j][0], p1 = S[j][1], p2 = S[j][2], p3 = S[j][3];
                float h0 = __bfloat162float(__float2bfloat16(p0));
                float h1 = __bfloat162float(__float2bfloat16(p1));
                float h2f = __bfloat162float(__float2bfloat16(p2));
                float h3 = __bfloat162float(__float2bfloat16(p3));
                PH[t][h2 * 2 + 0] = pack_bf16(p0, p1);
                PH[t][h2 * 2 + 1] = pack_bf16(p2, p3);
                PL[t][h2 * 2 + 0] = pack_bf16(p0 - h0, p1 - h1);
                PL[t][h2 * 2 + 1] = pack_bf16(p2 - h2f, p3 - h3);
            }
        }

#pragma unroll
        for (int t = 0; t < 4; t++) {
#pragma unroll
            for (int dn = 0; dn < 4; dn++) {
                uint32_t r0, r1, r2, r3;
                LDSM4(r0, r1, r2, r3, st + ST_VH + dn * (16 * AROWB) + bSel + t * 32);
                uint32_t vh0[2] = {r0, r1}, vh1[2] = {r2, r3};
                MMA16816(O[dn * 2 + 0], PH[t], vh0);
                MMA16816(O[dn * 2 + 1], PH[t], vh1);
                MMA16816(O[dn * 2 + 0], PL[t], vh0);
                MMA16816(O[dn * 2 + 1], PL[t], vh1);
                LDSM4(r0, r1, r2, r3, st + ST_VL + dn * (16 * AROWB) + bSel + t * 32);
                uint32_t vl0[2] = {r0, r1}, vl1[2] = {r2, r3};
                MMA16816(O[dn * 2 + 0], PH[t], vl0);
                MMA16816(O[dn * 2 + 1], PH[t], vl1);
            }
        }
        __syncthreads();
    }

    // ---- fused epilogue: normalize, bf16 hi/lo write + osq atomics ----
    const int b = bh >> 4, h = bh & 15;
    const float inv0 = 1.f / lrow[0], inv1 = 1.f / lrow[1];
    const size_t m0 = (size_t)(b * T_ + rowg0);
    const size_t m1 = m0 + 8;
    __nv_bfloat16* oh0 = Oh + m0 * C_ + h * 64;
    __nv_bfloat16* ol0 = Ol + m0 * C_ + h * 64;
    __nv_bfloat16* oh1 = Oh + m1 * C_ + h * 64;
    __nv_bfloat16* ol1 = Ol + m1 * C_ + h * 64;
    float sq0 = 0.f, sq1 = 0.f;
#pragma unroll
    for (int j = 0; j < 8; j++) {
        float y0 = O[j][0] * inv0, y1 = O[j][1] * inv0;
        float y2 = O[j][2] * inv1, y3 = O[j][3] * inv1;
        sq0 += y0 * y0 + y1 * y1;
        sq1 += y2 * y2 + y3 * y3;
        __nv_bfloat162 hh, ll;
        hh.x = __float2bfloat16(y0); hh.y = __float2bfloat16(y1);
        ll.x = __float2bfloat16(y0 - __bfloat162float(hh.x));
        ll.y = __float2bfloat16(y1 - __bfloat162float(hh.y));
        *(__nv_bfloat162*)(oh0 + j * 8 + c2) = hh;
        *(__nv_bfloat162*)(ol0 + j * 8 + c2) = ll;
        hh.x = __float2bfloat16(y2); hh.y = __float2bfloat16(y3);
        ll.x = __float2bfloat16(y2 - __bfloat162float(hh.x));
        ll.y = __float2bfloat16(y3 - __bfloat162float(hh.y));
        *(__nv_bfloat162*)(oh1 + j * 8 + c2) = hh;
        *(__nv_bfloat162*)(ol1 + j * 8 + c2) = ll;
    }
    sq0 += __shfl_xor_sync(0xffffffffu, sq0, 1);
    sq0 += __shfl_xor_sync(0xffffffffu, sq0, 2);
    sq1 += __shfl_xor_sync(0xffffffffu, sq1, 1);
    sq1 += __shfl_xor_sync(0xffffffffu, sq1, 2);
    if ((lane & 3) == 0) {
        atomicAdd(osq + m0, sq0);
        atomicAdd(osq + m1, sq1);
    }
}

// ---------------- launcher ----------------
extern "C" void kernel_launch(void* const* d_in, const int* in_sizes, int n_in,
                              void* d_out, int out_size)
{
    (void)in_sizes; (void)n_in; (void)out_size;
    const float* x      = (const float*)d_in[0];
    const float* w_attn = (const float*)d_in[2];
    const float* b_attn = (const float*)d_in[3];
    const float* w_proj = (const float*)d_in[4];
    const float* b_proj = (const float*)d_in[5];
    float* out = (float*)d_out;

    float *xsq, *osq, *wsq1, *wsq2;
    __nv_bfloat16 *xh, *xl, *ah, *al, *w1h, *w1l, *w2h, *w2l;
    __nv_bfloat16 *qbh, *qbl, *kbh, *kbl, *vth, *vtl;
    cudaGetSymbolAddress((void**)&xsq,  g_xsq);
    cudaGetSymbolAddress((void**)&osq,  g_osq);
    cudaGetSymbolAddress((void**)&wsq1, g_wsq1);
    cudaGetSymbolAddress((void**)&wsq2, g_wsq2);
    cudaGetSymbolAddress((void**)&xh,   g_xh);
    cudaGetSymbolAddress((void**)&xl,   g_xl);
    cudaGetSymbolAddress((void**)&ah,   g_ah);
    cudaGetSymbolAddress((void**)&al,   g_al);
    cudaGetSymbolAddress((void**)&w1h,  g_w1h);
    cudaGetSymbolAddress((void**)&w1l,  g_w1l);
    cudaGetSymbolAddress((void**)&w2h,  g_w2h);
    cudaGetSymbolAddress((void**)&w2l,  g_w2l);
    cudaGetSymbolAddress((void**)&qbh,  g_qbh);
    cudaGetSymbolAddress((void**)&qbl,  g_qbl);
    cudaGetSymbolAddress((void**)&kbh,  g_kbh);
    cudaGetSymbolAddress((void**)&kbl,  g_kbl);
    cudaGetSymbolAddress((void**)&vth,  g_vth);
    cudaGetSymbolAddress((void**)&vtl,  g_vtl);

    const float scale1 = (float)(sqrt(3072.0) / log1p(3072.0));
    const float scale2 = (float)(sqrt(1024.0) / log1p(1024.0));

    cudaFuncSetAttribute(yat_mma_gemm_kernel,
                         cudaFuncAttributeMaxDynamicSharedMemorySize, MMA_SMEM);
    cudaFuncSetAttribute(yat_rope_gemm_kernel,
                         cudaFuncAttributeMaxDynamicSharedMemorySize, MMA_SMEM);
    cudaFuncSetAttribute(attn_mma_kernel,
                         cudaFuncAttributeMaxDynamicSharedMemorySize, ATTN_SMEM);

    prep_x_kernel<<<M_, 256>>>(x, xsq, xh, xl);
    colsq_kernel<<<N1_ / 64, 256>>>(w_attn, wsq1, C_, N1_);
    colsq_kernel<<<C_ / 64, 256>>>(w_proj, wsq2, C_, C_);
    wconv_kernel<<<dim3(N1_ / 32, C_ / 32), 256>>>(w_attn, w1h, w1l, C_, N1_);
    wconv_kernel<<<dim3(C_ / 32, C_ / 32), 256>>>(w_proj, w2h, w2l, C_, C_);

    cudaMemsetAsync(osq, 0, M_ * sizeof(float));

    yat_rope_gemm_kernel<<<dim3(N1_ / 128, M_ / 128), 256, MMA_SMEM>>>(
        xh, xl, w1h, w1l, xsq, wsq1, b_attn,
        qbh, qbl, kbh, kbl, vth, vtl, scale1);

    attn_mma_kernel<<<dim3(T_ / 128, B_ * H_), 256, ATTN_SMEM>>>(
        qbh, qbl, kbh, kbl, vth, vtl, ah, al, osq);

    yat_mma_gemm_kernel<<<dim3(C_ / 128, M_ / 128), 256, MMA_SMEM>>>(
        ah, al, w2h, w2l, osq, wsq2, b_proj, out, M_, C_, C_, scale2);
}

// round 8
// speedup vs baseline: 18.6459x; 1.3269x over previous
#include <cuda_runtime.h>
#include <cuda_fp16.h>
#include <math.h>
#include <stdint.h>

#define B_   2
#define T_   2048
#define C_   1024
#define H_   16
#define D_   64
#define M_   4096          // B_*T_
#define N1_  3072          // 3*C_
#define EPS_ 1e-6f

// ---------------- scratch (device globals; no allocation allowed) ----------------
__device__ float g_xsq[M_];
__device__ float g_osq[M_];
__device__ float g_wsq1[N1_];
__device__ float g_wsq2[C_];
// fp16 operands (A sides: hi only; B sides: hi+lo)
__device__ __half g_xh[(size_t)M_ * C_];
__device__ __half g_ah[(size_t)M_ * C_];
__device__ __half g_w1h[(size_t)N1_ * C_];  // [N,K] transposed
__device__ __half g_w1l[(size_t)N1_ * C_];
__device__ __half g_w2h[(size_t)C_ * C_];
__device__ __half g_w2l[(size_t)C_ * C_];
// attention operands
__device__ __half g_qbh[(size_t)B_ * H_ * T_ * D_];  // [B,H,T,D] (scaled), hi only
__device__ __half g_kbh[(size_t)B_ * H_ * T_ * D_];  // [B,H,T,D]
__device__ __half g_kbl[(size_t)B_ * H_ * T_ * D_];
__device__ __half g_vth[(size_t)B_ * H_ * D_ * T_];  // [B,H,D,T]
__device__ __half g_vtl[(size_t)B_ * H_ * D_ * T_];

__device__ __forceinline__ float fast_exp2(float x) {
    float r;
    asm("ex2.approx.ftz.f32 %0, %1;" : "=f"(r) : "f"(x));
    return r;
}

__device__ __forceinline__ uint32_t smem_u32(const void* p) {
    return (uint32_t)__cvta_generic_to_shared(p);
}

__device__ __forceinline__ uint32_t pack_f16(float lo, float hi) {
    uint32_t r;
    asm("cvt.rn.f16x2.f32 %0, %1, %2;" : "=r"(r) : "f"(hi), "f"(lo));
    return r;
}

// ======================= small helper kernels =======================

// fused: row sum-of-squares + fp32 -> fp16 of X (one read pass)
__global__ void prep_x_kernel(const float* __restrict__ X, float* __restrict__ xsq,
                              __half* __restrict__ Xh)
{
    int m = blockIdx.x;
    int tid = threadIdx.x;
    size_t i = (size_t)m * C_ + tid * 4;
    float4 v = *(const float4*)(X + i);
    *(__half2*)(Xh + i)     = __floats2half2_rn(v.x, v.y);
    *(__half2*)(Xh + i + 2) = __floats2half2_rn(v.z, v.w);

    float s = v.x * v.x + v.y * v.y + v.z * v.z + v.w * v.w;
#pragma unroll
    for (int o = 16; o; o >>= 1) s += __shfl_xor_sync(0xffffffffu, s, o);
    __shared__ float red[8];
    if ((tid & 31) == 0) red[tid >> 5] = s;
    __syncthreads();
    if (tid == 0) {
        float t = 0.f;
#pragma unroll
        for (int j = 0; j < 8; j++) t += red[j];
        xsq[m] = t;
    }
}

__global__ void colsq_kernel(const float* __restrict__ W, float* __restrict__ out,
                             int K, int N)
{
    __shared__ float red[4][64];
    int tx = threadIdx.x & 63, ty = threadIdx.x >> 6;
    int n = blockIdx.x * 64 + tx;
    float s = 0.f;
    for (int k = ty; k < K; k += 4) {
        float w = W[(size_t)k * N + n];
        s = fmaf(w, w, s);
    }
    red[ty][tx] = s;
    __syncthreads();
    if (ty == 0) out[n] = red[0][tx] + red[1][tx] + red[2][tx] + red[3][tx];
}

// W[K][N] fp32 -> WT[N][K] fp16 hi/lo (32x32 smem transpose)
__global__ void wconv_kernel(const float* __restrict__ W,
                             __half* __restrict__ WhT,
                             __half* __restrict__ WlT,
                             int K, int N)
{
    __shared__ float tile[32][33];
    int bx = blockIdx.x, by = blockIdx.y;
    int tx = threadIdx.x & 31, ty = threadIdx.x >> 5;
#pragma unroll
    for (int i = ty; i < 32; i += 8)
        tile[i][tx] = W[(size_t)(by * 32 + i) * N + bx * 32 + tx];
    __syncthreads();
#pragma unroll
    for (int i = ty; i < 32; i += 8) {
        int n = bx * 32 + i, k = by * 32 + tx;
        float v = tile[tx][i];
        __half h = __float2half_rn(v);
        WhT[(size_t)n * K + k] = h;
        WlT[(size_t)n * K + k] = __float2half_rn(v - __half2float(h));
    }
}

// ======================= mma.sync helpers =======================

#define LDSM4(r0, r1, r2, r3, addr) \
    asm volatile("ldmatrix.sync.aligned.m8n8.x4.shared.b16 {%0,%1,%2,%3}, [%4];" \
                 : "=r"(r0), "=r"(r1), "=r"(r2), "=r"(r3) : "r"(addr))

#define MMA16816(d, a, b) \
    asm volatile("mma.sync.aligned.m16n8k16.row.col.f32.f16.f16.f32 " \
                 "{%0,%1,%2,%3}, {%4,%5,%6,%7}, {%8,%9}, {%0,%1,%2,%3};" \
                 : "+f"((d)[0]), "+f"((d)[1]), "+f"((d)[2]), "+f"((d)[3]) \
                 : "r"((a)[0]), "r"((a)[1]), "r"((a)[2]), "r"((a)[3]), \
                   "r"((b)[0]), "r"((b)[1]))

__device__ __forceinline__ void cp16(uint32_t dst, const void* src) {
    asm volatile("cp.async.cg.shared.global [%0], [%1], 16;" :: "r"(dst), "l"(src));
}

// ======================= shared GEMM core (fp16x2, 2-pass) =======================
#define ROWB   80
#define TILEB  (128 * ROWB)
#define OFF_A  0
#define OFF_BH (1 * TILEB)
#define OFF_BL (2 * TILEB)
#define STAGEB (3 * TILEB)         // 30720
#define MMA_SMEM (2 * STAGEB)      // 61440

__device__ __forceinline__ void load_stage(
    uint32_t st, const __half* Ag,
    const __half* Bgh, const __half* Bgl,
    int k0, int K, int tid)
{
#pragma unroll
    for (int it = 0; it < 2; it++) {
        int idx = it * 256 + tid;
        int row = idx >> 2;
        int ch = (idx & 3) * 16;
        uint32_t dst = (uint32_t)row * ROWB + ch;
        size_t srcel = (size_t)row * K + k0;
        cp16(st + OFF_A + dst,  (const char*)(Ag + srcel) + ch);
        cp16(st + OFF_BH + dst, (const char*)(Bgh + srcel) + ch);
        cp16(st + OFF_BL + dst, (const char*)(Bgl + srcel) + ch);
    }
}

// 2-pass mainloop over one K-chunk stage: acc += Ah*Bh + Ah*Bl
__device__ __forceinline__ void gemm_chunk(
    uint32_t st, uint32_t aSel, uint32_t bSel, int warpM, int warpN,
    float acc[4][4][4])
{
#pragma unroll
    for (int ks = 0; ks < 2; ks++) {
        const uint32_t aB  = st + OFF_A  + (uint32_t)warpM * 64 * ROWB + aSel + ks * 32;
        const uint32_t bHB = st + OFF_BH + (uint32_t)warpN * 32 * ROWB + bSel + ks * 32;
        const uint32_t bLB = st + OFF_BL + (uint32_t)warpN * 32 * ROWB + bSel + ks * 32;
        uint32_t ah4[4][4];
#pragma unroll
        for (int mt = 0; mt < 4; mt++)
            LDSM4(ah4[mt][0], ah4[mt][1], ah4[mt][2], ah4[mt][3],
                  aB + mt * (16 * ROWB));
        uint32_t bh[4][2], bl[4][2];
#pragma unroll
        for (int nt2 = 0; nt2 < 2; nt2++) {
            uint32_t r0, r1, r2, r3;
            LDSM4(r0, r1, r2, r3, bHB + nt2 * (16 * ROWB));
            bh[nt2 * 2 + 0][0] = r0; bh[nt2 * 2 + 0][1] = r1;
            bh[nt2 * 2 + 1][0] = r2; bh[nt2 * 2 + 1][1] = r3;
            LDSM4(r0, r1, r2, r3, bLB + nt2 * (16 * ROWB));
            bl[nt2 * 2 + 0][0] = r0; bl[nt2 * 2 + 0][1] = r1;
            bl[nt2 * 2 + 1][0] = r2; bl[nt2 * 2 + 1][1] = r3;
        }
#pragma unroll
        for (int mt = 0; mt < 4; mt++)
#pragma unroll
            for (int nt = 0; nt < 4; nt++)
                MMA16816(acc[mt][nt], ah4[mt], bh[nt]);
#pragma unroll
        for (int mt = 0; mt < 4; mt++)
#pragma unroll
            for (int nt = 0; nt < 4; nt++)
                MMA16816(acc[mt][nt], ah4[mt], bl[nt]);
    }
}

// ======================= GEMM2: yat -> fp32 out =======================
__global__ void __launch_bounds__(256, 2) yat_mma_gemm_kernel(
    const __half* __restrict__ Ah,
    const __half* __restrict__ BhT, const __half* __restrict__ BlT,
    const float* __restrict__ asq, const float* __restrict__ bsq,
    const float* __restrict__ bias, float* __restrict__ Cout,
    int M, int N, int K, float scale)
{
    extern __shared__ char smem[];
    const uint32_t sb = smem_u32(smem);

    const int tid = threadIdx.x;
    const int wid = tid >> 5, lane = tid & 31;
    const int warpM = wid >> 2;
    const int warpN = wid & 3;
    const int rowBase = blockIdx.y * 128;
    const int colBase = blockIdx.x * 128;
    const int NC = K >> 5;

    const __half* Agh = Ah + (size_t)rowBase * K;
    const __half* Bgh = BhT + (size_t)colBase * K;
    const __half* Bgl = BlT + (size_t)colBase * K;

    const uint32_t aSel = (uint32_t)(lane & 15) * ROWB + (uint32_t)(lane >> 4) * 16;
    const uint32_t bSel = (uint32_t)(((lane >> 4) & 1) * 8 + (lane & 7)) * ROWB +
                          (uint32_t)((lane >> 3) & 1) * 16;

    float acc[4][4][4];
#pragma unroll
    for (int i = 0; i < 4; i++)
#pragma unroll
        for (int j = 0; j < 4; j++)
#pragma unroll
            for (int e = 0; e < 4; e++) acc[i][j][e] = 0.f;

    load_stage(sb, Agh, Bgh, Bgl, 0, K, tid);
    asm volatile("cp.async.commit_group;" ::: "memory");

    for (int c = 0; c < NC; c++) {
        if (c + 1 < NC) {
            load_stage(sb + (uint32_t)((c + 1) & 1) * STAGEB,
                       Agh, Bgh, Bgl, (c + 1) << 5, K, tid);
            asm volatile("cp.async.commit_group;" ::: "memory");
            asm volatile("cp.async.wait_group 1;" ::: "memory");
        } else {
            asm volatile("cp.async.wait_group 0;" ::: "memory");
        }
        __syncthreads();
        gemm_chunk(sb + (uint32_t)(c & 1) * STAGEB, aSel, bSel, warpM, warpN, acc);
        __syncthreads();
    }

    const int lr = lane >> 2, lc = (lane & 3) * 2;
    const int mW = rowBase + warpM * 64;
    const int nW = colBase + warpN * 32;
#pragma unroll
    for (int mt = 0; mt < 4; mt++) {
        const int r0g = mW + mt * 16 + lr;
        const int r1g = r0g + 8;
        const float av0 = asq[r0g];
        const float av1 = asq[r1g];
#pragma unroll
        for (int nt = 0; nt < 4; nt++) {
            const int cg = nW + nt * 8 + lc;
            const float bq0 = bsq[cg], bq1 = bsq[cg + 1];
            const float bi0 = bias[cg], bi1 = bias[cg + 1];
            float d00 = acc[mt][nt][0], d01 = acc[mt][nt][1];
            float d10 = acc[mt][nt][2], d11 = acc[mt][nt][3];
            float2 o0, o1;
            o0.x = __fdividef(d00 * d00, av0 + bq0 - 2.f * d00 + EPS_) * scale + bi0;
            o0.y = __fdividef(d01 * d01, av0 + bq1 - 2.f * d01 + EPS_) * scale + bi1;
            o1.x = __fdividef(d10 * d10, av1 + bq0 - 2.f * d10 + EPS_) * scale + bi0;
            o1.y = __fdividef(d11 * d11, av1 + bq1 - 2.f * d11 + EPS_) * scale + bi1;
            *(float2*)(Cout + (size_t)r0g * N + cg) = o0;
            *(float2*)(Cout + (size_t)r1g * N + cg) = o1;
        }
    }
}

// ======================= GEMM1: yat + RoPE + fp16 split fused epilogue =======================
// Writes Q [B,H,T,D] fp16 hi (pre-scaled), K hi/lo [B,H,T,D], V^T hi/lo [B,H,D,T].
__global__ void __launch_bounds__(256, 2) yat_rope_gemm_kernel(
    const __half* __restrict__ Ah,
    const __half* __restrict__ BhT, const __half* __restrict__ BlT,
    const float* __restrict__ asq, const float* __restrict__ bsq,
    const float* __restrict__ bias,
    __half* __restrict__ Qh,
    __half* __restrict__ Kh, __half* __restrict__ Kl,
    __half* __restrict__ VTh, __half* __restrict__ VTl,
    float scale)
{
    extern __shared__ char smem[];
    const uint32_t sb = smem_u32(smem);
    const int K = C_, N = N1_;

    const int tid = threadIdx.x;
    const int wid = tid >> 5, lane = tid & 31;
    const int warpM = wid >> 2;
    const int warpN = wid & 3;
    const int rowBase = blockIdx.y * 128;
    const int colBase = blockIdx.x * 128;
    const int NC = K >> 5;

    const __half* Agh = Ah + (size_t)rowBase * K;
    const __half* Bgh = BhT + (size_t)colBase * K;
    const __half* Bgl = BlT + (size_t)colBase * K;

    const uint32_t aSel = (uint32_t)(lane & 15) * ROWB + (uint32_t)(lane >> 4) * 16;
    const uint32_t bSel = (uint32_t)(((lane >> 4) & 1) * 8 + (lane & 7)) * ROWB +
                          (uint32_t)((lane >> 3) & 1) * 16;

    float acc[4][4][4];
#pragma unroll
    for (int i = 0; i < 4; i++)
#pragma unroll
        for (int j = 0; j < 4; j++)
#pragma unroll
            for (int e = 0; e < 4; e++) acc[i][j][e] = 0.f;

    load_stage(sb, Agh, Bgh, Bgl, 0, K, tid);
    asm volatile("cp.async.commit_group;" ::: "memory");

    for (int c = 0; c < NC; c++) {
        if (c + 1 < NC) {
            load_stage(sb + (uint32_t)((c + 1) & 1) * STAGEB,
                       Agh, Bgh, Bgl, (c + 1) << 5, K, tid);
            asm volatile("cp.async.commit_group;" ::: "memory");
            asm volatile("cp.async.wait_group 1;" ::: "memory");
        } else {
            asm volatile("cp.async.wait_group 0;" ::: "memory");
        }
        __syncthreads();
        gemm_chunk(sb + (uint32_t)(c & 1) * STAGEB, aSel, bSel, warpM, warpN, acc);
        __syncthreads();
    }

    // ---- epilogue: yat + bias, then RoPE/split per segment ----
    const int lr = lane >> 2, lc = (lane & 3) * 2;
    const int mW = rowBase + warpM * 64;
    const int nW = colBase + warpN * 32;
    const int seg = colBase >> 10;                 // 0=Q, 1=K, 2=V
    const float QSC = 0.125f * 1.4426950408889634f;

    float fr[4];
#pragma unroll
    for (int nt = 0; nt < 4; nt++) {
        int cg = nW + nt * 8 + lc;
        int i = (cg & 63) >> 1;
        fr[nt] = powf(10000.0f, -(float)i / 32.0f);
    }

#pragma unroll
    for (int mt = 0; mt < 4; mt++) {
        const int r0g = mW + mt * 16 + lr;
        const int r1g = r0g + 8;
        const float av0 = asq[r0g];
        const float av1 = asq[r1g];
        const int b0 = r0g >> 11, t0 = r0g & 2047;
        const int b1 = r1g >> 11, t1 = r1g & 2047;
#pragma unroll
        for (int nt = 0; nt < 4; nt++) {
            const int cg = nW + nt * 8 + lc;
            const float bq0 = bsq[cg], bq1 = bsq[cg + 1];
            const float bi0 = bias[cg], bi1 = bias[cg + 1];
            float d00 = acc[mt][nt][0], d01 = acc[mt][nt][1];
            float d10 = acc[mt][nt][2], d11 = acc[mt][nt][3];
            float y00 = __fdividef(d00 * d00, av0 + bq0 - 2.f * d00 + EPS_) * scale + bi0;
            float y01 = __fdividef(d01 * d01, av0 + bq1 - 2.f * d01 + EPS_) * scale + bi1;
            float y10 = __fdividef(d10 * d10, av1 + bq0 - 2.f * d10 + EPS_) * scale + bi0;
            float y11 = __fdividef(d11 * d11, av1 + bq1 - 2.f * d11 + EPS_) * scale + bi1;

            const int colh = cg & 1023;
            const int h = colh >> 6;
            const int d = colh & 63;

            if (seg < 2) {
                float s0, c0, s1, c1;
                sincosf((float)t0 * fr[nt], &s0, &c0);
                sincosf((float)t1 * fr[nt], &s1, &c1);
                float a0 = y00 * c0 - y01 * s0;
                float a1 = y01 * c0 + y00 * s0;
                float e0 = y10 * c1 - y11 * s1;
                float e1 = y11 * c1 + y10 * s1;
                size_t o0 = ((size_t)(b0 * H_ + h) * T_ + t0) * D_ + d;
                size_t o1 = ((size_t)(b1 * H_ + h) * T_ + t1) * D_ + d;
                if (seg == 0) {
                    *(__half2*)(Qh + o0) = __floats2half2_rn(a0 * QSC, a1 * QSC);
                    *(__half2*)(Qh + o1) = __floats2half2_rn(e0 * QSC, e1 * QSC);
                } else {
                    __half2 hh = __floats2half2_rn(a0, a1);
                    __half2 ll;
                    ll.x = __float2half_rn(a0 - __half2float(hh.x));
                    ll.y = __float2half_rn(a1 - __half2float(hh.y));
                    *(__half2*)(Kh + o0) = hh;
                    *(__half2*)(Kl + o0) = ll;
                    hh = __floats2half2_rn(e0, e1);
                    ll.x = __float2half_rn(e0 - __half2float(hh.x));
                    ll.y = __float2half_rn(e1 - __half2float(hh.y));
                    *(__half2*)(Kh + o1) = hh;
                    *(__half2*)(Kl + o1) = ll;
                }
            } else {
                size_t ov0 = ((size_t)(b0 * H_ + h) * D_ + d) * T_ + t0;
                size_t ov1 = ((size_t)(b1 * H_ + h) * D_ + d) * T_ + t1;
                __half vh;
                vh = __float2half_rn(y00);
                VTh[ov0] = vh; VTl[ov0] = __float2half_rn(y00 - __half2float(vh));
                vh = __float2half_rn(y01);
                VTh[ov0 + T_] = vh; VTl[ov0 + T_] = __float2half_rn(y01 - __half2float(vh));
                vh = __float2half_rn(y10);
                VTh[ov1] = vh; VTl[ov1] = __float2half_rn(y10 - __half2float(vh));
                vh = __float2half_rn(y11);
                VTh[ov1 + T_] = vh; VTl[ov1 + T_] = __float2half_rn(y11 - __half2float(vh));
            }
        }
    }
}

// ======================= tensor-core causal flash attention (fp16x2) =======================
// BQ=128, BKV=64, 8 warps x 16 q-rows. S = Qh*(Kh+Kl), O = Ph*(Vh+Vl).
#define AROWB 144
#define QTILE (128 * AROWB)
#define KVTILE (64 * AROWB)
#define SQH_OFF 0
#define STG_OFF QTILE
#define STGSZ  (4 * KVTILE)
#define ST_KH 0
#define ST_KL (1 * KVTILE)
#define ST_VH (2 * KVTILE)
#define ST_VL (3 * KVTILE)
#define ATTN_SMEM (QTILE + 2 * STGSZ)   // 92160

__device__ __forceinline__ void attn_load_stage(
    uint32_t st, const __half* kh, const __half* kl,
    const __half* vth, const __half* vtl,
    size_t bhT, size_t bhD, int k0, int tid)
{
#pragma unroll
    for (int it = 0; it < 2; it++) {
        int idx = it * 256 + tid;
        int row = idx >> 3;
        int ch = (idx & 7) * 16;
        uint32_t dst = (uint32_t)row * AROWB + ch;
        cp16(st + ST_KH + dst, (const char*)(kh + (bhT + k0 + row) * D_) + ch);
        cp16(st + ST_KL + dst, (const char*)(kl + (bhT + k0 + row) * D_) + ch);
        cp16(st + ST_VH + dst, (const char*)(vth + (bhD + row) * T_ + k0) + ch);
        cp16(st + ST_VL + dst, (const char*)(vtl + (bhD + row) * T_ + k0) + ch);
    }
}

__global__ void __launch_bounds__(256, 2) attn_mma_kernel(
    const __half* __restrict__ qh,
    const __half* __restrict__ kh, const __half* __restrict__ kl,
    const __half* __restrict__ vth, const __half* __restrict__ vtl,
    __half* __restrict__ Oh, float* __restrict__ osq)
{
    extern __shared__ char smem[];
    const uint32_t sb = smem_u32(smem);

    const int bh = blockIdx.y;
    const int qx = 15 - (int)blockIdx.x;
    const int q0 = qx * 128;
    const size_t bhT = (size_t)bh * T_;
    const size_t bhD = (size_t)bh * D_;

    const int tid = threadIdx.x;
    const int wid = tid >> 5, lane = tid & 31;
    const int lr = lane >> 2, c2 = (lane & 3) * 2;

    const uint32_t aSel = (uint32_t)(lane & 15) * AROWB + (uint32_t)(lane >> 4) * 16;
    const uint32_t bSel = (uint32_t)(((lane >> 4) & 1) * 8 + (lane & 7)) * AROWB +
                          (uint32_t)((lane >> 3) & 1) * 16;

    // ---- load Q tile: 128 rows x 128 B (8 x 16B chunks per row) ----
#pragma unroll
    for (int it = 0; it < 4; it++) {
        int idx = it * 256 + tid;          // 0..1023
        int row = idx >> 3;                // 0..127
        int ch = (idx & 7) * 16;           // 8 chunks x 16B = 128B
        uint32_t dst = (uint32_t)row * AROWB + ch;
        cp16(sb + SQH_OFF + dst, (const char*)(qh + (bhT + q0 + row) * D_) + ch);
    }
    asm volatile("cp.async.commit_group;" ::: "memory");

    attn_load_stage(sb + STG_OFF, kh, kl, vth, vtl, bhT, bhD, 0, tid);
    asm volatile("cp.async.commit_group;" ::: "memory");

    asm volatile("cp.async.wait_group 1;" ::: "memory");
    __syncthreads();
    uint32_t qhf[4][4];
    {
        const uint32_t aQ = sb + SQH_OFF + (uint32_t)wid * 16 * AROWB + aSel;
#pragma unroll
        for (int ks = 0; ks < 4; ks++)
            LDSM4(qhf[ks][0], qhf[ks][1], qhf[ks][2], qhf[ks][3], aQ + ks * 32);
    }

    float O[8][4];
#pragma unroll
    for (int j = 0; j < 8; j++)
#pragma unroll
        for (int e = 0; e < 4; e++) O[j][e] = 0.f;
    float mrow[2] = {-1e30f, -1e30f};
    float lrow[2] = {0.f, 0.f};

    const int ntiles = 2 * qx + 2;
    const int rowg0 = q0 + wid * 16 + lr;

    for (int kt = 0; kt < ntiles; kt++) {
        const uint32_t st = sb + STG_OFF + (uint32_t)(kt & 1) * STGSZ;
        if (kt + 1 < ntiles) {
            attn_load_stage(sb + STG_OFF + (uint32_t)((kt + 1) & 1) * STGSZ,
                            kh, kl, vth, vtl, bhT, bhD, (kt + 1) * 64, tid);
            asm volatile("cp.async.commit_group;" ::: "memory");
            asm volatile("cp.async.wait_group 1;" ::: "memory");
        } else {
            asm volatile("cp.async.wait_group 0;" ::: "memory");
        }
        __syncthreads();

        float S[8][4];
#pragma unroll
        for (int j = 0; j < 8; j++)
#pragma unroll
            for (int e = 0; e < 4; e++) S[j][e] = 0.f;

#pragma unroll
        for (int ks = 0; ks < 4; ks++) {
#pragma unroll
            for (int np = 0; np < 4; np++) {
                uint32_t r0, r1, r2, r3;
                LDSM4(r0, r1, r2, r3, st + ST_KH + np * (16 * AROWB) + bSel + ks * 32);
                uint32_t bh0[2] = {r0, r1}, bh1[2] = {r2, r3};
                MMA16816(S[np * 2 + 0], qhf[ks], bh0);
                MMA16816(S[np * 2 + 1], qhf[ks], bh1);
                LDSM4(r0, r1, r2, r3, st + ST_KL + np * (16 * AROWB) + bSel + ks * 32);
                uint32_t bl0[2] = {r0, r1}, bl1[2] = {r2, r3};
                MMA16816(S[np * 2 + 0], qhf[ks], bl0);
                MMA16816(S[np * 2 + 1], qhf[ks], bl1);
            }
        }

        const int k0 = kt * 64;
        if (kt >= 2 * qx) {
#pragma unroll
            for (int j = 0; j < 8; j++) {
                int col = k0 + j * 8 + c2;
                if (col > rowg0)     S[j][0] = -1e30f;
                if (col + 1 > rowg0) S[j][1] = -1e30f;
                if (col > rowg0 + 8)     S[j][2] = -1e30f;
                if (col + 1 > rowg0 + 8) S[j][3] = -1e30f;
            }
        }

#pragma unroll
        for (int i = 0; i < 2; i++) {
            float mx = -1e30f;
#pragma unroll
            for (int j = 0; j < 8; j++)
                mx = fmaxf(mx, fmaxf(S[j][2 * i], S[j][2 * i + 1]));
            mx = fmaxf(mx, __shfl_xor_sync(0xffffffffu, mx, 1));
            mx = fmaxf(mx, __shfl_xor_sync(0xffffffffu, mx, 2));
            float mn = fmaxf(mrow[i], mx);
            float cf = fast_exp2(mrow[i] - mn);
            mrow[i] = mn;
            float rs = 0.f;
#pragma unroll
            for (int j = 0; j < 8; j++) {
                float p0 = fast_exp2(S[j][2 * i] - mn);
                float p1 = fast_exp2(S[j][2 * i + 1] - mn);
                S[j][2 * i] = p0; S[j][2 * i + 1] = p1;
                rs += p0 + p1;
            }
            rs += __shfl_xor_sync(0xffffffffu, rs, 1);
            rs += __shfl_xor_sync(0xffffffffu, rs, 2);
            lrow[i] = lrow[i] * cf + rs;
#pragma unroll
            for (int j = 0; j < 8; j++) { O[j][2 * i] *= cf; O[j][2 * i + 1] *= cf; }
        }

        // ---- pack P into A fragments (hi only) ----
        uint32_t PH[4][4];
#pragma unroll
        for (int t = 0; t < 4; t++) {
#pragma unroll
            for (int h2 = 0; h2 < 2; h2++) {
                int j = 2 * t + h2;
                PH[t][h2 * 2 + 0] = pack_f16(S[j][0], S[j][1]);
                PH[t][h2 * 2 + 1] = pack_f16(S[j][2], S[j][3]);
            }
        }

#pragma unroll
        for (int t = 0; t < 4; t++) {
#pragma unroll
            for (int dn = 0; dn < 4; dn++) {
                uint32_t r0, r1, r2, r3;
                LDSM4(r0, r1, r2, r3, st + ST_VH + dn * (16 * AROWB) + bSel + t * 32);
                uint32_t vh0[2] = {r0, r1}, vh1[2] = {r2, r3};
                MMA16816(O[dn * 2 + 0], PH[t], vh0);
                MMA16816(O[dn * 2 + 1], PH[t], vh1);
                LDSM4(r0, r1, r2, r3, st + ST_VL + dn * (16 * AROWB) + bSel + t * 32);
                uint32_t vl0[2] = {r0, r1}, vl1[2] = {r2, r3};
                MMA16816(O[dn * 2 + 0], PH[t], vl0);
                MMA16816(O[dn * 2 + 1], PH[t], vl1);
            }
        }
        __syncthreads();
    }

    // ---- fused epilogue: normalize, fp16 write + osq atomics ----
    const int b = bh >> 4, h = bh & 15;
    const float inv0 = 1.f / lrow[0], inv1 = 1.f / lrow[1];
    const size_t m0 = (size_t)(b * T_ + rowg0);
    const size_t m1 = m0 + 8;
    __half* oh0 = Oh + m0 * C_ + h * 64;
    __half* oh1 = Oh + m1 * C_ + h * 64;
    float sq0 = 0.f, sq1 = 0.f;
#pragma unroll
    for (int j = 0; j < 8; j++) {
        float y0 = O[j][0] * inv0, y1 = O[j][1] * inv0;
        float y2 = O[j][2] * inv1, y3 = O[j][3] * inv1;
        sq0 += y0 * y0 + y1 * y1;
        sq1 += y2 * y2 + y3 * y3;
        *(__half2*)(oh0 + j * 8 + c2) = __floats2half2_rn(y0, y1);
        *(__half2*)(oh1 + j * 8 + c2) = __floats2half2_rn(y2, y3);
    }
    sq0 += __shfl_xor_sync(0xffffffffu, sq0, 1);
    sq0 += __shfl_xor_sync(0xffffffffu, sq0, 2);
    sq1 += __shfl_xor_sync(0xffffffffu, sq1, 1);
    sq1 += __shfl_xor_sync(0xffffffffu, sq1, 2);
    if ((lane & 3) == 0) {
        atomicAdd(osq + m0, sq0);
        atomicAdd(osq + m1, sq1);
    }
}

// ---------------- launcher ----------------
extern "C" void kernel_launch(void* const* d_in, const int* in_sizes, int n_in,
                              void* d_out, int out_size)
{
    (void)in_sizes; (void)n_in; (void)out_size;
    const float* x      = (const float*)d_in[0];
    const float* w_attn = (const float*)d_in[2];
    const float* b_attn = (const float*)d_in[3];
    const float* w_proj = (const float*)d_in[4];
    const float* b_proj = (const float*)d_in[5];
    float* out = (float*)d_out;

    float *xsq, *osq, *wsq1, *wsq2;
    __half *xh, *ah, *w1h, *w1l, *w2h, *w2l;
    __half *qbh, *kbh, *kbl, *vth, *vtl;
    cudaGetSymbolAddress((void**)&xsq,  g_xsq);
    cudaGetSymbolAddress((void**)&osq,  g_osq);
    cudaGetSymbolAddress((void**)&wsq1, g_wsq1);
    cudaGetSymbolAddress((void**)&wsq2, g_wsq2);
    cudaGetSymbolAddress((void**)&xh,   g_xh);
    cudaGetSymbolAddress((void**)&ah,   g_ah);
    cudaGetSymbolAddress((void**)&w1h,  g_w1h);
    cudaGetSymbolAddress((void**)&w1l,  g_w1l);
    cudaGetSymbolAddress((void**)&w2h,  g_w2h);
    cudaGetSymbolAddress((void**)&w2l,  g_w2l);
    cudaGetSymbolAddress((void**)&qbh,  g_qbh);
    cudaGetSymbolAddress((void**)&kbh,  g_kbh);
    cudaGetSymbolAddress((void**)&kbl,  g_kbl);
    cudaGetSymbolAddress((void**)&vth,  g_vth);
    cudaGetSymbolAddress((void**)&vtl,  g_vtl);

    const float scale1 = (float)(sqrt(3072.0) / log1p(3072.0));
    const float scale2 = (float)(sqrt(1024.0) / log1p(1024.0));

    cudaFuncSetAttribute(yat_mma_gemm_kernel,
                         cudaFuncAttributeMaxDynamicSharedMemorySize, MMA_SMEM);
    cudaFuncSetAttribute(yat_rope_gemm_kernel,
                         cudaFuncAttributeMaxDynamicSharedMemorySize, MMA_SMEM);
    cudaFuncSetAttribute(attn_mma_kernel,
                         cudaFuncAttributeMaxDynamicSharedMemorySize, ATTN_SMEM);

    prep_x_kernel<<<M_, 256>>>(x, xsq, xh);
    colsq_kernel<<<N1_ / 64, 256>>>(w_attn, wsq1, C_, N1_);
    colsq_kernel<<<C_ / 64, 256>>>(w_proj, wsq2, C_, C_);
    wconv_kernel<<<dim3(N1_ / 32, C_ / 32), 256>>>(w_attn, w1h, w1l, C_, N1_);
    wconv_kernel<<<dim3(C_ / 32, C_ / 32), 256>>>(w_proj, w2h, w2l, C_, C_);

    cudaMemsetAsync(osq, 0, M_ * sizeof(float));

    yat_rope_gemm_kernel<<<dim3(N1_ / 128, M_ / 128), 256, MMA_SMEM>>>(
        xh, w1h, w1l, xsq, wsq1, b_attn,
        qbh, kbh, kbl, vth, vtl, scale1);

    attn_mma_kernel<<<dim3(T_ / 128, B_ * H_), 256, ATTN_SMEM>>>(
        qbh, kbh, kbl, vth, vtl, ah, osq);

    yat_mma_gemm_kernel<<<dim3(C_ / 128, M_ / 128), 256, MMA_SMEM>>>(
        ah, w2h, w2l, osq, wsq2, b_proj, out, M_, C_, C_, scale2);
}

// round 9
// speedup vs baseline: 24.2836x; 1.3024x over previous
#include <cuda_runtime.h>
#include <cuda_fp16.h>
#include <math.h>
#include <stdint.h>

#define B_   2
#define T_   2048
#define C_   1024
#define H_   16
#define D_   64
#define M_   4096          // B_*T_
#define N1_  3072          // 3*C_
#define EPS_ 1e-6f

// ---------------- scratch (device globals; no allocation allowed) ----------------
__device__ float g_xsq[M_];
__device__ float g_osq[M_];
__device__ float g_wsq1[N1_];
__device__ float g_wsq2[C_];
// fp16 operands (A sides: hi only; B sides: hi+lo)
__device__ __half g_xh[(size_t)M_ * C_];
__device__ __half g_ah[(size_t)M_ * C_];
__device__ __half g_w1h[(size_t)N1_ * C_];  // [N,K] transposed
__device__ __half g_w1l[(size_t)N1_ * C_];
__device__ __half g_w2h[(size_t)C_ * C_];
__device__ __half g_w2l[(size_t)C_ * C_];
// attention operands (pure fp16, no compensation)
__device__ __half g_qbh[(size_t)B_ * H_ * T_ * D_];  // [B,H,T,D] (scaled)
__device__ __half g_kbh[(size_t)B_ * H_ * T_ * D_];  // [B,H,T,D]
__device__ __half g_vth[(size_t)B_ * H_ * D_ * T_];  // [B,H,D,T]

__device__ __forceinline__ float fast_exp2(float x) {
    float r;
    asm("ex2.approx.ftz.f32 %0, %1;" : "=f"(r) : "f"(x));
    return r;
}

__device__ __forceinline__ uint32_t smem_u32(const void* p) {
    return (uint32_t)__cvta_generic_to_shared(p);
}

__device__ __forceinline__ uint32_t pack_f16(float lo, float hi) {
    uint32_t r;
    asm("cvt.rn.f16x2.f32 %0, %1, %2;" : "=r"(r) : "f"(hi), "f"(lo));
    return r;
}

// ======================= small helper kernels =======================

// fused: row sum-of-squares + fp32 -> fp16 of X (one read pass)
__global__ void prep_x_kernel(const float* __restrict__ X, float* __restrict__ xsq,
                              __half* __restrict__ Xh)
{
    int m = blockIdx.x;
    int tid = threadIdx.x;
    size_t i = (size_t)m * C_ + tid * 4;
    float4 v = *(const float4*)(X + i);
    *(__half2*)(Xh + i)     = __floats2half2_rn(v.x, v.y);
    *(__half2*)(Xh + i + 2) = __floats2half2_rn(v.z, v.w);

    float s = v.x * v.x + v.y * v.y + v.z * v.z + v.w * v.w;
#pragma unroll
    for (int o = 16; o; o >>= 1) s += __shfl_xor_sync(0xffffffffu, s, o);
    __shared__ float red[8];
    if ((tid & 31) == 0) red[tid >> 5] = s;
    __syncthreads();
    if (tid == 0) {
        float t = 0.f;
#pragma unroll
        for (int j = 0; j < 8; j++) t += red[j];
        xsq[m] = t;
    }
}

// W[K][N] fp32 -> WT[N][K] fp16 hi/lo (32x32 smem transpose),
// fused column sum-of-squares via warp reduce + atomicAdd (wsq pre-zeroed).
__global__ void wconv_kernel(const float* __restrict__ W,
                             __half* __restrict__ WhT,
                             __half* __restrict__ WlT,
                             float* __restrict__ wsq,
                             int K, int N)
{
    __shared__ float tile[32][33];
    int bx = blockIdx.x, by = blockIdx.y;
    int tx = threadIdx.x & 31, ty = threadIdx.x >> 5;
#pragma unroll
    for (int i = ty; i < 32; i += 8)
        tile[i][tx] = W[(size_t)(by * 32 + i) * N + bx * 32 + tx];
    __syncthreads();
#pragma unroll
    for (int i = ty; i < 32; i += 8) {
        int n = bx * 32 + i, k = by * 32 + tx;
        float v = tile[tx][i];
        __half h = __float2half_rn(v);
        WhT[(size_t)n * K + k] = h;
        WlT[(size_t)n * K + k] = __float2half_rn(v - __half2float(h));
        float s = v * v;
#pragma unroll
        for (int o = 16; o; o >>= 1) s += __shfl_xor_sync(0xffffffffu, s, o);
        if (tx == 0) atomicAdd(wsq + n, s);
    }
}

// ======================= mma.sync helpers =======================

#define LDSM4(r0, r1, r2, r3, addr) \
    asm volatile("ldmatrix.sync.aligned.m8n8.x4.shared.b16 {%0,%1,%2,%3}, [%4];" \
                 : "=r"(r0), "=r"(r1), "=r"(r2), "=r"(r3) : "r"(addr))

#define MMA16816(d, a, b) \
    asm volatile("mma.sync.aligned.m16n8k16.row.col.f32.f16.f16.f32 " \
                 "{%0,%1,%2,%3}, {%4,%5,%6,%7}, {%8,%9}, {%0,%1,%2,%3};" \
                 : "+f"((d)[0]), "+f"((d)[1]), "+f"((d)[2]), "+f"((d)[3]) \
                 : "r"((a)[0]), "r"((a)[1]), "r"((a)[2]), "r"((a)[3]), \
                   "r"((b)[0]), "r"((b)[1]))

__device__ __forceinline__ void cp16(uint32_t dst, const void* src) {
    asm volatile("cp.async.cg.shared.global [%0], [%1], 16;" :: "r"(dst), "l"(src));
}

// ======================= shared GEMM core (fp16x2, 2-pass) =======================
#define ROWB   80
#define TILEB  (128 * ROWB)
#define OFF_A  0
#define OFF_BH (1 * TILEB)
#define OFF_BL (2 * TILEB)
#define STAGEB (3 * TILEB)         // 30720
#define MMA_SMEM (2 * STAGEB)      // 61440

__device__ __forceinline__ void load_stage(
    uint32_t st, const __half* Ag,
    const __half* Bgh, const __half* Bgl,
    int k0, int K, int tid)
{
#pragma unroll
    for (int it = 0; it < 2; it++) {
        int idx = it * 256 + tid;
        int row = idx >> 2;
        int ch = (idx & 3) * 16;
        uint32_t dst = (uint32_t)row * ROWB + ch;
        size_t srcel = (size_t)row * K + k0;
        cp16(st + OFF_A + dst,  (const char*)(Ag + srcel) + ch);
        cp16(st + OFF_BH + dst, (const char*)(Bgh + srcel) + ch);
        cp16(st + OFF_BL + dst, (const char*)(Bgl + srcel) + ch);
    }
}

// 2-pass mainloop over one K-chunk stage: acc += Ah*Bh + Ah*Bl
__device__ __forceinline__ void gemm_chunk(
    uint32_t st, uint32_t aSel, uint32_t bSel, int warpM, int warpN,
    float acc[4][4][4])
{
#pragma unroll
    for (int ks = 0; ks < 2; ks++) {
        const uint32_t aB  = st + OFF_A  + (uint32_t)warpM * 64 * ROWB + aSel + ks * 32;
        const uint32_t bHB = st + OFF_BH + (uint32_t)warpN * 32 * ROWB + bSel + ks * 32;
        const uint32_t bLB = st + OFF_BL + (uint32_t)warpN * 32 * ROWB + bSel + ks * 32;
        uint32_t ah4[4][4];
#pragma unroll
        for (int mt = 0; mt < 4; mt++)
            LDSM4(ah4[mt][0], ah4[mt][1], ah4[mt][2], ah4[mt][3],
                  aB + mt * (16 * ROWB));
        uint32_t bh[4][2], bl[4][2];
#pragma unroll
        for (int nt2 = 0; nt2 < 2; nt2++) {
            uint32_t r0, r1, r2, r3;
            LDSM4(r0, r1, r2, r3, bHB + nt2 * (16 * ROWB));
            bh[nt2 * 2 + 0][0] = r0; bh[nt2 * 2 + 0][1] = r1;
            bh[nt2 * 2 + 1][0] = r2; bh[nt2 * 2 + 1][1] = r3;
            LDSM4(r0, r1, r2, r3, bLB + nt2 * (16 * ROWB));
            bl[nt2 * 2 + 0][0] = r0; bl[nt2 * 2 + 0][1] = r1;
            bl[nt2 * 2 + 1][0] = r2; bl[nt2 * 2 + 1][1] = r3;
        }
#pragma unroll
        for (int mt = 0; mt < 4; mt++)
#pragma unroll
            for (int nt = 0; nt < 4; nt++)
                MMA16816(acc[mt][nt], ah4[mt], bh[nt]);
#pragma unroll
        for (int mt = 0; mt < 4; mt++)
#pragma unroll
            for (int nt = 0; nt < 4; nt++)
                MMA16816(acc[mt][nt], ah4[mt], bl[nt]);
    }
}

// ======================= GEMM2: yat -> fp32 out =======================
__global__ void __launch_bounds__(256, 2) yat_mma_gemm_kernel(
    const __half* __restrict__ Ah,
    const __half* __restrict__ BhT, const __half* __restrict__ BlT,
    const float* __restrict__ asq, const float* __restrict__ bsq,
    const float* __restrict__ bias, float* __restrict__ Cout,
    int M, int N, int K, float scale)
{
    extern __shared__ char smem[];
    const uint32_t sb = smem_u32(smem);

    const int tid = threadIdx.x;
    const int wid = tid >> 5, lane = tid & 31;
    const int warpM = wid >> 2;
    const int warpN = wid & 3;
    const int rowBase = blockIdx.y * 128;
    const int colBase = blockIdx.x * 128;
    const int NC = K >> 5;

    const __half* Agh = Ah + (size_t)rowBase * K;
    const __half* Bgh = BhT + (size_t)colBase * K;
    const __half* Bgl = BlT + (size_t)colBase * K;

    const uint32_t aSel = (uint32_t)(lane & 15) * ROWB + (uint32_t)(lane >> 4) * 16;
    const uint32_t bSel = (uint32_t)(((lane >> 4) & 1) * 8 + (lane & 7)) * ROWB +
                          (uint32_t)((lane >> 3) & 1) * 16;

    float acc[4][4][4];
#pragma unroll
    for (int i = 0; i < 4; i++)
#pragma unroll
        for (int j = 0; j < 4; j++)
#pragma unroll
            for (int e = 0; e < 4; e++) acc[i][j][e] = 0.f;

    load_stage(sb, Agh, Bgh, Bgl, 0, K, tid);
    asm volatile("cp.async.commit_group;" ::: "memory");

    for (int c = 0; c < NC; c++) {
        if (c + 1 < NC) {
            load_stage(sb + (uint32_t)((c + 1) & 1) * STAGEB,
                       Agh, Bgh, Bgl, (c + 1) << 5, K, tid);
            asm volatile("cp.async.commit_group;" ::: "memory");
            asm volatile("cp.async.wait_group 1;" ::: "memory");
        } else {
            asm volatile("cp.async.wait_group 0;" ::: "memory");
        }
        __syncthreads();
        gemm_chunk(sb + (uint32_t)(c & 1) * STAGEB, aSel, bSel, warpM, warpN, acc);
        __syncthreads();
    }

    const int lr = lane >> 2, lc = (lane & 3) * 2;
    const int mW = rowBase + warpM * 64;
    const int nW = colBase + warpN * 32;
#pragma unroll
    for (int mt = 0; mt < 4; mt++) {
        const int r0g = mW + mt * 16 + lr;
        const int r1g = r0g + 8;
        const float av0 = asq[r0g];
        const float av1 = asq[r1g];
#pragma unroll
        for (int nt = 0; nt < 4; nt++) {
            const int cg = nW + nt * 8 + lc;
            const float bq0 = bsq[cg], bq1 = bsq[cg + 1];
            const float bi0 = bias[cg], bi1 = bias[cg + 1];
            float d00 = acc[mt][nt][0], d01 = acc[mt][nt][1];
            float d10 = acc[mt][nt][2], d11 = acc[mt][nt][3];
            float2 o0, o1;
            o0.x = __fdividef(d00 * d00, av0 + bq0 - 2.f * d00 + EPS_) * scale + bi0;
            o0.y = __fdividef(d01 * d01, av0 + bq1 - 2.f * d01 + EPS_) * scale + bi1;
            o1.x = __fdividef(d10 * d10, av1 + bq0 - 2.f * d10 + EPS_) * scale + bi0;
            o1.y = __fdividef(d11 * d11, av1 + bq1 - 2.f * d11 + EPS_) * scale + bi1;
            *(float2*)(Cout + (size_t)r0g * N + cg) = o0;
            *(float2*)(Cout + (size_t)r1g * N + cg) = o1;
        }
    }
}

// ======================= GEMM1: yat + RoPE + fp16 fused epilogue =======================
// Writes Q [B,H,T,D] fp16 (pre-scaled), K [B,H,T,D] fp16, V^T [B,H,D,T] fp16.
__global__ void __launch_bounds__(256, 2) yat_rope_gemm_kernel(
    const __half* __restrict__ Ah,
    const __half* __restrict__ BhT, const __half* __restrict__ BlT,
    const float* __restrict__ asq, const float* __restrict__ bsq,
    const float* __restrict__ bias,
    __half* __restrict__ Qh, __half* __restrict__ Kh,
    __half* __restrict__ VTh,
    float scale)
{
    extern __shared__ char smem[];
    const uint32_t sb = smem_u32(smem);
    const int K = C_, N = N1_;

    const int tid = threadIdx.x;
    const int wid = tid >> 5, lane = tid & 31;
    const int warpM = wid >> 2;
    const int warpN = wid & 3;
    const int rowBase = blockIdx.y * 128;
    const int colBase = blockIdx.x * 128;
    const int NC = K >> 5;

    const __half* Agh = Ah + (size_t)rowBase * K;
    const __half* Bgh = BhT + (size_t)colBase * K;
    const __half* Bgl = BlT + (size_t)colBase * K;

    const uint32_t aSel = (uint32_t)(lane & 15) * ROWB + (uint32_t)(lane >> 4) * 16;
    const uint32_t bSel = (uint32_t)(((lane >> 4) & 1) * 8 + (lane & 7)) * ROWB +
                          (uint32_t)((lane >> 3) & 1) * 16;

    float acc[4][4][4];
#pragma unroll
    for (int i = 0; i < 4; i++)
#pragma unroll
        for (int j = 0; j < 4; j++)
#pragma unroll
            for (int e = 0; e < 4; e++) acc[i][j][e] = 0.f;

    load_stage(sb, Agh, Bgh, Bgl, 0, K, tid);
    asm volatile("cp.async.commit_group;" ::: "memory");

    for (int c = 0; c < NC; c++) {
        if (c + 1 < NC) {
            load_stage(sb + (uint32_t)((c + 1) & 1) * STAGEB,
                       Agh, Bgh, Bgl, (c + 1) << 5, K, tid);
            asm volatile("cp.async.commit_group;" ::: "memory");
            asm volatile("cp.async.wait_group 1;" ::: "memory");
        } else {
            asm volatile("cp.async.wait_group 0;" ::: "memory");
        }
        __syncthreads();
        gemm_chunk(sb + (uint32_t)(c & 1) * STAGEB, aSel, bSel, warpM, warpN, acc);
        __syncthreads();
    }

    // ---- epilogue: yat + bias, then RoPE/split per segment ----
    const int lr = lane >> 2, lc = (lane & 3) * 2;
    const int mW = rowBase + warpM * 64;
    const int nW = colBase + warpN * 32;
    const int seg = colBase >> 10;                 // 0=Q, 1=K, 2=V
    const float QSC = 0.125f * 1.4426950408889634f;

    float fr[4];
#pragma unroll
    for (int nt = 0; nt < 4; nt++) {
        int cg = nW + nt * 8 + lc;
        int i = (cg & 63) >> 1;
        fr[nt] = powf(10000.0f, -(float)i / 32.0f);
    }

#pragma unroll
    for (int mt = 0; mt < 4; mt++) {
        const int r0g = mW + mt * 16 + lr;
        const int r1g = r0g + 8;
        const float av0 = asq[r0g];
        const float av1 = asq[r1g];
        const int b0 = r0g >> 11, t0 = r0g & 2047;
        const int b1 = r1g >> 11, t1 = r1g & 2047;
#pragma unroll
        for (int nt = 0; nt < 4; nt++) {
            const int cg = nW + nt * 8 + lc;
            const float bq0 = bsq[cg], bq1 = bsq[cg + 1];
            const float bi0 = bias[cg], bi1 = bias[cg + 1];
            float d00 = acc[mt][nt][0], d01 = acc[mt][nt][1];
            float d10 = acc[mt][nt][2], d11 = acc[mt][nt][3];
            float y00 = __fdividef(d00 * d00, av0 + bq0 - 2.f * d00 + EPS_) * scale + bi0;
            float y01 = __fdividef(d01 * d01, av0 + bq1 - 2.f * d01 + EPS_) * scale + bi1;
            float y10 = __fdividef(d10 * d10, av1 + bq0 - 2.f * d10 + EPS_) * scale + bi0;
            float y11 = __fdividef(d11 * d11, av1 + bq1 - 2.f * d11 + EPS_) * scale + bi1;

            const int colh = cg & 1023;
            const int h = colh >> 6;
            const int d = colh & 63;

            if (seg < 2) {
                float s0, c0, s1, c1;
                sincosf((float)t0 * fr[nt], &s0, &c0);
                sincosf((float)t1 * fr[nt], &s1, &c1);
                float sc = (seg == 0) ? QSC : 1.0f;
                float a0 = (y00 * c0 - y01 * s0) * sc;
                float a1 = (y01 * c0 + y00 * s0) * sc;
                float e0 = (y10 * c1 - y11 * s1) * sc;
                float e1 = (y11 * c1 + y10 * s1) * sc;
                __half* Dst = (seg == 0) ? Qh : Kh;
                size_t o0 = ((size_t)(b0 * H_ + h) * T_ + t0) * D_ + d;
                size_t o1 = ((size_t)(b1 * H_ + h) * T_ + t1) * D_ + d;
                *(__half2*)(Dst + o0) = __floats2half2_rn(a0, a1);
                *(__half2*)(Dst + o1) = __floats2half2_rn(e0, e1);
            } else {
                size_t ov0 = ((size_t)(b0 * H_ + h) * D_ + d) * T_ + t0;
                size_t ov1 = ((size_t)(b1 * H_ + h) * D_ + d) * T_ + t1;
                VTh[ov0]      = __float2half_rn(y00);
                VTh[ov0 + T_] = __float2half_rn(y01);
                VTh[ov1]      = __float2half_rn(y10);
                VTh[ov1 + T_] = __float2half_rn(y11);
            }
        }
    }
}

// ======================= tensor-core causal flash attention (pure fp16) =======================
// BQ=128, BKV=64, 8 warps x 16 q-rows. S = Qh*Kh, O = Ph*Vh (single pass each).
#define AROWB 144
#define QTILE (128 * AROWB)
#define KVTILE (64 * AROWB)
#define SQH_OFF 0
#define STG_OFF QTILE
#define STGSZ  (2 * KVTILE)
#define ST_KH 0
#define ST_VH (1 * KVTILE)
#define ATTN_SMEM (QTILE + 2 * STGSZ)   // 55296

__device__ __forceinline__ void attn_load_stage(
    uint32_t st, const __half* kh, const __half* vth,
    size_t bhT, size_t bhD, int k0, int tid)
{
#pragma unroll
    for (int it = 0; it < 2; it++) {
        int idx = it * 256 + tid;          // 0..511
        int row = idx >> 3;                // 0..63
        int ch = (idx & 7) * 16;           // 8 x 16B = 128B row
        uint32_t dst = (uint32_t)row * AROWB + ch;
        cp16(st + ST_KH + dst, (const char*)(kh + (bhT + k0 + row) * D_) + ch);
        cp16(st + ST_VH + dst, (const char*)(vth + (bhD + row) * T_ + k0) + ch);
    }
}

__global__ void __launch_bounds__(256, 2) attn_mma_kernel(
    const __half* __restrict__ qh, const __half* __restrict__ kh,
    const __half* __restrict__ vth,
    __half* __restrict__ Oh, float* __restrict__ osq)
{
    extern __shared__ char smem[];
    const uint32_t sb = smem_u32(smem);

    const int bh = blockIdx.y;
    const int qx = 15 - (int)blockIdx.x;
    const int q0 = qx * 128;
    const size_t bhT = (size_t)bh * T_;
    const size_t bhD = (size_t)bh * D_;

    const int tid = threadIdx.x;
    const int wid = tid >> 5, lane = tid & 31;
    const int lr = lane >> 2, c2 = (lane & 3) * 2;

    const uint32_t aSel = (uint32_t)(lane & 15) * AROWB + (uint32_t)(lane >> 4) * 16;
    const uint32_t bSel = (uint32_t)(((lane >> 4) & 1) * 8 + (lane & 7)) * AROWB +
                          (uint32_t)((lane >> 3) & 1) * 16;

    // ---- load Q tile: 128 rows x 128 B ----
#pragma unroll
    for (int it = 0; it < 4; it++) {
        int idx = it * 256 + tid;
        int row = idx >> 3;
        int ch = (idx & 7) * 16;
        uint32_t dst = (uint32_t)row * AROWB + ch;
        cp16(sb + SQH_OFF + dst, (const char*)(qh + (bhT + q0 + row) * D_) + ch);
    }
    asm volatile("cp.async.commit_group;" ::: "memory");

    attn_load_stage(sb + STG_OFF, kh, vth, bhT, bhD, 0, tid);
    asm volatile("cp.async.commit_group;" ::: "memory");

    asm volatile("cp.async.wait_group 1;" ::: "memory");
    __syncthreads();
    uint32_t qhf[4][4];
    {
        const uint32_t aQ = sb + SQH_OFF + (uint32_t)wid * 16 * AROWB + aSel;
#pragma unroll
        for (int ks = 0; ks < 4; ks++)
            LDSM4(qhf[ks][0], qhf[ks][1], qhf[ks][2], qhf[ks][3], aQ + ks * 32);
    }

    float O[8][4];
#pragma unroll
    for (int j = 0; j < 8; j++)
#pragma unroll
        for (int e = 0; e < 4; e++) O[j][e] = 0.f;
    float mrow[2] = {-1e30f, -1e30f};
    float lrow[2] = {0.f, 0.f};

    const int ntiles = 2 * qx + 2;
    const int rowg0 = q0 + wid * 16 + lr;

    for (int kt = 0; kt < ntiles; kt++) {
        const uint32_t st = sb + STG_OFF + (uint32_t)(kt & 1) * STGSZ;
        if (kt + 1 < ntiles) {
            attn_load_stage(sb + STG_OFF + (uint32_t)((kt + 1) & 1) * STGSZ,
                            kh, vth, bhT, bhD, (kt + 1) * 64, tid);
            asm volatile("cp.async.commit_group;" ::: "memory");
            asm volatile("cp.async.wait_group 1;" ::: "memory");
        } else {
            asm volatile("cp.async.wait_group 0;" ::: "memory");
        }
        __syncthreads();

        float S[8][4];
#pragma unroll
        for (int j = 0; j < 8; j++)
#pragma unroll
            for (int e = 0; e < 4; e++) S[j][e] = 0.f;

#pragma unroll
        for (int ks = 0; ks < 4; ks++) {
#pragma unroll
            for (int np = 0; np < 4; np++) {
                uint32_t r0, r1, r2, r3;
                LDSM4(r0, r1, r2, r3, st + ST_KH + np * (16 * AROWB) + bSel + ks * 32);
                uint32_t bh0[2] = {r0, r1}, bh1[2] = {r2, r3};
                MMA16816(S[np * 2 + 0], qhf[ks], bh0);
                MMA16816(S[np * 2 + 1], qhf[ks], bh1);
            }
        }

        const int k0 = kt * 64;
        if (kt >= 2 * qx) {
#pragma unroll
            for (int j = 0; j < 8; j++) {
                int col = k0 + j * 8 + c2;
                if (col > rowg0)     S[j][0] = -1e30f;
                if (col + 1 > rowg0) S[j][1] = -1e30f;
                if (col > rowg0 + 8)     S[j][2] = -1e30f;
                if (col + 1 > rowg0 + 8) S[j][3] = -1e30f;
            }
        }

#pragma unroll
        for (int i = 0; i < 2; i++) {
            float mx = -1e30f;
#pragma unroll
            for (int j = 0; j < 8; j++)
                mx = fmaxf(mx, fmaxf(S[j][2 * i], S[j][2 * i + 1]));
            mx = fmaxf(mx, __shfl_xor_sync(0xffffffffu, mx, 1));
            mx = fmaxf(mx, __shfl_xor_sync(0xffffffffu, mx, 2));
            float mn = fmaxf(mrow[i], mx);
            float cf = fast_exp2(mrow[i] - mn);
            mrow[i] = mn;
            float rs = 0.f;
#pragma unroll
            for (int j = 0; j < 8; j++) {
                float p0 = fast_exp2(S[j][2 * i] - mn);
                float p1 = fast_exp2(S[j][2 * i + 1] - mn);
                S[j][2 * i] = p0; S[j][2 * i + 1] = p1;
                rs += p0 + p1;
            }
            rs += __shfl_xor_sync(0xffffffffu, rs, 1);
            rs += __shfl_xor_sync(0xffffffffu, rs, 2);
            lrow[i] = lrow[i] * cf + rs;
#pragma unroll
            for (int j = 0; j < 8; j++) { O[j][2 * i] *= cf; O[j][2 * i + 1] *= cf; }
        }

        // ---- pack P into A fragments ----
        uint32_t PH[4][4];
#pragma unroll
        for (int t = 0; t < 4; t++) {
#pragma unroll
            for (int h2 = 0; h2 < 2; h2++) {
                int j = 2 * t + h2;
                PH[t][h2 * 2 + 0] = pack_f16(S[j][0], S[j][1]);
                PH[t][h2 * 2 + 1] = pack_f16(S[j][2], S[j][3]);
            }
        }

#pragma unroll
        for (int t = 0; t < 4; t++) {
#pragma unroll
            for (int dn = 0; dn < 4; dn++) {
                uint32_t r0, r1, r2, r3;
                LDSM4(r0, r1, r2, r3, st + ST_VH + dn * (16 * AROWB) + bSel + t * 32);
                uint32_t vh0[2] = {r0, r1}, vh1[2] = {r2, r3};
                MMA16816(O[dn * 2 + 0], PH[t], vh0);
                MMA16816(O[dn * 2 + 1], PH[t], vh1);
            }
        }
        __syncthreads();
    }

    // ---- fused epilogue: normalize, fp16 write + osq atomics ----
    const int b = bh >> 4, h = bh & 15;
    const float inv0 = 1.f / lrow[0], inv1 = 1.f / lrow[1];
    const size_t m0 = (size_t)(b * T_ + rowg0);
    const size_t m1 = m0 + 8;
    __half* oh0 = Oh + m0 * C_ + h * 64;
    __half* oh1 = Oh + m1 * C_ + h * 64;
    float sq0 = 0.f, sq1 = 0.f;
#pragma unroll
    for (int j = 0; j < 8; j++) {
        float y0 = O[j][0] * inv0, y1 = O[j][1] * inv0;
        float y2 = O[j][2] * inv1, y3 = O[j][3] * inv1;
        sq0 += y0 * y0 + y1 * y1;
        sq1 += y2 * y2 + y3 * y3;
        *(__half2*)(oh0 + j * 8 + c2) = __floats2half2_rn(y0, y1);
        *(__half2*)(oh1 + j * 8 + c2) = __floats2half2_rn(y2, y3);
    }
    sq0 += __shfl_xor_sync(0xffffffffu, sq0, 1);
    sq0 += __shfl_xor_sync(0xffffffffu, sq0, 2);
    sq1 += __shfl_xor_sync(0xffffffffu, sq1, 1);
    sq1 += __shfl_xor_sync(0xffffffffu, sq1, 2);
    if ((lane & 3) == 0) {
        atomicAdd(osq + m0, sq0);
        atomicAdd(osq + m1, sq1);
    }
}

// ---------------- launcher ----------------
extern "C" void kernel_launch(void* const* d_in, const int* in_sizes, int n_in,
                              void* d_out, int out_size)
{
    (void)in_sizes; (void)n_in; (void)out_size;
    const float* x      = (const float*)d_in[0];
    const float* w_attn = (const float*)d_in[2];
    const float* b_attn = (const float*)d_in[3];
    const float* w_proj = (const float*)d_in[4];
    const float* b_proj = (const float*)d_in[5];
    float* out = (float*)d_out;

    float *xsq, *osq, *wsq1, *wsq2;
    __half *xh, *ah, *w1h, *w1l, *w2h, *w2l;
    __half *qbh, *kbh, *vth;
    cudaGetSymbolAddress((void**)&xsq,  g_xsq);
    cudaGetSymbolAddress((void**)&osq,  g_osq);
    cudaGetSymbolAddress((void**)&wsq1, g_wsq1);
    cudaGetSymbolAddress((void**)&wsq2, g_wsq2);
    cudaGetSymbolAddress((void**)&xh,   g_xh);
    cudaGetSymbolAddress((void**)&ah,   g_ah);
    cudaGetSymbolAddress((void**)&w1h,  g_w1h);
    cudaGetSymbolAddress((void**)&w1l,  g_w1l);
    cudaGetSymbolAddress((void**)&w2h,  g_w2h);
    cudaGetSymbolAddress((void**)&w2l,  g_w2l);
    cudaGetSymbolAddress((void**)&qbh,  g_qbh);
    cudaGetSymbolAddress((void**)&kbh,  g_kbh);
    cudaGetSymbolAddress((void**)&vth,  g_vth);

    const float scale1 = (float)(sqrt(3072.0) / log1p(3072.0));
    const float scale2 = (float)(sqrt(1024.0) / log1p(1024.0));

    cudaFuncSetAttribute(yat_mma_gemm_kernel,
                         cudaFuncAttributeMaxDynamicSharedMemorySize, MMA_SMEM);
    cudaFuncSetAttribute(yat_rope_gemm_kernel,
                         cudaFuncAttributeMaxDynamicSharedMemorySize, MMA_SMEM);
    cudaFuncSetAttribute(attn_mma_kernel,
                         cudaFuncAttributeMaxDynamicSharedMemorySize, ATTN_SMEM);

    cudaMemsetAsync(wsq1, 0, N1_ * sizeof(float));
    cudaMemsetAsync(wsq2, 0, C_ * sizeof(float));
    cudaMemsetAsync(osq,  0, M_ * sizeof(float));

    prep_x_kernel<<<M_, 256>>>(x, xsq, xh);
    wconv_kernel<<<dim3(N1_ / 32, C_ / 32), 256>>>(w_attn, w1h, w1l, wsq1, C_, N1_);
    wconv_kernel<<<dim3(C_ / 32, C_ / 32), 256>>>(w_proj, w2h, w2l, wsq2, C_, C_);

    yat_rope_gemm_kernel<<<dim3(N1_ / 128, M_ / 128), 256, MMA_SMEM>>>(
        xh, w1h, w1l, xsq, wsq1, b_attn,
        qbh, kbh, vth, scale1);

    attn_mma_kernel<<<dim3(T_ / 128, B_ * H_), 256, ATTN_SMEM>>>(
        qbh, kbh, vth, ah, osq);

    yat_mma_gemm_kernel<<<dim3(C_ / 128, M_ / 128), 256, MMA_SMEM>>>(
        ah, w2h, w2l, osq, wsq2, b_proj, out, M_, C_, C_, scale2);
}

// round 10
// speedup vs baseline: 25.4978x; 1.0500x over previous
#include <cuda_runtime.h>
#include <cuda_fp16.h>
#include <math.h>
#include <stdint.h>

#define B_   2
#define T_   2048
#define C_   1024
#define H_   16
#define D_   64
#define M_   4096          // B_*T_
#define N1_  3072          // 3*C_
#define EPS_ 1e-6f

// ---------------- scratch (device globals; no allocation allowed) ----------------
__device__ float g_xsq[M_];
__device__ float g_osq[M_];
__device__ float g_wsq1[N1_];
__device__ float g_wsq2[C_];
// fp16 operands (A sides: hi only; B sides: hi+lo)
__device__ __half g_xh[(size_t)M_ * C_];
__device__ __half g_ah[(size_t)M_ * C_];
__device__ __half g_w1h[(size_t)N1_ * C_];  // [N,K] transposed
__device__ __half g_w1l[(size_t)N1_ * C_];
__device__ __half g_w2h[(size_t)C_ * C_];
__device__ __half g_w2l[(size_t)C_ * C_];
// attention operands (pure fp16)
__device__ __half g_qbh[(size_t)B_ * H_ * T_ * D_];  // [B,H,T,D] (scaled)
__device__ __half g_kbh[(size_t)B_ * H_ * T_ * D_];  // [B,H,T,D]
__device__ __half g_vth[(size_t)B_ * H_ * D_ * T_];  // [B,H,D,T]

__device__ __forceinline__ float fast_exp2(float x) {
    float r;
    asm("ex2.approx.ftz.f32 %0, %1;" : "=f"(r) : "f"(x));
    return r;
}

__device__ __forceinline__ uint32_t smem_u32(const void* p) {
    return (uint32_t)__cvta_generic_to_shared(p);
}

__device__ __forceinline__ uint32_t pack_f16(float lo, float hi) {
    uint32_t r;
    asm("cvt.rn.f16x2.f32 %0, %1, %2;" : "=r"(r) : "f"(hi), "f"(lo));
    return r;
}

// ======================= small helper kernels =======================

__global__ void prep_x_kernel(const float* __restrict__ X, float* __restrict__ xsq,
                              __half* __restrict__ Xh)
{
    int m = blockIdx.x;
    int tid = threadIdx.x;
    size_t i = (size_t)m * C_ + tid * 4;
    float4 v = *(const float4*)(X + i);
    *(__half2*)(Xh + i)     = __floats2half2_rn(v.x, v.y);
    *(__half2*)(Xh + i + 2) = __floats2half2_rn(v.z, v.w);

    float s = v.x * v.x + v.y * v.y + v.z * v.z + v.w * v.w;
#pragma unroll
    for (int o = 16; o; o >>= 1) s += __shfl_xor_sync(0xffffffffu, s, o);
    __shared__ float red[8];
    if ((tid & 31) == 0) red[tid >> 5] = s;
    __syncthreads();
    if (tid == 0) {
        float t = 0.f;
#pragma unroll
        for (int j = 0; j < 8; j++) t += red[j];
        xsq[m] = t;
    }
}

// W[K][N] fp32 -> WT[N][K] fp16 hi/lo + fused column sum-of-squares (wsq pre-zeroed)
__global__ void wconv_kernel(const float* __restrict__ W,
                             __half* __restrict__ WhT,
                             __half* __restrict__ WlT,
                             float* __restrict__ wsq,
                             int K, int N)
{
    __shared__ float tile[32][33];
    int bx = blockIdx.x, by = blockIdx.y;
    int tx = threadIdx.x & 31, ty = threadIdx.x >> 5;
#pragma unroll
    for (int i = ty; i < 32; i += 8)
        tile[i][tx] = W[(size_t)(by * 32 + i) * N + bx * 32 + tx];
    __syncthreads();
#pragma unroll
    for (int i = ty; i < 32; i += 8) {
        int n = bx * 32 + i, k = by * 32 + tx;
        float v = tile[tx][i];
        __half h = __float2half_rn(v);
        WhT[(size_t)n * K + k] = h;
        WlT[(size_t)n * K + k] = __float2half_rn(v - __half2float(h));
        float s = v * v;
#pragma unroll
        for (int o = 16; o; o >>= 1) s += __shfl_xor_sync(0xffffffffu, s, o);
        if (tx == 0) atomicAdd(wsq + n, s);
    }
}

// ======================= mma.sync helpers =======================

#define LDSM4(r0, r1, r2, r3, addr) \
    asm volatile("ldmatrix.sync.aligned.m8n8.x4.shared.b16 {%0,%1,%2,%3}, [%4];" \
                 : "=r"(r0), "=r"(r1), "=r"(r2), "=r"(r3) : "r"(addr))

#define MMA16816(d, a, b) \
    asm volatile("mma.sync.aligned.m16n8k16.row.col.f32.f16.f16.f32 " \
                 "{%0,%1,%2,%3}, {%4,%5,%6,%7}, {%8,%9}, {%0,%1,%2,%3};" \
                 : "+f"((d)[0]), "+f"((d)[1]), "+f"((d)[2]), "+f"((d)[3]) \
                 : "r"((a)[0]), "r"((a)[1]), "r"((a)[2]), "r"((a)[3]), \
                   "r"((b)[0]), "r"((b)[1]))

__device__ __forceinline__ void cp16(uint32_t dst, const void* src) {
    asm volatile("cp.async.cg.shared.global [%0], [%1], 16;" :: "r"(dst), "l"(src));
}

// ======================= shared GEMM core (fp16x2, 2-pass, BK=64) =======================
#define ROWB   144                 // 128B data + 16B pad, conflict-free ldmatrix
#define TILEB  (128 * ROWB)        // 18432
#define OFF_A  0
#define OFF_BH (1 * TILEB)
#define OFF_BL (2 * TILEB)
#define STAGEB (3 * TILEB)         // 55296
#define MMA_SMEM (2 * STAGEB)      // 110592

__device__ __forceinline__ void load_stage(
    uint32_t st, const __half* Ag,
    const __half* Bgh, const __half* Bgl,
    int k0, int K, int tid)
{
#pragma unroll
    for (int it = 0; it < 4; it++) {
        int idx = it * 256 + tid;          // 0..1023
        int row = idx >> 3;                // 0..127
        int ch = (idx & 7) * 16;           // 8 x 16B = 128B (64 fp16)
        uint32_t dst = (uint32_t)row * ROWB + ch;
        size_t srcel = (size_t)row * K + k0;
        cp16(st + OFF_A + dst,  (const char*)(Ag + srcel) + ch);
        cp16(st + OFF_BH + dst, (const char*)(Bgh + srcel) + ch);
        cp16(st + OFF_BL + dst, (const char*)(Bgl + srcel) + ch);
    }
}

// 2-pass mainloop over one BK=64 chunk: acc += Ah*Bh + Ah*Bl (4 k-steps)
__device__ __forceinline__ void gemm_chunk(
    uint32_t st, uint32_t aSel, uint32_t bSel, int warpM, int warpN,
    float acc[4][4][4])
{
#pragma unroll
    for (int ks = 0; ks < 4; ks++) {
        const uint32_t aB  = st + OFF_A  + (uint32_t)warpM * 64 * ROWB + aSel + ks * 32;
        const uint32_t bHB = st + OFF_BH + (uint32_t)warpN * 32 * ROWB + bSel + ks * 32;
        const uint32_t bLB = st + OFF_BL + (uint32_t)warpN * 32 * ROWB + bSel + ks * 32;
        uint32_t ah4[4][4];
#pragma unroll
        for (int mt = 0; mt < 4; mt++)
            LDSM4(ah4[mt][0], ah4[mt][1], ah4[mt][2], ah4[mt][3],
                  aB + mt * (16 * ROWB));
        uint32_t bh[4][2], bl[4][2];
#pragma unroll
        for (int nt2 = 0; nt2 < 2; nt2++) {
            uint32_t r0, r1, r2, r3;
            LDSM4(r0, r1, r2, r3, bHB + nt2 * (16 * ROWB));
            bh[nt2 * 2 + 0][0] = r0; bh[nt2 * 2 + 0][1] = r1;
            bh[nt2 * 2 + 1][0] = r2; bh[nt2 * 2 + 1][1] = r3;
            LDSM4(r0, r1, r2, r3, bLB + nt2 * (16 * ROWB));
            bl[nt2 * 2 + 0][0] = r0; bl[nt2 * 2 + 0][1] = r1;
            bl[nt2 * 2 + 1][0] = r2; bl[nt2 * 2 + 1][1] = r3;
        }
#pragma unroll
        for (int mt = 0; mt < 4; mt++)
#pragma unroll
            for (int nt = 0; nt < 4; nt++)
                MMA16816(acc[mt][nt], ah4[mt], bh[nt]);
#pragma unroll
        for (int mt = 0; mt < 4; mt++)
#pragma unroll
            for (int nt = 0; nt < 4; nt++)
                MMA16816(acc[mt][nt], ah4[mt], bl[nt]);
    }
}

// GEMM mainloop driver (shared by both yat kernels)
#define GEMM_MAIN(Agh, Bgh, Bgl, K)                                            \
    float acc[4][4][4];                                                        \
    _Pragma("unroll")                                                          \
    for (int i = 0; i < 4; i++)                                                \
        _Pragma("unroll")                                                      \
        for (int j = 0; j < 4; j++)                                            \
            _Pragma("unroll")                                                  \
            for (int e = 0; e < 4; e++) acc[i][j][e] = 0.f;                    \
    load_stage(sb, Agh, Bgh, Bgl, 0, K, tid);                                  \
    asm volatile("cp.async.commit_group;" ::: "memory");                       \
    const int NC = (K) >> 6;                                                   \
    for (int c = 0; c < NC; c++) {                                             \
        if (c + 1 < NC) {                                                      \
            load_stage(sb + (uint32_t)((c + 1) & 1) * STAGEB,                  \
                       Agh, Bgh, Bgl, (c + 1) << 6, K, tid);                   \
            asm volatile("cp.async.commit_group;" ::: "memory");               \
            asm volatile("cp.async.wait_group 1;" ::: "memory");               \
        } else {                                                               \
            asm volatile("cp.async.wait_group 0;" ::: "memory");               \
        }                                                                      \
        __syncthreads();                                                       \
        gemm_chunk(sb + (uint32_t)(c & 1) * STAGEB, aSel, bSel, warpM, warpN,  \
                   acc);                                                       \
        __syncthreads();                                                       \
    }

// ======================= GEMM2: yat -> fp32 out =======================
__global__ void __launch_bounds__(256, 2) yat_mma_gemm_kernel(
    const __half* __restrict__ Ah,
    const __half* __restrict__ BhT, const __half* __restrict__ BlT,
    const float* __restrict__ asq, const float* __restrict__ bsq,
    const float* __restrict__ bias, float* __restrict__ Cout,
    int M, int N, int K, float scale)
{
    extern __shared__ char smem[];
    const uint32_t sb = smem_u32(smem);

    const int tid = threadIdx.x;
    const int wid = tid >> 5, lane = tid & 31;
    const int warpM = wid >> 2;
    const int warpN = wid & 3;
    const int rowBase = blockIdx.y * 128;
    const int colBase = blockIdx.x * 128;

    const __half* Agh = Ah + (size_t)rowBase * K;
    const __half* Bgh = BhT + (size_t)colBase * K;
    const __half* Bgl = BlT + (size_t)colBase * K;

    const uint32_t aSel = (uint32_t)(lane & 15) * ROWB + (uint32_t)(lane >> 4) * 16;
    const uint32_t bSel = (uint32_t)(((lane >> 4) & 1) * 8 + (lane & 7)) * ROWB +
                          (uint32_t)((lane >> 3) & 1) * 16;

    GEMM_MAIN(Agh, Bgh, Bgl, K)

    const int lr = lane >> 2, lc = (lane & 3) * 2;
    const int mW = rowBase + warpM * 64;
    const int nW = colBase + warpN * 32;
#pragma unroll
    for (int mt = 0; mt < 4; mt++) {
        const int r0g = mW + mt * 16 + lr;
        const int r1g = r0g + 8;
        const float av0 = asq[r0g];
        const float av1 = asq[r1g];
#pragma unroll
        for (int nt = 0; nt < 4; nt++) {
            const int cg = nW + nt * 8 + lc;
            const float bq0 = bsq[cg], bq1 = bsq[cg + 1];
            const float bi0 = bias[cg], bi1 = bias[cg + 1];
            float d00 = acc[mt][nt][0], d01 = acc[mt][nt][1];
            float d10 = acc[mt][nt][2], d11 = acc[mt][nt][3];
            float2 o0, o1;
            o0.x = __fdividef(d00 * d00, av0 + bq0 - 2.f * d00 + EPS_) * scale + bi0;
            o0.y = __fdividef(d01 * d01, av0 + bq1 - 2.f * d01 + EPS_) * scale + bi1;
            o1.x = __fdividef(d10 * d10, av1 + bq0 - 2.f * d10 + EPS_) * scale + bi0;
            o1.y = __fdividef(d11 * d11, av1 + bq1 - 2.f * d11 + EPS_) * scale + bi1;
            *(float2*)(Cout + (size_t)r0g * N + cg) = o0;
            *(float2*)(Cout + (size_t)r1g * N + cg) = o1;
        }
    }
}

// ======================= GEMM1: yat + RoPE + fp16 fused epilogue =======================
__global__ void __launch_bounds__(256, 2) yat_rope_gemm_kernel(
    const __half* __restrict__ Ah,
    const __half* __restrict__ BhT, const __half* __restrict__ BlT,
    const float* __restrict__ asq, const float* __restrict__ bsq,
    const float* __restrict__ bias,
    __half* __restrict__ Qh, __half* __restrict__ Kh,
    __half* __restrict__ VTh,
    float scale)
{
    extern __shared__ char smem[];
    const uint32_t sb = smem_u32(smem);
    const int K = C_, N = N1_;
    (void)N;

    const int tid = threadIdx.x;
    const int wid = tid >> 5, lane = tid & 31;
    const int warpM = wid >> 2;
    const int warpN = wid & 3;
    const int rowBase = blockIdx.y * 128;
    const int colBase = blockIdx.x * 128;

    const __half* Agh = Ah + (size_t)rowBase * K;
    const __half* Bgh = BhT + (size_t)colBase * K;
    const __half* Bgl = BlT + (size_t)colBase * K;

    const uint32_t aSel = (uint32_t)(lane & 15) * ROWB + (uint32_t)(lane >> 4) * 16;
    const uint32_t bSel = (uint32_t)(((lane >> 4) & 1) * 8 + (lane & 7)) * ROWB +
                          (uint32_t)((lane >> 3) & 1) * 16;

    GEMM_MAIN(Agh, Bgh, Bgl, K)

    // ---- epilogue: yat + bias, then RoPE/split per segment ----
    const int lr = lane >> 2, lc = (lane & 3) * 2;
    const int mW = rowBase + warpM * 64;
    const int nW = colBase + warpN * 32;
    const int seg = colBase >> 10;                 // 0=Q, 1=K, 2=V
    const float QSC = 0.125f * 1.4426950408889634f;

    float fr[4];
#pragma unroll
    for (int nt = 0; nt < 4; nt++) {
        int cg = nW + nt * 8 + lc;
        int i = (cg & 63) >> 1;
        fr[nt] = powf(10000.0f, -(float)i / 32.0f);
    }

#pragma unroll
    for (int mt = 0; mt < 4; mt++) {
        const int r0g = mW + mt * 16 + lr;
        const int r1g = r0g + 8;
        const float av0 = asq[r0g];
        const float av1 = asq[r1g];
        const int b0 = r0g >> 11, t0 = r0g & 2047;
        const int b1 = r1g >> 11, t1 = r1g & 2047;
#pragma unroll
        for (int nt = 0; nt < 4; nt++) {
            const int cg = nW + nt * 8 + lc;
            const float bq0 = bsq[cg], bq1 = bsq[cg + 1];
            const float bi0 = bias[cg], bi1 = bias[cg + 1];
            float d00 = acc[mt][nt][0], d01 = acc[mt][nt][1];
            float d10 = acc[mt][nt][2], d11 = acc[mt][nt][3];
            float y00 = __fdividef(d00 * d00, av0 + bq0 - 2.f * d00 + EPS_) * scale + bi0;
            float y01 = __fdividef(d01 * d01, av0 + bq1 - 2.f * d01 + EPS_) * scale + bi1;
            float y10 = __fdividef(d10 * d10, av1 + bq0 - 2.f * d10 + EPS_) * scale + bi0;
            float y11 = __fdividef(d11 * d11, av1 + bq1 - 2.f * d11 + EPS_) * scale + bi1;

            const int colh = cg & 1023;
            const int h = colh >> 6;
            const int d = colh & 63;

            if (seg < 2) {
                float s0, c0, s1, c1;
                sincosf((float)t0 * fr[nt], &s0, &c0);
                sincosf((float)t1 * fr[nt], &s1, &c1);
                float sc = (seg == 0) ? QSC : 1.0f;
                float a0 = (y00 * c0 - y01 * s0) * sc;
                float a1 = (y01 * c0 + y00 * s0) * sc;
                float e0 = (y10 * c1 - y11 * s1) * sc;
                float e1 = (y11 * c1 + y10 * s1) * sc;
                __half* Dst = (seg == 0) ? Qh : Kh;
                size_t o0 = ((size_t)(b0 * H_ + h) * T_ + t0) * D_ + d;
                size_t o1 = ((size_t)(b1 * H_ + h) * T_ + t1) * D_ + d;
                *(__half2*)(Dst + o0) = __floats2half2_rn(a0, a1);
                *(__half2*)(Dst + o1) = __floats2half2_rn(e0, e1);
            } else {
                size_t ov0 = ((size_t)(b0 * H_ + h) * D_ + d) * T_ + t0;
                size_t ov1 = ((size_t)(b1 * H_ + h) * D_ + d) * T_ + t1;
                VTh[ov0]      = __float2half_rn(y00);
                VTh[ov0 + T_] = __float2half_rn(y01);
                VTh[ov1]      = __float2half_rn(y10);
                VTh[ov1 + T_] = __float2half_rn(y11);
            }
        }
    }
}

// ======================= tensor-core causal flash attention (pure fp16, 3-stage) =======================
#define AROWB 144
#define QTILE (128 * AROWB)
#define KVTILE (64 * AROWB)
#define SQH_OFF 0
#define STG_OFF QTILE
#define STGSZ  (2 * KVTILE)          // KH + VH = 18432
#define ST_KH 0
#define ST_VH (1 * KVTILE)
#define ATTN_SMEM (QTILE + 3 * STGSZ)   // 73728

__device__ __forceinline__ void attn_load_stage(
    uint32_t st, const __half* kh, const __half* vth,
    size_t bhT, size_t bhD, int k0, int tid)
{
#pragma unroll
    for (int it = 0; it < 2; it++) {
        int idx = it * 256 + tid;
        int row = idx >> 3;
        int ch = (idx & 7) * 16;
        uint32_t dst = (uint32_t)row * AROWB + ch;
        cp16(st + ST_KH + dst, (const char*)(kh + (bhT + k0 + row) * D_) + ch);
        cp16(st + ST_VH + dst, (const char*)(vth + (bhD + row) * T_ + k0) + ch);
    }
}

__global__ void __launch_bounds__(256, 2) attn_mma_kernel(
    const __half* __restrict__ qh, const __half* __restrict__ kh,
    const __half* __restrict__ vth,
    __half* __restrict__ Oh, float* __restrict__ osq)
{
    extern __shared__ char smem[];
    const uint32_t sb = smem_u32(smem);

    const int bh = blockIdx.y;
    const int qx = 15 - (int)blockIdx.x;
    const int q0 = qx * 128;
    const size_t bhT = (size_t)bh * T_;
    const size_t bhD = (size_t)bh * D_;

    const int tid = threadIdx.x;
    const int wid = tid >> 5, lane = tid & 31;
    const int lr = lane >> 2, c2 = (lane & 3) * 2;

    const uint32_t aSel = (uint32_t)(lane & 15) * AROWB + (uint32_t)(lane >> 4) * 16;
    const uint32_t bSel = (uint32_t)(((lane >> 4) & 1) * 8 + (lane & 7)) * AROWB +
                          (uint32_t)((lane >> 3) & 1) * 16;

    const int ntiles = 2 * qx + 2;

    // ---- group 0: Q tile + KV stage 0 ----
#pragma unroll
    for (int it = 0; it < 4; it++) {
        int idx = it * 256 + tid;
        int row = idx >> 3;
        int ch = (idx & 7) * 16;
        uint32_t dst = (uint32_t)row * AROWB + ch;
        cp16(sb + SQH_OFF + dst, (const char*)(qh + (bhT + q0 + row) * D_) + ch);
    }
    attn_load_stage(sb + STG_OFF, kh, vth, bhT, bhD, 0, tid);
    asm volatile("cp.async.commit_group;" ::: "memory");
    // ---- group 1: KV stage 1 (ntiles >= 2 always) ----
    attn_load_stage(sb + STG_OFF + STGSZ, kh, vth, bhT, bhD, 64, tid);
    asm volatile("cp.async.commit_group;" ::: "memory");

    asm volatile("cp.async.wait_group 1;" ::: "memory");
    __syncthreads();
    uint32_t qhf[4][4];
    {
        const uint32_t aQ = sb + SQH_OFF + (uint32_t)wid * 16 * AROWB + aSel;
#pragma unroll
        for (int ks = 0; ks < 4; ks++)
            LDSM4(qhf[ks][0], qhf[ks][1], qhf[ks][2], qhf[ks][3], aQ + ks * 32);
    }

    float O[8][4];
#pragma unroll
    for (int j = 0; j < 8; j++)
#pragma unroll
        for (int e = 0; e < 4; e++) O[j][e] = 0.f;
    float mrow[2] = {-1e30f, -1e30f};
    float lrow[2] = {0.f, 0.f};

    const int rowg0 = q0 + wid * 16 + lr;
    int slot = 0;

    for (int kt = 0; kt < ntiles; kt++) {
        const uint32_t st = sb + STG_OFF + (uint32_t)slot * STGSZ;
        if (++slot == 3) slot = 0;
        if (kt + 2 < ntiles) {
            int ns = slot + 1; if (ns == 3) ns = 0;     // (kt+2) % 3
            attn_load_stage(sb + STG_OFF + (uint32_t)ns * STGSZ,
                            kh, vth, bhT, bhD, (kt + 2) * 64, tid);
            asm volatile("cp.async.commit_group;" ::: "memory");
            asm volatile("cp.async.wait_group 2;" ::: "memory");
        } else if (kt + 1 < ntiles) {
            asm volatile("cp.async.wait_group 1;" ::: "memory");
        } else {
            asm volatile("cp.async.wait_group 0;" ::: "memory");
        }
        __syncthreads();

        float S[8][4];
#pragma unroll
        for (int j = 0; j < 8; j++)
#pragma unroll
            for (int e = 0; e < 4; e++) S[j][e] = 0.f;

#pragma unroll
        for (int ks = 0; ks < 4; ks++) {
#pragma unroll
            for (int np = 0; np < 4; np++) {
                uint32_t r0, r1, r2, r3;
                LDSM4(r0, r1, r2, r3, st + ST_KH + np * (16 * AROWB) + bSel + ks * 32);
                uint32_t bh0[2] = {r0, r1}, bh1[2] = {r2, r3};
                MMA16816(S[np * 2 + 0], qhf[ks], bh0);
                MMA16816(S[np * 2 + 1], qhf[ks], bh1);
            }
        }

        const int k0 = kt * 64;
        if (kt >= 2 * qx) {
#pragma unroll
            for (int j = 0; j < 8; j++) {
                int col = k0 + j * 8 + c2;
                if (col > rowg0)     S[j][0] = -1e30f;
                if (col + 1 > rowg0) S[j][1] = -1e30f;
                if (col > rowg0 + 8)     S[j][2] = -1e30f;
                if (col + 1 > rowg0 + 8) S[j][3] = -1e30f;
            }
        }

#pragma unroll
        for (int i = 0; i < 2; i++) {
            float mx = -1e30f;
#pragma unroll
            for (int j = 0; j < 8; j++)
                mx = fmaxf(mx, fmaxf(S[j][2 * i], S[j][2 * i + 1]));
            mx = fmaxf(mx, __shfl_xor_sync(0xffffffffu, mx, 1));
            mx = fmaxf(mx, __shfl_xor_sync(0xffffffffu, mx, 2));
            float mn = fmaxf(mrow[i], mx);
            float cf = fast_exp2(mrow[i] - mn);
            mrow[i] = mn;
            float rs = 0.f;
#pragma unroll
            for (int j = 0; j < 8; j++) {
                float p0 = fast_exp2(S[j][2 * i] - mn);
                float p1 = fast_exp2(S[j][2 * i + 1] - mn);
                S[j][2 * i] = p0; S[j][2 * i + 1] = p1;
                rs += p0 + p1;
            }
            rs += __shfl_xor_sync(0xffffffffu, rs, 1);
            rs += __shfl_xor_sync(0xffffffffu, rs, 2);
            lrow[i] = lrow[i] * cf + rs;
#pragma unroll
            for (int j = 0; j < 8; j++) { O[j][2 * i] *= cf; O[j][2 * i + 1] *= cf; }
        }

        uint32_t PH[4][4];
#pragma unroll
        for (int t = 0; t < 4; t++) {
#pragma unroll
            for (int h2 = 0; h2 < 2; h2++) {
                int j = 2 * t + h2;
                PH[t][h2 * 2 + 0] = pack_f16(S[j][0], S[j][1]);
                PH[t][h2 * 2 + 1] = pack_f16(S[j][2], S[j][3]);
            }
        }

#pragma unroll
        for (int t = 0; t < 4; t++) {
#pragma unroll
            for (int dn = 0; dn < 4; dn++) {
                uint32_t r0, r1, r2, r3;
                LDSM4(r0, r1, r2, r3, st + ST_VH + dn * (16 * AROWB) + bSel + t * 32);
                uint32_t vh0[2] = {r0, r1}, vh1[2] = {r2, r3};
                MMA16816(O[dn * 2 + 0], PH[t], vh0);
                MMA16816(O[dn * 2 + 1], PH[t], vh1);
            }
        }
        __syncthreads();
    }

    // ---- fused epilogue: normalize, fp16 write + osq atomics ----
    const int b = bh >> 4, h = bh & 15;
    const float inv0 = 1.f / lrow[0], inv1 = 1.f / lrow[1];
    const size_t m0 = (size_t)(b * T_ + rowg0);
    const size_t m1 = m0 + 8;
    __half* oh0 = Oh + m0 * C_ + h * 64;
    __half* oh1 = Oh + m1 * C_ + h * 64;
    float sq0 = 0.f, sq1 = 0.f;
#pragma unroll
    for (int j = 0; j < 8; j++) {
        float y0 = O[j][0] * inv0, y1 = O[j][1] * inv0;
        float y2 = O[j][2] * inv1, y3 = O[j][3] * inv1;
        sq0 += y0 * y0 + y1 * y1;
        sq1 += y2 * y2 + y3 * y3;
        *(__half2*)(oh0 + j * 8 + c2) = __floats2half2_rn(y0, y1);
        *(__half2*)(oh1 + j * 8 + c2) = __floats2half2_rn(y2, y3);
    }
    sq0 += __shfl_xor_sync(0xffffffffu, sq0, 1);
    sq0 += __shfl_xor_sync(0xffffffffu, sq0, 2);
    sq1 += __shfl_xor_sync(0xffffffffu, sq1, 1);
    sq1 += __shfl_xor_sync(0xffffffffu, sq1, 2);
    if ((lane & 3) == 0) {
        atomicAdd(osq + m0, sq0);
        atomicAdd(osq + m1, sq1);
    }
}

// ---------------- launcher ----------------
extern "C" void kernel_launch(void* const* d_in, const int* in_sizes, int n_in,
                              void* d_out, int out_size)
{
    (void)in_sizes; (void)n_in; (void)out_size;
    const float* x      = (const float*)d_in[0];
    const float* w_attn = (const float*)d_in[2];
    const float* b_attn = (const float*)d_in[3];
    const float* w_proj = (const float*)d_in[4];
    const float* b_proj = (const float*)d_in[5];
    float* out = (float*)d_out;

    float *xsq, *osq, *wsq1, *wsq2;
    __half *xh, *ah, *w1h, *w1l, *w2h, *w2l;
    __half *qbh, *kbh, *vth;
    cudaGetSymbolAddress((void**)&xsq,  g_xsq);
    cudaGetSymbolAddress((void**)&osq,  g_osq);
    cudaGetSymbolAddress((void**)&wsq1, g_wsq1);
    cudaGetSymbolAddress((void**)&wsq2, g_wsq2);
    cudaGetSymbolAddress((void**)&xh,   g_xh);
    cudaGetSymbolAddress((void**)&ah,   g_ah);
    cudaGetSymbolAddress((void**)&w1h,  g_w1h);
    cudaGetSymbolAddress((void**)&w1l,  g_w1l);
    cudaGetSymbolAddress((void**)&w2h,  g_w2h);
    cudaGetSymbolAddress((void**)&w2l,  g_w2l);
    cudaGetSymbolAddress((void**)&qbh,  g_qbh);
    cudaGetSymbolAddress((void**)&kbh,  g_kbh);
    cudaGetSymbolAddress((void**)&vth,  g_vth);

    const float scale1 = (float)(sqrt(3072.0) / log1p(3072.0));
    const float scale2 = (float)(sqrt(1024.0) / log1p(1024.0));

    cudaFuncSetAttribute(yat_mma_gemm_kernel,
                         cudaFuncAttributeMaxDynamicSharedMemorySize, MMA_SMEM);
    cudaFuncSetAttribute(yat_rope_gemm_kernel,
                         cudaFuncAttributeMaxDynamicSharedMemorySize, MMA_SMEM);
    cudaFuncSetAttribute(attn_mma_kernel,
                         cudaFuncAttributeMaxDynamicSharedMemorySize, ATTN_SMEM);

    cudaMemsetAsync(wsq1, 0, N1_ * sizeof(float));
    cudaMemsetAsync(wsq2, 0, C_ * sizeof(float));
    cudaMemsetAsync(osq,  0, M_ * sizeof(float));

    prep_x_kernel<<<M_, 256>>>(x, xsq, xh);
    wconv_kernel<<<dim3(N1_ / 32, C_ / 32), 256>>>(w_attn, w1h, w1l, wsq1, C_, N1_);
    wconv_kernel<<<dim3(C_ / 32, C_ / 32), 256>>>(w_proj, w2h, w2l, wsq2, C_, C_);

    yat_rope_gemm_kernel<<<dim3(N1_ / 128, M_ / 128), 256, MMA_SMEM>>>(
        xh, w1h, w1l, xsq, wsq1, b_attn,
        qbh, kbh, vth, scale1);

    attn_mma_kernel<<<dim3(T_ / 128, B_ * H_), 256, ATTN_SMEM>>>(
        qbh, kbh, vth, ah, osq);

    yat_mma_gemm_kernel<<<dim3(C_ / 128, M_ / 128), 256, MMA_SMEM>>>(
        ah, w2h, w2l, osq, wsq2, b_proj, out, M_, C_, C_, scale2);
}

// round 11
// speedup vs baseline: 34.7666x; 1.3635x over previous
#include <cuda_runtime.h>
#include <cuda_fp16.h>
#include <math.h>
#include <stdint.h>

#define B_   2
#define T_   2048
#define C_   1024
#define H_   16
#define D_   64
#define M_   4096          // B_*T_
#define N1_  3072          // 3*C_
#define EPS_ 1e-6f

// ---------------- scratch (device globals; no allocation allowed) ----------------
__device__ float g_xsq[M_];
__device__ float g_osq[M_];
__device__ float g_wsq1[N1_];
__device__ float g_wsq2[C_];
// fp16 operands (all uncompensated; error budget verified across rounds 6-10)
__device__ __half g_xh[(size_t)M_ * C_];
__device__ __half g_ah[(size_t)M_ * C_];
__device__ __half g_w1h[(size_t)N1_ * C_];  // [N,K] transposed
__device__ __half g_w2h[(size_t)C_ * C_];
// attention operands
__device__ __half g_qbh[(size_t)B_ * H_ * T_ * D_];  // [B,H,T,D] (scaled)
__device__ __half g_kbh[(size_t)B_ * H_ * T_ * D_];  // [B,H,T,D]
__device__ __half g_vth[(size_t)B_ * H_ * D_ * T_];  // [B,H,D,T]

__device__ __forceinline__ float fast_exp2(float x) {
    float r;
    asm("ex2.approx.ftz.f32 %0, %1;" : "=f"(r) : "f"(x));
    return r;
}

__device__ __forceinline__ uint32_t smem_u32(const void* p) {
    return (uint32_t)__cvta_generic_to_shared(p);
}

__device__ __forceinline__ uint32_t pack_f16(float lo, float hi) {
    uint32_t r;
    asm("cvt.rn.f16x2.f32 %0, %1, %2;" : "=r"(r) : "f"(hi), "f"(lo));
    return r;
}

// ======================= small helper kernels =======================

__global__ void prep_x_kernel(const float* __restrict__ X, float* __restrict__ xsq,
                              __half* __restrict__ Xh)
{
    int m = blockIdx.x;
    int tid = threadIdx.x;
    size_t i = (size_t)m * C_ + tid * 4;
    float4 v = *(const float4*)(X + i);
    *(__half2*)(Xh + i)     = __floats2half2_rn(v.x, v.y);
    *(__half2*)(Xh + i + 2) = __floats2half2_rn(v.z, v.w);

    float s = v.x * v.x + v.y * v.y + v.z * v.z + v.w * v.w;
#pragma unroll
    for (int o = 16; o; o >>= 1) s += __shfl_xor_sync(0xffffffffu, s, o);
    __shared__ float red[8];
    if ((tid & 31) == 0) red[tid >> 5] = s;
    __syncthreads();
    if (tid == 0) {
        float t = 0.f;
#pragma unroll
        for (int j = 0; j < 8; j++) t += red[j];
        xsq[m] = t;
    }
}

// W[K][N] fp32 -> WT[N][K] fp16 + fused column sum-of-squares (wsq pre-zeroed)
__global__ void wconv_kernel(const float* __restrict__ W,
                             __half* __restrict__ WhT,
                             float* __restrict__ wsq,
                             int K, int N)
{
    __shared__ float tile[32][33];
    int bx = blockIdx.x, by = blockIdx.y;
    int tx = threadIdx.x & 31, ty = threadIdx.x >> 5;
#pragma unroll
    for (int i = ty; i < 32; i += 8)
        tile[i][tx] = W[(size_t)(by * 32 + i) * N + bx * 32 + tx];
    __syncthreads();
#pragma unroll
    for (int i = ty; i < 32; i += 8) {
        int n = bx * 32 + i, k = by * 32 + tx;
        float v = tile[tx][i];
        WhT[(size_t)n * K + k] = __float2half_rn(v);
        float s = v * v;
#pragma unroll
        for (int o = 16; o; o >>= 1) s += __shfl_xor_sync(0xffffffffu, s, o);
        if (tx == 0) atomicAdd(wsq + n, s);
    }
}

// ======================= mma.sync helpers =======================

#define LDSM4(r0, r1, r2, r3, addr) \
    asm volatile("ldmatrix.sync.aligned.m8n8.x4.shared.b16 {%0,%1,%2,%3}, [%4];" \
                 : "=r"(r0), "=r"(r1), "=r"(r2), "=r"(r3) : "r"(addr))

#define MMA16816(d, a, b) \
    asm volatile("mma.sync.aligned.m16n8k16.row.col.f32.f16.f16.f32 " \
                 "{%0,%1,%2,%3}, {%4,%5,%6,%7}, {%8,%9}, {%0,%1,%2,%3};" \
                 : "+f"((d)[0]), "+f"((d)[1]), "+f"((d)[2]), "+f"((d)[3]) \
                 : "r"((a)[0]), "r"((a)[1]), "r"((a)[2]), "r"((a)[3]), \
                   "r"((b)[0]), "r"((b)[1]))

__device__ __forceinline__ void cp16(uint32_t dst, const void* src) {
    asm volatile("cp.async.cg.shared.global [%0], [%1], 16;" :: "r"(dst), "l"(src));
}

// ======================= shared GEMM core (pure fp16, 1-pass, BK=64, 3-stage) =======================
#define ROWB   144                 // 128B data + 16B pad, conflict-free ldmatrix
#define TILEB  (128 * ROWB)        // 18432
#define OFF_A  0
#define OFF_B  TILEB
#define STAGEB (2 * TILEB)         // 36864
#define MMA_SMEM (3 * STAGEB)      // 110592

__device__ __forceinline__ void load_stage(
    uint32_t st, const __half* Ag, const __half* Bg,
    int k0, int K, int tid)
{
#pragma unroll
    for (int it = 0; it < 4; it++) {
        int idx = it * 256 + tid;          // 0..1023
        int row = idx >> 3;                // 0..127
        int ch = (idx & 7) * 16;           // 8 x 16B = 128B (64 fp16)
        uint32_t dst = (uint32_t)row * ROWB + ch;
        size_t srcel = (size_t)row * K + k0;
        cp16(st + OFF_A + dst, (const char*)(Ag + srcel) + ch);
        cp16(st + OFF_B + dst, (const char*)(Bg + srcel) + ch);
    }
}

// single-pass mainloop over one BK=64 chunk (4 k-steps)
__device__ __forceinline__ void gemm_chunk(
    uint32_t st, uint32_t aSel, uint32_t bSel, int warpM, int warpN,
    float acc[4][4][4])
{
#pragma unroll
    for (int ks = 0; ks < 4; ks++) {
        const uint32_t aB = st + OFF_A + (uint32_t)warpM * 64 * ROWB + aSel + ks * 32;
        const uint32_t bB = st + OFF_B + (uint32_t)warpN * 32 * ROWB + bSel + ks * 32;
        uint32_t ah4[4][4];
#pragma unroll
        for (int mt = 0; mt < 4; mt++)
            LDSM4(ah4[mt][0], ah4[mt][1], ah4[mt][2], ah4[mt][3],
                  aB + mt * (16 * ROWB));
        uint32_t bh[4][2];
#pragma unroll
        for (int nt2 = 0; nt2 < 2; nt2++) {
            uint32_t r0, r1, r2, r3;
            LDSM4(r0, r1, r2, r3, bB + nt2 * (16 * ROWB));
            bh[nt2 * 2 + 0][0] = r0; bh[nt2 * 2 + 0][1] = r1;
            bh[nt2 * 2 + 1][0] = r2; bh[nt2 * 2 + 1][1] = r3;
        }
#pragma unroll
        for (int mt = 0; mt < 4; mt++)
#pragma unroll
            for (int nt = 0; nt < 4; nt++)
                MMA16816(acc[mt][nt], ah4[mt], bh[nt]);
    }
}

// GEMM mainloop driver: 3-stage pipeline, ONE __syncthreads per chunk
#define GEMM_MAIN(Agh, Bgh, K)                                                 \
    float acc[4][4][4];                                                        \
    _Pragma("unroll")                                                          \
    for (int i = 0; i < 4; i++)                                                \
        _Pragma("unroll")                                                      \
        for (int j = 0; j < 4; j++)                                            \
            _Pragma("unroll")                                                  \
            for (int e = 0; e < 4; e++) acc[i][j][e] = 0.f;                    \
    load_stage(sb, Agh, Bgh, 0, K, tid);                                       \
    asm volatile("cp.async.commit_group;" ::: "memory");                       \
    load_stage(sb + STAGEB, Agh, Bgh, 64, K, tid);                             \
    asm volatile("cp.async.commit_group;" ::: "memory");                       \
    const int NC = (K) >> 6;                                                   \
    int slot = 0;                                                              \
    for (int c = 0; c < NC; c++) {                                             \
        if (c + 1 < NC) {                                                      \
            asm volatile("cp.async.wait_group 1;" ::: "memory");               \
        } else {                                                               \
            asm volatile("cp.async.wait_group 0;" ::: "memory");               \
        }                                                                      \
        __syncthreads();                                                       \
        const uint32_t stb = sb + (uint32_t)slot * STAGEB;                     \
        if (++slot == 3) slot = 0;                                             \
        if (c + 2 < NC) {                                                      \
            int ns = slot + 1; if (ns == 3) ns = 0;                            \
            load_stage(sb + (uint32_t)ns * STAGEB, Agh, Bgh, (c + 2) << 6, K,  \
                       tid);                                                   \
            asm volatile("cp.async.commit_group;" ::: "memory");               \
        }                                                                      \
        gemm_chunk(stb, aSel, bSel, warpM, warpN, acc);                        \
    }

// ======================= GEMM2: yat -> fp32 out =======================
__global__ void __launch_bounds__(256, 2) yat_mma_gemm_kernel(
    const __half* __restrict__ Ah, const __half* __restrict__ BhT,
    const float* __restrict__ asq, const float* __restrict__ bsq,
    const float* __restrict__ bias, float* __restrict__ Cout,
    int M, int N, int K, float scale)
{
    extern __shared__ char smem[];
    const uint32_t sb = smem_u32(smem);

    const int tid = threadIdx.x;
    const int wid = tid >> 5, lane = tid & 31;
    const int warpM = wid >> 2;
    const int warpN = wid & 3;
    const int rowBase = blockIdx.y * 128;
    const int colBase = blockIdx.x * 128;

    const __half* Agh = Ah + (size_t)rowBase * K;
    const __half* Bgh = BhT + (size_t)colBase * K;

    const uint32_t aSel = (uint32_t)(lane & 15) * ROWB + (uint32_t)(lane >> 4) * 16;
    const uint32_t bSel = (uint32_t)(((lane >> 4) & 1) * 8 + (lane & 7)) * ROWB +
                          (uint32_t)((lane >> 3) & 1) * 16;

    GEMM_MAIN(Agh, Bgh, K)

    const int lr = lane >> 2, lc = (lane & 3) * 2;
    const int mW = rowBase + warpM * 64;
    const int nW = colBase + warpN * 32;
#pragma unroll
    for (int mt = 0; mt < 4; mt++) {
        const int r0g = mW + mt * 16 + lr;
        const int r1g = r0g + 8;
        const float av0 = asq[r0g];
        const float av1 = asq[r1g];
#pragma unroll
        for (int nt = 0; nt < 4; nt++) {
            const int cg = nW + nt * 8 + lc;
            const float bq0 = bsq[cg], bq1 = bsq[cg + 1];
            const float bi0 = bias[cg], bi1 = bias[cg + 1];
            float d00 = acc[mt][nt][0], d01 = acc[mt][nt][1];
            float d10 = acc[mt][nt][2], d11 = acc[mt][nt][3];
            float2 o0, o1;
            o0.x = __fdividef(d00 * d00, av0 + bq0 - 2.f * d00 + EPS_) * scale + bi0;
            o0.y = __fdividef(d01 * d01, av0 + bq1 - 2.f * d01 + EPS_) * scale + bi1;
            o1.x = __fdividef(d10 * d10, av1 + bq0 - 2.f * d10 + EPS_) * scale + bi0;
            o1.y = __fdividef(d11 * d11, av1 + bq1 - 2.f * d11 + EPS_) * scale + bi1;
            *(float2*)(Cout + (size_t)r0g * N + cg) = o0;
            *(float2*)(Cout + (size_t)r1g * N + cg) = o1;
        }
    }
}

// ======================= GEMM1: yat + RoPE + fp16 fused epilogue =======================
__global__ void __launch_bounds__(256, 2) yat_rope_gemm_kernel(
    const __half* __restrict__ Ah, const __half* __restrict__ BhT,
    const float* __restrict__ asq, const float* __restrict__ bsq,
    const float* __restrict__ bias,
    __half* __restrict__ Qh, __half* __restrict__ Kh,
    __half* __restrict__ VTh,
    float scale)
{
    extern __shared__ char smem[];
    const uint32_t sb = smem_u32(smem);
    const int K = C_;

    const int tid = threadIdx.x;
    const int wid = tid >> 5, lane = tid & 31;
    const int warpM = wid >> 2;
    const int warpN = wid & 3;
    const int rowBase = blockIdx.y * 128;
    const int colBase = blockIdx.x * 128;

    const __half* Agh = Ah + (size_t)rowBase * K;
    const __half* Bgh = BhT + (size_t)colBase * K;

    const uint32_t aSel = (uint32_t)(lane & 15) * ROWB + (uint32_t)(lane >> 4) * 16;
    const uint32_t bSel = (uint32_t)(((lane >> 4) & 1) * 8 + (lane & 7)) * ROWB +
                          (uint32_t)((lane >> 3) & 1) * 16;

    GEMM_MAIN(Agh, Bgh, K)

    // ---- epilogue: yat + bias, then RoPE/split per segment ----
    const int lr = lane >> 2, lc = (lane & 3) * 2;
    const int mW = rowBase + warpM * 64;
    const int nW = colBase + warpN * 32;
    const int seg = colBase >> 10;                 // 0=Q, 1=K, 2=V
    const float QSC = 0.125f * 1.4426950408889634f;

    float fr[4];
#pragma unroll
    for (int nt = 0; nt < 4; nt++) {
        int cg = nW + nt * 8 + lc;
        int i = (cg & 63) >> 1;
        fr[nt] = powf(10000.0f, -(float)i / 32.0f);
    }

#pragma unroll
    for (int mt = 0; mt < 4; mt++) {
        const int r0g = mW + mt * 16 + lr;
        const int r1g = r0g + 8;
        const float av0 = asq[r0g];
        const float av1 = asq[r1g];
        const int b0 = r0g >> 11, t0 = r0g & 2047;
        const int b1 = r1g >> 11, t1 = r1g & 2047;
#pragma unroll
        for (int nt = 0; nt < 4; nt++) {
            const int cg = nW + nt * 8 + lc;
            const float bq0 = bsq[cg], bq1 = bsq[cg + 1];
            const float bi0 = bias[cg], bi1 = bias[cg + 1];
            float d00 = acc[mt][nt][0], d01 = acc[mt][nt][1];
            float d10 = acc[mt][nt][2], d11 = acc[mt][nt][3];
            float y00 = __fdividef(d00 * d00, av0 + bq0 - 2.f * d00 + EPS_) * scale + bi0;
            float y01 = __fdividef(d01 * d01, av0 + bq1 - 2.f * d01 + EPS_) * scale + bi1;
            float y10 = __fdividef(d10 * d10, av1 + bq0 - 2.f * d10 + EPS_) * scale + bi0;
            float y11 = __fdividef(d11 * d11, av1 + bq1 - 2.f * d11 + EPS_) * scale + bi1;

            const int colh = cg & 1023;
            const int h = colh >> 6;
            const int d = colh & 63;

            if (seg < 2) {
                float s0, c0, s1, c1;
                sincosf((float)t0 * fr[nt], &s0, &c0);
                sincosf((float)t1 * fr[nt], &s1, &c1);
                float sc = (seg == 0) ? QSC : 1.0f;
                float a0 = (y00 * c0 - y01 * s0) * sc;
                float a1 = (y01 * c0 + y00 * s0) * sc;
                float e0 = (y10 * c1 - y11 * s1) * sc;
                float e1 = (y11 * c1 + y10 * s1) * sc;
                __half* Dst = (seg == 0) ? Qh : Kh;
                size_t o0 = ((size_t)(b0 * H_ + h) * T_ + t0) * D_ + d;
                size_t o1 = ((size_t)(b1 * H_ + h) * T_ + t1) * D_ + d;
                *(__half2*)(Dst + o0) = __floats2half2_rn(a0, a1);
                *(__half2*)(Dst + o1) = __floats2half2_rn(e0, e1);
            } else {
                size_t ov0 = ((size_t)(b0 * H_ + h) * D_ + d) * T_ + t0;
                size_t ov1 = ((size_t)(b1 * H_ + h) * D_ + d) * T_ + t1;
                VTh[ov0]      = __float2half_rn(y00);
                VTh[ov0 + T_] = __float2half_rn(y01);
                VTh[ov1]      = __float2half_rn(y10);
                VTh[ov1 + T_] = __float2half_rn(y11);
            }
        }
    }
}

// ======================= tensor-core causal flash attention (pure fp16, 3-stage) =======================
#define AROWB 144
#define QTILE (128 * AROWB)
#define KVTILE (64 * AROWB)
#define SQH_OFF 0
#define STG_OFF QTILE
#define STGSZ  (2 * KVTILE)          // KH + VH = 18432
#define ST_KH 0
#define ST_VH (1 * KVTILE)
#define ATTN_SMEM (QTILE + 3 * STGSZ)   // 73728

__device__ __forceinline__ void attn_load_stage(
    uint32_t st, const __half* kh, const __half* vth,
    size_t bhT, size_t bhD, int k0, int tid)
{
#pragma unroll
    for (int it = 0; it < 2; it++) {
        int idx = it * 256 + tid;
        int row = idx >> 3;
        int ch = (idx & 7) * 16;
        uint32_t dst = (uint32_t)row * AROWB + ch;
        cp16(st + ST_KH + dst, (const char*)(kh + (bhT + k0 + row) * D_) + ch);
        cp16(st + ST_VH + dst, (const char*)(vth + (bhD + row) * T_ + k0) + ch);
    }
}

__global__ void __launch_bounds__(256, 2) attn_mma_kernel(
    const __half* __restrict__ qh, const __half* __restrict__ kh,
    const __half* __restrict__ vth,
    __half* __restrict__ Oh, float* __restrict__ osq)
{
    extern __shared__ char smem[];
    const uint32_t sb = smem_u32(smem);

    const int bh = blockIdx.y;
    const int qx = 15 - (int)blockIdx.x;
    const int q0 = qx * 128;
    const size_t bhT = (size_t)bh * T_;
    const size_t bhD = (size_t)bh * D_;

    const int tid = threadIdx.x;
    const int wid = tid >> 5, lane = tid & 31;
    const int lr = lane >> 2, c2 = (lane & 3) * 2;

    const uint32_t aSel = (uint32_t)(lane & 15) * AROWB + (uint32_t)(lane >> 4) * 16;
    const uint32_t bSel = (uint32_t)(((lane >> 4) & 1) * 8 + (lane & 7)) * AROWB +
                          (uint32_t)((lane >> 3) & 1) * 16;

    const int ntiles = 2 * qx + 2;

    // ---- group 0: Q tile + KV stage 0 ----
#pragma unroll
    for (int it = 0; it < 4; it++) {
        int idx = it * 256 + tid;
        int row = idx >> 3;
        int ch = (idx & 7) * 16;
        uint32_t dst = (uint32_t)row * AROWB + ch;
        cp16(sb + SQH_OFF + dst, (const char*)(qh + (bhT + q0 + row) * D_) + ch);
    }
    attn_load_stage(sb + STG_OFF, kh, vth, bhT, bhD, 0, tid);
    asm volatile("cp.async.commit_group;" ::: "memory");
    // ---- group 1: KV stage 1 (ntiles >= 2 always) ----
    attn_load_stage(sb + STG_OFF + STGSZ, kh, vth, bhT, bhD, 64, tid);
    asm volatile("cp.async.commit_group;" ::: "memory");

    asm volatile("cp.async.wait_group 1;" ::: "memory");
    __syncthreads();
    uint32_t qhf[4][4];
    {
        const uint32_t aQ = sb + SQH_OFF + (uint32_t)wid * 16 * AROWB + aSel;
#pragma unroll
        for (int ks = 0; ks < 4; ks++)
            LDSM4(qhf[ks][0], qhf[ks][1], qhf[ks][2], qhf[ks][3], aQ + ks * 32);
    }

    float O[8][4];
#pragma unroll
    for (int j = 0; j < 8; j++)
#pragma unroll
        for (int e = 0; e < 4; e++) O[j][e] = 0.f;
    float mrow[2] = {-1e30f, -1e30f};
    float lrow[2] = {0.f, 0.f};

    const int rowg0 = q0 + wid * 16 + lr;
    int slot = 0;

    for (int kt = 0; kt < ntiles; kt++) {
        if (kt + 1 < ntiles) {
            asm volatile("cp.async.wait_group 1;" ::: "memory");
        } else {
            asm volatile("cp.async.wait_group 0;" ::: "memory");
        }
        __syncthreads();
        const uint32_t st = sb + STG_OFF + (uint32_t)slot * STGSZ;
        if (++slot == 3) slot = 0;
        if (kt + 2 < ntiles) {
            int ns = slot + 1; if (ns == 3) ns = 0;
            attn_load_stage(sb + STG_OFF + (uint32_t)ns * STGSZ,
                            kh, vth, bhT, bhD, (kt + 2) * 64, tid);
            asm volatile("cp.async.commit_group;" ::: "memory");
        }

        float S[8][4];
#pragma unroll
        for (int j = 0; j < 8; j++)
#pragma unroll
            for (int e = 0; e < 4; e++) S[j][e] = 0.f;

#pragma unroll
        for (int ks = 0; ks < 4; ks++) {
#pragma unroll
            for (int np = 0; np < 4; np++) {
                uint32_t r0, r1, r2, r3;
                LDSM4(r0, r1, r2, r3, st + ST_KH + np * (16 * AROWB) + bSel + ks * 32);
                uint32_t bh0[2] = {r0, r1}, bh1[2] = {r2, r3};
                MMA16816(S[np * 2 + 0], qhf[ks], bh0);
                MMA16816(S[np * 2 + 1], qhf[ks], bh1);
            }
        }

        const int k0 = kt * 64;
        if (kt >= 2 * qx) {
#pragma unroll
            for (int j = 0; j < 8; j++) {
                int col = k0 + j * 8 + c2;
                if (col > rowg0)     S[j][0] = -1e30f;
                if (col + 1 > rowg0) S[j][1] = -1e30f;
                if (col > rowg0 + 8)     S[j][2] = -1e30f;
                if (col + 1 > rowg0 + 8) S[j][3] = -1e30f;
            }
        }

#pragma unroll
        for (int i = 0; i < 2; i++) {
            float mx = -1e30f;
#pragma unroll
            for (int j = 0; j < 8; j++)
                mx = fmaxf(mx, fmaxf(S[j][2 * i], S[j][2 * i + 1]));
            mx = fmaxf(mx, __shfl_xor_sync(0xffffffffu, mx, 1));
            mx = fmaxf(mx, __shfl_xor_sync(0xffffffffu, mx, 2));
            float mn = fmaxf(mrow[i], mx);
            float cf = fast_exp2(mrow[i] - mn);
            mrow[i] = mn;
            float rs = 0.f;
#pragma unroll
            for (int j = 0; j < 8; j++) {
                float p0 = fast_exp2(S[j][2 * i] - mn);
                float p1 = fast_exp2(S[j][2 * i + 1] - mn);
                S[j][2 * i] = p0; S[j][2 * i + 1] = p1;
                rs += p0 + p1;
            }
            rs += __shfl_xor_sync(0xffffffffu, rs, 1);
            rs += __shfl_xor_sync(0xffffffffu, rs, 2);
            lrow[i] = lrow[i] * cf + rs;
#pragma unroll
            for (int j = 0; j < 8; j++) { O[j][2 * i] *= cf; O[j][2 * i + 1] *= cf; }
        }

        uint32_t PH[4][4];
#pragma unroll
        for (int t = 0; t < 4; t++) {
#pragma unroll
            for (int h2 = 0; h2 < 2; h2++) {
                int j = 2 * t + h2;
                PH[t][h2 * 2 + 0] = pack_f16(S[j][0], S[j][1]);
                PH[t][h2 * 2 + 1] = pack_f16(S[j][2], S[j][3]);
            }
        }

#pragma unroll
        for (int t = 0; t < 4; t++) {
#pragma unroll
            for (int dn = 0; dn < 4; dn++) {
                uint32_t r0, r1, r2, r3;
                LDSM4(r0, r1, r2, r3, st + ST_VH + dn * (16 * AROWB) + bSel + t * 32);
                uint32_t vh0[2] = {r0, r1}, vh1[2] = {r2, r3};
                MMA16816(O[dn * 2 + 0], PH[t], vh0);
                MMA16816(O[dn * 2 + 1], PH[t], vh1);
            }
        }
    }

    // ---- fused epilogue: normalize, fp16 write + osq atomics ----
    const int b = bh >> 4, h = bh & 15;
    const float inv0 = 1.f / lrow[0], inv1 = 1.f / lrow[1];
    const size_t m0 = (size_t)(b * T_ + rowg0);
    const size_t m1 = m0 + 8;
    __half* oh0 = Oh + m0 * C_ + h * 64;
    __half* oh1 = Oh + m1 * C_ + h * 64;
    float sq0 = 0.f, sq1 = 0.f;
#pragma unroll
    for (int j = 0; j < 8; j++) {
        float y0 = O[j][0] * inv0, y1 = O[j][1] * inv0;
        float y2 = O[j][2] * inv1, y3 = O[j][3] * inv1;
        sq0 += y0 * y0 + y1 * y1;
        sq1 += y2 * y2 + y3 * y3;
        *(__half2*)(oh0 + j * 8 + c2) = __floats2half2_rn(y0, y1);
        *(__half2*)(oh1 + j * 8 + c2) = __floats2half2_rn(y2, y3);
    }
    sq0 += __shfl_xor_sync(0xffffffffu, sq0, 1);
    sq0 += __shfl_xor_sync(0xffffffffu, sq0, 2);
    sq1 += __shfl_xor_sync(0xffffffffu, sq1, 1);
    sq1 += __shfl_xor_sync(0xffffffffu, sq1, 2);
    if ((lane & 3) == 0) {
        atomicAdd(osq + m0, sq0);
        atomicAdd(osq + m1, sq1);
    }
}

// ---------------- launcher ----------------
extern "C" void kernel_launch(void* const* d_in, const int* in_sizes, int n_in,
                              void* d_out, int out_size)
{
    (void)in_sizes; (void)n_in; (void)out_size;
    const float* x      = (const float*)d_in[0];
    const float* w_attn = (const float*)d_in[2];
    const float* b_attn = (const float*)d_in[3];
    const float* w_proj = (const float*)d_in[4];
    const float* b_proj = (const float*)d_in[5];
    float* out = (float*)d_out;

    float *xsq, *osq, *wsq1, *wsq2;
    __half *xh, *ah, *w1h, *w2h;
    __half *qbh, *kbh, *vth;
    cudaGetSymbolAddress((void**)&xsq,  g_xsq);
    cudaGetSymbolAddress((void**)&osq,  g_osq);
    cudaGetSymbolAddress((void**)&wsq1, g_wsq1);
    cudaGetSymbolAddress((void**)&wsq2, g_wsq2);
    cudaGetSymbolAddress((void**)&xh,   g_xh);
    cudaGetSymbolAddress((void**)&ah,   g_ah);
    cudaGetSymbolAddress((void**)&w1h,  g_w1h);
    cudaGetSymbolAddress((void**)&w2h,  g_w2h);
    cudaGetSymbolAddress((void**)&qbh,  g_qbh);
    cudaGetSymbolAddress((void**)&kbh,  g_kbh);
    cudaGetSymbolAddress((void**)&vth,  g_vth);

    const float scale1 = (float)(sqrt(3072.0) / log1p(3072.0));
    const float scale2 = (float)(sqrt(1024.0) / log1p(1024.0));

    cudaFuncSetAttribute(yat_mma_gemm_kernel,
                         cudaFuncAttributeMaxDynamicSharedMemorySize, MMA_SMEM);
    cudaFuncSetAttribute(yat_rope_gemm_kernel,
                         cudaFuncAttributeMaxDynamicSharedMemorySize, MMA_SMEM);
    cudaFuncSetAttribute(attn_mma_kernel,
                         cudaFuncAttributeMaxDynamicSharedMemorySize, ATTN_SMEM);

    cudaMemsetAsync(wsq1, 0, N1_ * sizeof(float));
    cudaMemsetAsync(wsq2, 0, C_ * sizeof(float));
    cudaMemsetAsync(osq,  0, M_ * sizeof(float));

    prep_x_kernel<<<M_, 256>>>(x, xsq, xh);
    wconv_kernel<<<dim3(N1_ / 32, C_ / 32), 256>>>(w_attn, w1h, wsq1, C_, N1_);
    wconv_kernel<<<dim3(C_ / 32, C_ / 32), 256>>>(w_proj, w2h, wsq2, C_, C_);

    yat_rope_gemm_kernel<<<dim3(N1_ / 128, M_ / 128), 256, MMA_SMEM>>>(
        xh, w1h, xsq, wsq1, b_attn, qbh, kbh, vth, scale1);

    attn_mma_kernel<<<dim3(T_ / 128, B_ * H_), 256, ATTN_SMEM>>>(
        qbh, kbh, vth, ah, osq);

    yat_mma_gemm_kernel<<<dim3(C_ / 128, M_ / 128), 256, MMA_SMEM>>>(
        ah, w2h, osq, wsq2, b_proj, out, M_, C_, C_, scale2);
}